// round 1
// baseline (speedup 1.0000x reference)
#include <cuda_runtime.h>
#include <math.h>
#include <stdint.h>

#define BB 4
#define SS_ 1024
#define DD 512
#define HH 8
#define DKK 64
#define PP_ 2047   // 2*S-1

// ---------------- scratch (device globals: allocation-free) ----------------
__device__ float g_xn[BB*SS_*DD];
__device__ float g_qu[BB*SS_*DD];
__device__ float g_qv[BB*SS_*DD];
__device__ float g_k [BB*SS_*DD];
__device__ float g_v [BB*SS_*DD];
__device__ float g_pe[PP_*DD];
__device__ float g_p [PP_*DD];
__device__ float g_sc[(size_t)BB*HH*SS_*SS_];   // 128 MB scores/attn (in-place softmax)
__device__ float g_tmp[BB*SS_*DD];

// ---------------- LayerNorm: one block per row (512 cols) ----------------
__global__ void ln_kernel(const float* __restrict__ x, const float* __restrict__ gamma,
                          const float* __restrict__ beta, float* __restrict__ out) {
    __shared__ float red[4];
    int row = blockIdx.x;
    int t = threadIdx.x;  // 128 threads
    const float4* xr = (const float4*)(x + (size_t)row * DD);
    float4 v = xr[t];
    float s = v.x + v.y + v.z + v.w;
    #pragma unroll
    for (int o = 16; o; o >>= 1) s += __shfl_xor_sync(0xffffffffu, s, o);
    if ((t & 31) == 0) red[t >> 5] = s;
    __syncthreads();
    float mu = (red[0] + red[1] + red[2] + red[3]) * (1.0f / DD);
    float dx = v.x - mu, dy = v.y - mu, dz = v.z - mu, dw = v.w - mu;
    float ss = dx*dx + dy*dy + dz*dz + dw*dw;
    #pragma unroll
    for (int o = 16; o; o >>= 1) ss += __shfl_xor_sync(0xffffffffu, ss, o);
    __syncthreads();
    if ((t & 31) == 0) red[t >> 5] = ss;
    __syncthreads();
    float var = (red[0] + red[1] + red[2] + red[3]) * (1.0f / DD);
    float rstd = rsqrtf(var + 1e-5f);
    float4 g = ((const float4*)gamma)[t];
    float4 be = ((const float4*)beta)[t];
    float4 o4;
    o4.x = dx * rstd * g.x + be.x;
    o4.y = dy * rstd * g.y + be.y;
    o4.z = dz * rstd * g.z + be.z;
    o4.w = dw * rstd * g.w + be.w;
    ((float4*)(out + (size_t)row * DD))[t] = o4;
}

// ---------------- positional embedding pe[2047][512] ----------------
__global__ void pe_kernel(float* __restrict__ pe) {
    int j = blockIdx.x;            // 0..2046
    int t = threadIdx.x;           // 0..255, pair index
    float pos = (float)(j - (SS_ - 1));
    // div_term = exp(i * (-ln(10000)/512)), i = 2*t
    const float kconst = -0.01798894603901598415f;   // ln(10000)/512
    float div = expf((float)(2 * t) * kconst);
    float ang = pos * div;
    float sa, ca;
    sincosf(ang, &sa, &ca);
    pe[(size_t)j * DD + 2 * t]     = sa;
    pe[(size_t)j * DD + 2 * t + 1] = ca;
}

// ---------------- generic NT GEMM: C[M,512] = A[M,512] @ Bw[512,512]^T ----------------
// 128x128 tile, BK=8, 256 threads, 8x8 microtile.
// If C1 != null: C0 = acc+bias+add0[n], C1 = acc+bias+add1[n]; else C0 = acc+(bias?bias[n]:0).
__global__ __launch_bounds__(256) void gemm_nt(
    const float* __restrict__ A, const float* __restrict__ Bw,
    const float* __restrict__ bias, float* __restrict__ C0, float* __restrict__ C1,
    const float* __restrict__ add0, const float* __restrict__ add1, int M)
{
    __shared__ float sA[8][132];
    __shared__ float sB[8][132];
    const int bm = blockIdx.y * 128;
    const int bn = blockIdx.x * 128;
    const int tid = threadIdx.x;
    const int lr = tid >> 1;
    const int lc = (tid & 1) * 4;
    const int tx = tid & 15;
    const int ty = tid >> 4;
    float acc[8][8];
    #pragma unroll
    for (int i = 0; i < 8; ++i)
        #pragma unroll
        for (int j = 0; j < 8; ++j) acc[i][j] = 0.0f;

    const bool aok = (bm + lr) < M;
    const float* Aptr = A + (size_t)(bm + lr) * DD + lc;
    const float* Bptr = Bw + (size_t)(bn + lr) * DD + lc;

    for (int kt = 0; kt < DD / 8; ++kt) {
        float4 av = aok ? *(const float4*)(Aptr + kt * 8) : make_float4(0.f, 0.f, 0.f, 0.f);
        float4 bv = *(const float4*)(Bptr + kt * 8);
        __syncthreads();
        sA[lc + 0][lr] = av.x; sA[lc + 1][lr] = av.y; sA[lc + 2][lr] = av.z; sA[lc + 3][lr] = av.w;
        sB[lc + 0][lr] = bv.x; sB[lc + 1][lr] = bv.y; sB[lc + 2][lr] = bv.z; sB[lc + 3][lr] = bv.w;
        __syncthreads();
        #pragma unroll
        for (int k = 0; k < 8; ++k) {
            float a[8], b[8];
            float4 t0 = *(const float4*)&sA[k][ty * 4];
            float4 t1 = *(const float4*)&sA[k][64 + ty * 4];
            a[0]=t0.x; a[1]=t0.y; a[2]=t0.z; a[3]=t0.w; a[4]=t1.x; a[5]=t1.y; a[6]=t1.z; a[7]=t1.w;
            float4 u0 = *(const float4*)&sB[k][tx * 4];
            float4 u1 = *(const float4*)&sB[k][64 + tx * 4];
            b[0]=u0.x; b[1]=u0.y; b[2]=u0.z; b[3]=u0.w; b[4]=u1.x; b[5]=u1.y; b[6]=u1.z; b[7]=u1.w;
            #pragma unroll
            for (int i = 0; i < 8; ++i)
                #pragma unroll
                for (int j = 0; j < 8; ++j)
                    acc[i][j] += a[i] * b[j];
        }
    }
    #pragma unroll
    for (int i = 0; i < 8; ++i) {
        int m = bm + ((i < 4) ? (ty * 4 + i) : (64 + ty * 4 + i - 4));
        if (m >= M) continue;
        #pragma unroll
        for (int j = 0; j < 8; ++j) {
            int n = bn + ((j < 4) ? (tx * 4 + j) : (64 + tx * 4 + j - 4));
            float val = acc[i][j];
            if (bias) val += bias[n];
            if (C1) {
                C0[(size_t)m * DD + n] = val + add0[n];
                C1[(size_t)m * DD + n] = val + add1[n];
            } else {
                C0[(size_t)m * DD + n] = val;
            }
        }
    }
}

// ---------------- scores: AC + BD (rel-shifted) fused ----------------
// scores[b,h,q,k] = ( (q+u)·k  +  (q+v)·p[S+k-q] ) / 8 ; wrap (q=0,k=S-1) uses p-row via qv[1]·p[0]
__global__ __launch_bounds__(256) void scores_kernel(
    const float* __restrict__ qu, const float* __restrict__ qv,
    const float* __restrict__ kmat, const float* __restrict__ pmat,
    const unsigned char* __restrict__ mask, float* __restrict__ sc)
{
    __shared__ float sQu[8][132];
    __shared__ float sQv[8][132];
    __shared__ float sK [8][132];
    __shared__ float sP [8][256];   // 255 diagonal-band rows (transposed: [k][r])

    const int bh = blockIdx.z;
    const int b = bh >> 3, h = bh & 7;
    const int qc = blockIdx.y * 128;
    const int kc = blockIdx.x * 128;
    const int pbase = SS_ + kc - qc - 127;   // >= 1 always
    const int tid = threadIdx.x;
    const int lr = tid >> 1;
    const int lc = (tid & 1) * 4;
    const int tx = tid & 15;
    const int ty = tid >> 4;

    float acc[8][8];
    #pragma unroll
    for (int i = 0; i < 8; ++i)
        #pragma unroll
        for (int j = 0; j < 8; ++j) acc[i][j] = 0.0f;

    const float* quP = qu + ((size_t)(b * SS_ + qc + lr)) * DD + h * DKK + lc;
    const float* qvP = qv + ((size_t)(b * SS_ + qc + lr)) * DD + h * DKK + lc;
    const float* kP  = kmat + ((size_t)(b * SS_ + kc + lr)) * DD + h * DKK + lc;

    const int prow0 = tid >> 1;                 // 0..127
    const int pc0   = (tid & 1) * 4;
    const int idx1  = tid + 256;                // 256..511 (< 510 valid)
    const int prow1 = idx1 >> 1;                // 128..254
    const int pc1   = (idx1 & 1) * 4;
    const bool p1ok = (idx1 < 510);

    for (int kt = 0; kt < 8; ++kt) {
        float4 aQu = *(const float4*)(quP + kt * 8);
        float4 aQv = *(const float4*)(qvP + kt * 8);
        float4 aK  = *(const float4*)(kP  + kt * 8);
        int pi0 = pbase + prow0;
        int pi1 = pbase + prow1;
        float4 pv0 = (pi0 < PP_) ? *(const float4*)(pmat + (size_t)pi0 * DD + h * DKK + kt * 8 + pc0)
                                 : make_float4(0.f, 0.f, 0.f, 0.f);
        float4 pv1 = (p1ok && pi1 < PP_) ? *(const float4*)(pmat + (size_t)pi1 * DD + h * DKK + kt * 8 + pc1)
                                         : make_float4(0.f, 0.f, 0.f, 0.f);
        __syncthreads();
        sQu[lc+0][lr]=aQu.x; sQu[lc+1][lr]=aQu.y; sQu[lc+2][lr]=aQu.z; sQu[lc+3][lr]=aQu.w;
        sQv[lc+0][lr]=aQv.x; sQv[lc+1][lr]=aQv.y; sQv[lc+2][lr]=aQv.z; sQv[lc+3][lr]=aQv.w;
        sK [lc+0][lr]=aK.x;  sK [lc+1][lr]=aK.y;  sK [lc+2][lr]=aK.z;  sK [lc+3][lr]=aK.w;
        sP[pc0+0][prow0]=pv0.x; sP[pc0+1][prow0]=pv0.y; sP[pc0+2][prow0]=pv0.z; sP[pc0+3][prow0]=pv0.w;
        if (p1ok) { sP[pc1+0][prow1]=pv1.x; sP[pc1+1][prow1]=pv1.y; sP[pc1+2][prow1]=pv1.z; sP[pc1+3][prow1]=pv1.w; }
        __syncthreads();

        const int base = 124 + 4 * (tx - ty);   // center-band start (r = base + off + 64*band)
        #pragma unroll
        for (int k = 0; k < 8; ++k) {
            float aq[8], av[8], bk[8];
            float4 t0 = *(const float4*)&sQu[k][ty * 4];
            float4 t1 = *(const float4*)&sQu[k][64 + ty * 4];
            aq[0]=t0.x; aq[1]=t0.y; aq[2]=t0.z; aq[3]=t0.w; aq[4]=t1.x; aq[5]=t1.y; aq[6]=t1.z; aq[7]=t1.w;
            float4 v0 = *(const float4*)&sQv[k][ty * 4];
            float4 v1 = *(const float4*)&sQv[k][64 + ty * 4];
            av[0]=v0.x; av[1]=v0.y; av[2]=v0.z; av[3]=v0.w; av[4]=v1.x; av[5]=v1.y; av[6]=v1.z; av[7]=v1.w;
            float4 u0 = *(const float4*)&sK[k][tx * 4];
            float4 u1 = *(const float4*)&sK[k][64 + tx * 4];
            bk[0]=u0.x; bk[1]=u0.y; bk[2]=u0.z; bk[3]=u0.w; bk[4]=u1.x; bk[5]=u1.y; bk[6]=u1.z; bk[7]=u1.w;
            float pm[7], pc_[7], pl[7];
            #pragma unroll
            for (int t7 = 0; t7 < 7; ++t7) {
                pm[t7]  = sP[k][base - 64 + t7];
                pc_[t7] = sP[k][base + t7];
                pl[t7]  = sP[k][base + 64 + t7];
            }
            #pragma unroll
            for (int i = 0; i < 8; ++i) {
                #pragma unroll
                for (int j = 0; j < 8; ++j) {
                    acc[i][j] += aq[i] * bk[j];
                    const int band = (j >> 2) - (i >> 2);        // compile-time per unrolled iter
                    const int off  = (j & 3) - (i & 3) + 3;
                    float pv = (band == 0) ? pc_[off] : ((band < 0) ? pm[off] : pl[off]);
                    acc[i][j] += av[i] * pv;
                }
            }
        }
    }

    // epilogue: scale, wrap fix, mask, store
    #pragma unroll
    for (int i = 0; i < 8; ++i) {
        int q = qc + ((i < 4) ? (ty * 4 + i) : (64 + ty * 4 + i - 4));
        #pragma unroll
        for (int j = 0; j < 8; ++j) {
            int k = kc + ((j < 4) ? (tx * 4 + j) : (64 + tx * 4 + j - 4));
            float val = acc[i][j];
            if (q == 0 && k == SS_ - 1) {
                // rel_shift wrap: bd = qv[b,h,1,:] . p[0,h,:]
                float s = 0.0f;
                const float* qr = qv + ((size_t)(b * SS_ + 1)) * DD + h * DKK;
                const float* pr = pmat + h * DKK;
                #pragma unroll
                for (int d = 0; d < DKK; ++d) s += qr[d] * pr[d];
                val += s;
            }
            val *= 0.125f;   // 1/sqrt(64)
            if (mask[(size_t)b * SS_ * SS_ + (size_t)q * SS_ + k]) val = -10000.0f;
            sc[((size_t)bh * SS_ + q) * SS_ + k] = val;
        }
    }
}

// ---------------- row softmax over 1024 (in-place) ----------------
__global__ void softmax_kernel(float* __restrict__ sc) {
    __shared__ float red[33];
    size_t row = blockIdx.x;
    float* r = sc + row * SS_;
    int t = threadIdx.x;  // 256 threads, 4 elems each
    float4 v = ((const float4*)r)[t];
    float m = fmaxf(fmaxf(v.x, v.y), fmaxf(v.z, v.w));
    #pragma unroll
    for (int o = 16; o; o >>= 1) m = fmaxf(m, __shfl_xor_sync(0xffffffffu, m, o));
    if ((t & 31) == 0) red[t >> 5] = m;
    __syncthreads();
    if (t == 0) {
        float mm = red[0];
        #pragma unroll
        for (int i = 1; i < 8; ++i) mm = fmaxf(mm, red[i]);
        red[32] = mm;
    }
    __syncthreads();
    m = red[32];
    float4 e;
    e.x = expf(v.x - m); e.y = expf(v.y - m); e.z = expf(v.z - m); e.w = expf(v.w - m);
    float s = e.x + e.y + e.z + e.w;
    #pragma unroll
    for (int o = 16; o; o >>= 1) s += __shfl_xor_sync(0xffffffffu, s, o);
    __syncthreads();
    if ((t & 31) == 0) red[t >> 5] = s;
    __syncthreads();
    if (t == 0) {
        float tot = 0.0f;
        #pragma unroll
        for (int i = 0; i < 8; ++i) tot += red[i];
        red[32] = 1.0f / tot;
    }
    __syncthreads();
    float inv = red[32];
    e.x *= inv; e.y *= inv; e.z *= inv; e.w *= inv;
    ((float4*)r)[t] = e;
}

// ---------------- attn @ V : per (b,h), out[b,q,h,d] layout (b*S+q)*512 + h*64 + d ----------------
__global__ __launch_bounds__(256) void av_kernel(const float* __restrict__ att,
                                                 const float* __restrict__ vmat,
                                                 float* __restrict__ out) {
    __shared__ float sAtt[16][132];
    __shared__ float sV[16][68];
    const int bh = blockIdx.y;
    const int b = bh >> 3, h = bh & 7;
    const int qc = blockIdx.x * 128;
    const int tid = threadIdx.x;
    const int tx = tid & 15;
    const int ty = tid >> 4;

    // att tile loads: 128 rows x 16 cols = 512 float4; idx = tid, tid+256
    const int ar0 = tid >> 2, ac0 = (tid & 3) * 4;
    const int ar1 = (tid + 256) >> 2, ac1 = ((tid + 256) & 3) * 4;
    // v tile loads: 16 rows x 64 cols = 256 float4
    const int vr = tid >> 4, vc = (tid & 15) * 4;

    float acc[8][4];
    #pragma unroll
    for (int i = 0; i < 8; ++i)
        #pragma unroll
        for (int j = 0; j < 4; ++j) acc[i][j] = 0.0f;

    for (int kt = 0; kt < SS_ / 16; ++kt) {
        float4 a0 = *(const float4*)(att + ((size_t)bh * SS_ + qc + ar0) * SS_ + kt * 16 + ac0);
        float4 a1 = *(const float4*)(att + ((size_t)bh * SS_ + qc + ar1) * SS_ + kt * 16 + ac1);
        float4 vv = *(const float4*)(vmat + ((size_t)(b * SS_ + kt * 16 + vr)) * DD + h * DKK + vc);
        __syncthreads();
        sAtt[ac0+0][ar0]=a0.x; sAtt[ac0+1][ar0]=a0.y; sAtt[ac0+2][ar0]=a0.z; sAtt[ac0+3][ar0]=a0.w;
        sAtt[ac1+0][ar1]=a1.x; sAtt[ac1+1][ar1]=a1.y; sAtt[ac1+2][ar1]=a1.z; sAtt[ac1+3][ar1]=a1.w;
        *(float4*)&sV[vr][vc] = vv;
        __syncthreads();
        #pragma unroll
        for (int k = 0; k < 16; ++k) {
            float a[8];
            float4 t0 = *(const float4*)&sAtt[k][ty * 4];
            float4 t1 = *(const float4*)&sAtt[k][64 + ty * 4];
            a[0]=t0.x; a[1]=t0.y; a[2]=t0.z; a[3]=t0.w; a[4]=t1.x; a[5]=t1.y; a[6]=t1.z; a[7]=t1.w;
            float4 bv = *(const float4*)&sV[k][tx * 4];
            float bj[4] = {bv.x, bv.y, bv.z, bv.w};
            #pragma unroll
            for (int i = 0; i < 8; ++i)
                #pragma unroll
                for (int j = 0; j < 4; ++j)
                    acc[i][j] += a[i] * bj[j];
        }
    }
    #pragma unroll
    for (int i = 0; i < 8; ++i) {
        int q = qc + ((i < 4) ? (ty * 4 + i) : (64 + ty * 4 + i - 4));
        float* o = out + ((size_t)(b * SS_ + q)) * DD + h * DKK + tx * 4;
        #pragma unroll
        for (int j = 0; j < 4; ++j) o[j] = acc[i][j];
    }
}

// ---------------- launch ----------------
extern "C" void kernel_launch(void* const* d_in, const int* in_sizes, int n_in,
                              void* d_out, int out_size) {
    const float* inputs        = (const float*)d_in[0];
    const unsigned char* amask = (const unsigned char*)d_in[1];
    const float* Wq = (const float*)d_in[2];
    const float* bq = (const float*)d_in[3];
    const float* Wk = (const float*)d_in[4];
    const float* bk = (const float*)d_in[5];
    const float* Wv = (const float*)d_in[6];
    const float* bv = (const float*)d_in[7];
    const float* Wo = (const float*)d_in[8];
    const float* bo = (const float*)d_in[9];
    const float* Wp = (const float*)d_in[10];
    const float* pu = (const float*)d_in[11];  // (H,DK) flat == per-column add
    const float* pv = (const float*)d_in[12];
    const float* gamma = (const float*)d_in[13];
    const float* beta  = (const float*)d_in[14];
    float* out = (float*)d_out;

    float *xn, *qu, *qv, *kk, *vv, *pe, *pp, *sc, *tmp;
    cudaGetSymbolAddress((void**)&xn, g_xn);
    cudaGetSymbolAddress((void**)&qu, g_qu);
    cudaGetSymbolAddress((void**)&qv, g_qv);
    cudaGetSymbolAddress((void**)&kk, g_k);
    cudaGetSymbolAddress((void**)&vv, g_v);
    cudaGetSymbolAddress((void**)&pe, g_pe);
    cudaGetSymbolAddress((void**)&pp, g_p);
    cudaGetSymbolAddress((void**)&sc, g_sc);
    cudaGetSymbolAddress((void**)&tmp, g_tmp);

    ln_kernel<<<BB * SS_, 128>>>(inputs, gamma, beta, xn);
    pe_kernel<<<PP_, 256>>>(pe);

    // projections
    gemm_nt<<<dim3(4, 32), 256>>>(xn, Wq, bq, qu, qv, pu, pv, BB * SS_);
    gemm_nt<<<dim3(4, 32), 256>>>(xn, Wk, bk, kk, nullptr, nullptr, nullptr, BB * SS_);
    gemm_nt<<<dim3(4, 32), 256>>>(xn, Wv, bv, vv, nullptr, nullptr, nullptr, BB * SS_);
    gemm_nt<<<dim3(4, 16), 256>>>(pe, Wp, nullptr, pp, nullptr, nullptr, nullptr, PP_);

    // fused AC+BD scores
    scores_kernel<<<dim3(8, 8, BB * HH), 256>>>(qu, qv, kk, pp, amask, sc);

    // softmax rows
    softmax_kernel<<<BB * HH * SS_, 256>>>(sc);

    // attn @ V
    av_kernel<<<dim3(8, BB * HH), 256>>>(sc, vv, tmp);

    // output projection
    gemm_nt<<<dim3(4, 32), 256>>>(tmp, Wo, bo, out, nullptr, nullptr, nullptr, BB * SS_);

    (void)in_sizes; (void)n_in; (void)out_size;
}

// round 2
// speedup vs baseline: 1.5564x; 1.5564x over previous
#include <cuda_runtime.h>
#include <math.h>
#include <stdint.h>

#define BB 4
#define SS_ 1024
#define DD 512
#define HH 8
#define DKK 64
#define PP_ 2047   // 2*S-1

// ---------------- scratch (device globals: allocation-free) ----------------
__device__ float g_xn[BB*SS_*DD];
__device__ float g_qu[BB*SS_*DD];
__device__ float g_qv[BB*SS_*DD];
__device__ float g_k [BB*SS_*DD];
__device__ float g_v [BB*SS_*DD];
__device__ float g_pe[PP_*DD];
__device__ float g_p [PP_*DD];
__device__ float g_sc[(size_t)BB*HH*SS_*SS_];   // 128 MB scores/attn (in-place softmax)
__device__ float g_tmp[BB*SS_*DD];

// ---------------- LayerNorm: one block per row (512 cols) ----------------
__global__ void ln_kernel(const float* __restrict__ x, const float* __restrict__ gamma,
                          const float* __restrict__ beta, float* __restrict__ out) {
    __shared__ float red[4];
    int row = blockIdx.x;
    int t = threadIdx.x;  // 128 threads
    const float4* xr = (const float4*)(x + (size_t)row * DD);
    float4 v = xr[t];
    float s = v.x + v.y + v.z + v.w;
    #pragma unroll
    for (int o = 16; o; o >>= 1) s += __shfl_xor_sync(0xffffffffu, s, o);
    if ((t & 31) == 0) red[t >> 5] = s;
    __syncthreads();
    float mu = (red[0] + red[1] + red[2] + red[3]) * (1.0f / DD);
    float dx = v.x - mu, dy = v.y - mu, dz = v.z - mu, dw = v.w - mu;
    float ss = dx*dx + dy*dy + dz*dz + dw*dw;
    #pragma unroll
    for (int o = 16; o; o >>= 1) ss += __shfl_xor_sync(0xffffffffu, ss, o);
    __syncthreads();
    if ((t & 31) == 0) red[t >> 5] = ss;
    __syncthreads();
    float var = (red[0] + red[1] + red[2] + red[3]) * (1.0f / DD);
    float rstd = rsqrtf(var + 1e-5f);
    float4 g = ((const float4*)gamma)[t];
    float4 be = ((const float4*)beta)[t];
    float4 o4;
    o4.x = dx * rstd * g.x + be.x;
    o4.y = dy * rstd * g.y + be.y;
    o4.z = dz * rstd * g.z + be.z;
    o4.w = dw * rstd * g.w + be.w;
    ((float4*)(out + (size_t)row * DD))[t] = o4;
}

// ---------------- positional embedding pe[2047][512] ----------------
__global__ void pe_kernel(float* __restrict__ pe) {
    int j = blockIdx.x;            // 0..2046
    int t = threadIdx.x;           // 0..255, pair index
    float pos = (float)(j - (SS_ - 1));
    // div_term = exp(i * (-ln(10000)/512)), i = 2*t
    const float kconst = -0.01798894603901598415f;   // ln(10000)/512
    float div = expf((float)(2 * t) * kconst);
    float ang = pos * div;
    float sa, ca;
    sincosf(ang, &sa, &ca);
    pe[(size_t)j * DD + 2 * t]     = sa;
    pe[(size_t)j * DD + 2 * t + 1] = ca;
}

// ---------------- generic NT GEMM: C[M,512] = A[M,512] @ Bw[512,512]^T ----------------
// 128x128 tile, BK=8, 256 threads, 8x8 microtile.
// If C1 != null: C0 = acc+bias+add0[n], C1 = acc+bias+add1[n]; else C0 = acc+(bias?bias[n]:0).
__global__ __launch_bounds__(256) void gemm_nt(
    const float* __restrict__ A, const float* __restrict__ Bw,
    const float* __restrict__ bias, float* __restrict__ C0, float* __restrict__ C1,
    const float* __restrict__ add0, const float* __restrict__ add1, int M)
{
    __shared__ float sA[8][132];
    __shared__ float sB[8][132];
    const int bm = blockIdx.y * 128;
    const int bn = blockIdx.x * 128;
    const int tid = threadIdx.x;
    const int lr = tid >> 1;
    const int lc = (tid & 1) * 4;
    const int tx = tid & 15;
    const int ty = tid >> 4;
    float acc[8][8];
    #pragma unroll
    for (int i = 0; i < 8; ++i)
        #pragma unroll
        for (int j = 0; j < 8; ++j) acc[i][j] = 0.0f;

    const bool aok = (bm + lr) < M;
    const float* Aptr = A + (size_t)(bm + lr) * DD + lc;
    const float* Bptr = Bw + (size_t)(bn + lr) * DD + lc;

    for (int kt = 0; kt < DD / 8; ++kt) {
        float4 av = aok ? *(const float4*)(Aptr + kt * 8) : make_float4(0.f, 0.f, 0.f, 0.f);
        float4 bv = *(const float4*)(Bptr + kt * 8);
        __syncthreads();
        sA[lc + 0][lr] = av.x; sA[lc + 1][lr] = av.y; sA[lc + 2][lr] = av.z; sA[lc + 3][lr] = av.w;
        sB[lc + 0][lr] = bv.x; sB[lc + 1][lr] = bv.y; sB[lc + 2][lr] = bv.z; sB[lc + 3][lr] = bv.w;
        __syncthreads();
        #pragma unroll
        for (int k = 0; k < 8; ++k) {
            float a[8], b[8];
            float4 t0 = *(const float4*)&sA[k][ty * 4];
            float4 t1 = *(const float4*)&sA[k][64 + ty * 4];
            a[0]=t0.x; a[1]=t0.y; a[2]=t0.z; a[3]=t0.w; a[4]=t1.x; a[5]=t1.y; a[6]=t1.z; a[7]=t1.w;
            float4 u0 = *(const float4*)&sB[k][tx * 4];
            float4 u1 = *(const float4*)&sB[k][64 + tx * 4];
            b[0]=u0.x; b[1]=u0.y; b[2]=u0.z; b[3]=u0.w; b[4]=u1.x; b[5]=u1.y; b[6]=u1.z; b[7]=u1.w;
            #pragma unroll
            for (int i = 0; i < 8; ++i)
                #pragma unroll
                for (int j = 0; j < 8; ++j)
                    acc[i][j] += a[i] * b[j];
        }
    }
    #pragma unroll
    for (int i = 0; i < 8; ++i) {
        int m = bm + ((i < 4) ? (ty * 4 + i) : (64 + ty * 4 + i - 4));
        if (m >= M) continue;
        #pragma unroll
        for (int j = 0; j < 8; ++j) {
            int n = bn + ((j < 4) ? (tx * 4 + j) : (64 + tx * 4 + j - 4));
            float val = acc[i][j];
            if (bias) val += bias[n];
            if (C1) {
                C0[(size_t)m * DD + n] = val + add0[n];
                C1[(size_t)m * DD + n] = val + add1[n];
            } else {
                C0[(size_t)m * DD + n] = val;
            }
        }
    }
}

// ---------------- scores: AC + BD (rel-shifted) fused ----------------
// scores[b,h,q,k] = ( (q+u)·k  +  (q+v)·p[S+k-q] ) / 8 ; wrap (q=0,k=S-1) uses p-row via qv[1]·p[0]
__global__ __launch_bounds__(256) void scores_kernel(
    const float* __restrict__ qu, const float* __restrict__ qv,
    const float* __restrict__ kmat, const float* __restrict__ pmat,
    const unsigned char* __restrict__ mask, float* __restrict__ sc)
{
    __shared__ float sQu[8][132];
    __shared__ float sQv[8][132];
    __shared__ float sK [8][132];
    __shared__ float sP [8][256];   // 255 diagonal-band rows (transposed: [k][r])

    const int bh = blockIdx.z;
    const int b = bh >> 3, h = bh & 7;
    const int qc = blockIdx.y * 128;
    const int kc = blockIdx.x * 128;
    const int pbase = SS_ + kc - qc - 127;   // >= 1 always
    const int tid = threadIdx.x;
    const int lr = tid >> 1;
    const int lc = (tid & 1) * 4;
    const int tx = tid & 15;
    const int ty = tid >> 4;

    float acc[8][8];
    #pragma unroll
    for (int i = 0; i < 8; ++i)
        #pragma unroll
        for (int j = 0; j < 8; ++j) acc[i][j] = 0.0f;

    const float* quP = qu + ((size_t)(b * SS_ + qc + lr)) * DD + h * DKK + lc;
    const float* qvP = qv + ((size_t)(b * SS_ + qc + lr)) * DD + h * DKK + lc;
    const float* kP  = kmat + ((size_t)(b * SS_ + kc + lr)) * DD + h * DKK + lc;

    const int prow0 = tid >> 1;                 // 0..127
    const int pc0   = (tid & 1) * 4;
    const int idx1  = tid + 256;                // 256..511 (< 510 valid)
    const int prow1 = idx1 >> 1;                // 128..254
    const int pc1   = (idx1 & 1) * 4;
    const bool p1ok = (idx1 < 510);

    for (int kt = 0; kt < 8; ++kt) {
        float4 aQu = *(const float4*)(quP + kt * 8);
        float4 aQv = *(const float4*)(qvP + kt * 8);
        float4 aK  = *(const float4*)(kP  + kt * 8);
        int pi0 = pbase + prow0;
        int pi1 = pbase + prow1;
        float4 pv0 = (pi0 < PP_) ? *(const float4*)(pmat + (size_t)pi0 * DD + h * DKK + kt * 8 + pc0)
                                 : make_float4(0.f, 0.f, 0.f, 0.f);
        float4 pv1 = (p1ok && pi1 < PP_) ? *(const float4*)(pmat + (size_t)pi1 * DD + h * DKK + kt * 8 + pc1)
                                         : make_float4(0.f, 0.f, 0.f, 0.f);
        __syncthreads();
        sQu[lc+0][lr]=aQu.x; sQu[lc+1][lr]=aQu.y; sQu[lc+2][lr]=aQu.z; sQu[lc+3][lr]=aQu.w;
        sQv[lc+0][lr]=aQv.x; sQv[lc+1][lr]=aQv.y; sQv[lc+2][lr]=aQv.z; sQv[lc+3][lr]=aQv.w;
        sK [lc+0][lr]=aK.x;  sK [lc+1][lr]=aK.y;  sK [lc+2][lr]=aK.z;  sK [lc+3][lr]=aK.w;
        sP[pc0+0][prow0]=pv0.x; sP[pc0+1][prow0]=pv0.y; sP[pc0+2][prow0]=pv0.z; sP[pc0+3][prow0]=pv0.w;
        if (p1ok) { sP[pc1+0][prow1]=pv1.x; sP[pc1+1][prow1]=pv1.y; sP[pc1+2][prow1]=pv1.z; sP[pc1+3][prow1]=pv1.w; }
        __syncthreads();

        const int base = 124 + 4 * (tx - ty);   // center-band start (r = base + off + 64*band)
        #pragma unroll
        for (int k = 0; k < 8; ++k) {
            float aq[8], av[8], bk[8];
            float4 t0 = *(const float4*)&sQu[k][ty * 4];
            float4 t1 = *(const float4*)&sQu[k][64 + ty * 4];
            aq[0]=t0.x; aq[1]=t0.y; aq[2]=t0.z; aq[3]=t0.w; aq[4]=t1.x; aq[5]=t1.y; aq[6]=t1.z; aq[7]=t1.w;
            float4 v0 = *(const float4*)&sQv[k][ty * 4];
            float4 v1 = *(const float4*)&sQv[k][64 + ty * 4];
            av[0]=v0.x; av[1]=v0.y; av[2]=v0.z; av[3]=v0.w; av[4]=v1.x; av[5]=v1.y; av[6]=v1.z; av[7]=v1.w;
            float4 u0 = *(const float4*)&sK[k][tx * 4];
            float4 u1 = *(const float4*)&sK[k][64 + tx * 4];
            bk[0]=u0.x; bk[1]=u0.y; bk[2]=u0.z; bk[3]=u0.w; bk[4]=u1.x; bk[5]=u1.y; bk[6]=u1.z; bk[7]=u1.w;
            float pm[7], pc_[7], pl[7];
            #pragma unroll
            for (int t7 = 0; t7 < 7; ++t7) {
                pm[t7]  = sP[k][base - 64 + t7];
                pc_[t7] = sP[k][base + t7];
                pl[t7]  = sP[k][base + 64 + t7];
            }
            #pragma unroll
            for (int i = 0; i < 8; ++i) {
                #pragma unroll
                for (int j = 0; j < 8; ++j) {
                    acc[i][j] += aq[i] * bk[j];
                    const int band = (j >> 2) - (i >> 2);        // compile-time per unrolled iter
                    const int off  = (j & 3) - (i & 3) + 3;
                    float pv = (band == 0) ? pc_[off] : ((band < 0) ? pm[off] : pl[off]);
                    acc[i][j] += av[i] * pv;
                }
            }
        }
    }

    // epilogue: scale, wrap fix, mask, store
    #pragma unroll
    for (int i = 0; i < 8; ++i) {
        int q = qc + ((i < 4) ? (ty * 4 + i) : (64 + ty * 4 + i - 4));
        #pragma unroll
        for (int j = 0; j < 8; ++j) {
            int k = kc + ((j < 4) ? (tx * 4 + j) : (64 + tx * 4 + j - 4));
            float val = acc[i][j];
            if (q == 0 && k == SS_ - 1) {
                // rel_shift wrap: bd = qv[b,h,1,:] . p[0,h,:]
                float s = 0.0f;
                const float* qr = qv + ((size_t)(b * SS_ + 1)) * DD + h * DKK;
                const float* pr = pmat + h * DKK;
                #pragma unroll
                for (int d = 0; d < DKK; ++d) s += qr[d] * pr[d];
                val += s;
            }
            val *= 0.125f;   // 1/sqrt(64)
            if (mask[(size_t)b * SS_ * SS_ + (size_t)q * SS_ + k]) val = -10000.0f;
            sc[((size_t)bh * SS_ + q) * SS_ + k] = val;
        }
    }
}

// ---------------- row softmax over 1024 (in-place) ----------------
__global__ void softmax_kernel(float* __restrict__ sc) {
    __shared__ float red[33];
    size_t row = blockIdx.x;
    float* r = sc + row * SS_;
    int t = threadIdx.x;  // 256 threads, 4 elems each
    float4 v = ((const float4*)r)[t];
    float m = fmaxf(fmaxf(v.x, v.y), fmaxf(v.z, v.w));
    #pragma unroll
    for (int o = 16; o; o >>= 1) m = fmaxf(m, __shfl_xor_sync(0xffffffffu, m, o));
    if ((t & 31) == 0) red[t >> 5] = m;
    __syncthreads();
    if (t == 0) {
        float mm = red[0];
        #pragma unroll
        for (int i = 1; i < 8; ++i) mm = fmaxf(mm, red[i]);
        red[32] = mm;
    }
    __syncthreads();
    m = red[32];
    float4 e;
    e.x = expf(v.x - m); e.y = expf(v.y - m); e.z = expf(v.z - m); e.w = expf(v.w - m);
    float s = e.x + e.y + e.z + e.w;
    #pragma unroll
    for (int o = 16; o; o >>= 1) s += __shfl_xor_sync(0xffffffffu, s, o);
    __syncthreads();
    if ((t & 31) == 0) red[t >> 5] = s;
    __syncthreads();
    if (t == 0) {
        float tot = 0.0f;
        #pragma unroll
        for (int i = 0; i < 8; ++i) tot += red[i];
        red[32] = 1.0f / tot;
    }
    __syncthreads();
    float inv = red[32];
    e.x *= inv; e.y *= inv; e.z *= inv; e.w *= inv;
    ((float4*)r)[t] = e;
}

// ---------------- attn @ V : per (b,h), out[b,q,h,d] layout (b*S+q)*512 + h*64 + d ----------------
__global__ __launch_bounds__(256) void av_kernel(const float* __restrict__ att,
                                                 const float* __restrict__ vmat,
                                                 float* __restrict__ out) {
    __shared__ float sAtt[16][132];
    __shared__ float sV[16][68];
    const int bh = blockIdx.y;
    const int b = bh >> 3, h = bh & 7;
    const int qc = blockIdx.x * 128;
    const int tid = threadIdx.x;
    const int tx = tid & 15;
    const int ty = tid >> 4;

    // att tile loads: 128 rows x 16 cols = 512 float4; idx = tid, tid+256
    const int ar0 = tid >> 2, ac0 = (tid & 3) * 4;
    const int ar1 = (tid + 256) >> 2, ac1 = ((tid + 256) & 3) * 4;
    // v tile loads: 16 rows x 64 cols = 256 float4
    const int vr = tid >> 4, vc = (tid & 15) * 4;

    float acc[8][4];
    #pragma unroll
    for (int i = 0; i < 8; ++i)
        #pragma unroll
        for (int j = 0; j < 4; ++j) acc[i][j] = 0.0f;

    for (int kt = 0; kt < SS_ / 16; ++kt) {
        float4 a0 = *(const float4*)(att + ((size_t)bh * SS_ + qc + ar0) * SS_ + kt * 16 + ac0);
        float4 a1 = *(const float4*)(att + ((size_t)bh * SS_ + qc + ar1) * SS_ + kt * 16 + ac1);
        float4 vv = *(const float4*)(vmat + ((size_t)(b * SS_ + kt * 16 + vr)) * DD + h * DKK + vc);
        __syncthreads();
        sAtt[ac0+0][ar0]=a0.x; sAtt[ac0+1][ar0]=a0.y; sAtt[ac0+2][ar0]=a0.z; sAtt[ac0+3][ar0]=a0.w;
        sAtt[ac1+0][ar1]=a1.x; sAtt[ac1+1][ar1]=a1.y; sAtt[ac1+2][ar1]=a1.z; sAtt[ac1+3][ar1]=a1.w;
        *(float4*)&sV[vr][vc] = vv;
        __syncthreads();
        #pragma unroll
        for (int k = 0; k < 16; ++k) {
            float a[8];
            float4 t0 = *(const float4*)&sAtt[k][ty * 4];
            float4 t1 = *(const float4*)&sAtt[k][64 + ty * 4];
            a[0]=t0.x; a[1]=t0.y; a[2]=t0.z; a[3]=t0.w; a[4]=t1.x; a[5]=t1.y; a[6]=t1.z; a[7]=t1.w;
            float4 bv = *(const float4*)&sV[k][tx * 4];
            float bj[4] = {bv.x, bv.y, bv.z, bv.w};
            #pragma unroll
            for (int i = 0; i < 8; ++i)
                #pragma unroll
                for (int j = 0; j < 4; ++j)
                    acc[i][j] += a[i] * bj[j];
        }
    }
    #pragma unroll
    for (int i = 0; i < 8; ++i) {
        int q = qc + ((i < 4) ? (ty * 4 + i) : (64 + ty * 4 + i - 4));
        float* o = out + ((size_t)(b * SS_ + q)) * DD + h * DKK + tx * 4;
        #pragma unroll
        for (int j = 0; j < 4; ++j) o[j] = acc[i][j];
    }
}

// ---------------- launch ----------------
extern "C" void kernel_launch(void* const* d_in, const int* in_sizes, int n_in,
                              void* d_out, int out_size) {
    const float* inputs        = (const float*)d_in[0];
    const unsigned char* amask = (const unsigned char*)d_in[1];
    const float* Wq = (const float*)d_in[2];
    const float* bq = (const float*)d_in[3];
    const float* Wk = (const float*)d_in[4];
    const float* bk = (const float*)d_in[5];
    const float* Wv = (const float*)d_in[6];
    const float* bv = (const float*)d_in[7];
    const float* Wo = (const float*)d_in[8];
    const float* bo = (const float*)d_in[9];
    const float* Wp = (const float*)d_in[10];
    const float* pu = (const float*)d_in[11];  // (H,DK) flat == per-column add
    const float* pv = (const float*)d_in[12];
    const float* gamma = (const float*)d_in[13];
    const float* beta  = (const float*)d_in[14];
    float* out = (float*)d_out;

    float *xn, *qu, *qv, *kk, *vv, *pe, *pp, *sc, *tmp;
    cudaGetSymbolAddress((void**)&xn, g_xn);
    cudaGetSymbolAddress((void**)&qu, g_qu);
    cudaGetSymbolAddress((void**)&qv, g_qv);
    cudaGetSymbolAddress((void**)&kk, g_k);
    cudaGetSymbolAddress((void**)&vv, g_v);
    cudaGetSymbolAddress((void**)&pe, g_pe);
    cudaGetSymbolAddress((void**)&pp, g_p);
    cudaGetSymbolAddress((void**)&sc, g_sc);
    cudaGetSymbolAddress((void**)&tmp, g_tmp);

    ln_kernel<<<BB * SS_, 128>>>(inputs, gamma, beta, xn);
    pe_kernel<<<PP_, 256>>>(pe);

    // projections
    gemm_nt<<<dim3(4, 32), 256>>>(xn, Wq, bq, qu, qv, pu, pv, BB * SS_);
    gemm_nt<<<dim3(4, 32), 256>>>(xn, Wk, bk, kk, nullptr, nullptr, nullptr, BB * SS_);
    gemm_nt<<<dim3(4, 32), 256>>>(xn, Wv, bv, vv, nullptr, nullptr, nullptr, BB * SS_);
    gemm_nt<<<dim3(4, 16), 256>>>(pe, Wp, nullptr, pp, nullptr, nullptr, nullptr, PP_);

    // fused AC+BD scores
    scores_kernel<<<dim3(8, 8, BB * HH), 256>>>(qu, qv, kk, pp, amask, sc);

    // softmax rows
    softmax_kernel<<<BB * HH * SS_, 256>>>(sc);

    // attn @ V
    av_kernel<<<dim3(8, BB * HH), 256>>>(sc, vv, tmp);

    // output projection
    gemm_nt<<<dim3(4, 32), 256>>>(tmp, Wo, bo, out, nullptr, nullptr, nullptr, BB * SS_);

    (void)in_sizes; (void)n_in; (void)out_size;
}

// round 4
// speedup vs baseline: 2.2968x; 1.4757x over previous
#include <cuda_runtime.h>
#include <cuda_bf16.h>
#include <math.h>
#include <stdint.h>

#define BB 4
#define SS_ 1024
#define DD 512
#define HH 8
#define DKK 64
#define PP_ 2047
#define PPAD 2048
#define PBAND 2304   // padded p rows (zero beyond 2047)

typedef __nv_bfloat16 bf16;

// ---------------- scratch (device globals, zero-initialized) ----------------
__device__ float g_xn[BB*SS_*DD];
__device__ float g_pe[PPAD*DD];
__device__ float g_sc[(size_t)BB*HH*SS_*SS_];   // 128MB scores fp32
__device__ bf16 g_xh[BB*SS_*DD], g_xl[BB*SS_*DD];
__device__ bf16 g_peh[PPAD*DD],  g_pel[PPAD*DD];
__device__ bf16 g_wh[5*DD*DD],   g_wl[5*DD*DD];
__device__ bf16 g_quh[BB*SS_*DD], g_qul[BB*SS_*DD];
__device__ bf16 g_qvh[BB*SS_*DD], g_qvl[BB*SS_*DD];
__device__ bf16 g_kh [BB*SS_*DD], g_kl [BB*SS_*DD];
__device__ bf16 g_vh [BB*SS_*DD], g_vl [BB*SS_*DD];
__device__ bf16 g_php[(size_t)PBAND*DD], g_ppl[(size_t)PBAND*DD];  // p rows 2048..2303 stay zero
__device__ bf16 g_ah[(size_t)BB*HH*SS_*SS_], g_al[(size_t)BB*HH*SS_*SS_]; // attn hi/lo
__device__ bf16 g_th[BB*SS_*DD], g_tl[BB*SS_*DD];

// ---------------- warp-mma helpers ----------------
__device__ __forceinline__ void mma16816(float* d, const uint32_t* a, const uint32_t* b){
    asm volatile("mma.sync.aligned.m16n8k16.row.col.f32.bf16.bf16.f32 "
        "{%0,%1,%2,%3}, {%4,%5,%6,%7}, {%8,%9}, {%0,%1,%2,%3};"
        : "+f"(d[0]),"+f"(d[1]),"+f"(d[2]),"+f"(d[3])
        : "r"(a[0]),"r"(a[1]),"r"(a[2]),"r"(a[3]), "r"(b[0]),"r"(b[1]));
}
__device__ __forceinline__ void ldsm4(uint32_t* r, uint32_t addr){
    asm volatile("ldmatrix.sync.aligned.m8n8.x4.shared.b16 {%0,%1,%2,%3}, [%4];"
        :"=r"(r[0]),"=r"(r[1]),"=r"(r[2]),"=r"(r[3]):"r"(addr));
}
__device__ __forceinline__ void ldsm4t(uint32_t* r, uint32_t addr){
    asm volatile("ldmatrix.sync.aligned.m8n8.x4.trans.shared.b16 {%0,%1,%2,%3}, [%4];"
        :"=r"(r[0]),"=r"(r[1]),"=r"(r[2]),"=r"(r[3]):"r"(addr));
}
__device__ __forceinline__ uint32_t smem_u32(const void* p){
    uint32_t a; asm("{ .reg .u64 t; cvta.to.shared.u64 t, %1; cvt.u32.u64 %0, t; }":"=r"(a):"l"(p)); return a;
}
static __device__ __forceinline__ uint32_t swz(uint32_t o){ return o ^ ((o>>3)&0x70); }
// A-operand fragment address (row-major m16 x k16 tile in a 128B-row smem plane)
__device__ __forceinline__ uint32_t a_addr(uint32_t base, int m16, int k0, int lane){
    int g = lane>>3, r = lane&7;
    int row = m16 + r + (g&1)*8;
    uint32_t o = (uint32_t)(row*128 + (k0 + (g>>1)*8)*2);
    return base + swz(o);
}
// B-operand ([n][k] storage) fragment address: n16 x k16 -> 4 regs = 2 n-tiles
__device__ __forceinline__ uint32_t b_addr(uint32_t base, int n0, int k0, int lane){
    int g = lane>>3, r = lane&7;
    int row = n0 + r + (g>>1)*8;
    uint32_t o = (uint32_t)(row*128 + (k0 + (g&1)*8)*2);
    return base + swz(o);
}
// V-operand ([k][d] storage, trans ldmatrix): k16 x d16 -> 2 n(d)-tiles
__device__ __forceinline__ uint32_t v_addr(uint32_t base, int k0, int d0, int lane){
    int g = lane>>3, r = lane&7;
    int row = k0 + r + (g&1)*8;
    uint32_t o = (uint32_t)(row*128 + (d0 + (g>>1)*8)*2);
    return base + swz(o);
}
__device__ __forceinline__ void pack_hilo(float x, float y, uint32_t& hi, uint32_t& lo){
    bf16 hx = __float2bfloat16(x), hy = __float2bfloat16(y);
    float rx = x - __bfloat162float(hx), ry = y - __bfloat162float(hy);
    bf16 lx = __float2bfloat16(rx), ly = __float2bfloat16(ry);
    hi = ((uint32_t)__bfloat16_as_ushort(hy)<<16) | __bfloat16_as_ushort(hx);
    lo = ((uint32_t)__bfloat16_as_ushort(ly)<<16) | __bfloat16_as_ushort(lx);
}

// ---------------- LayerNorm ----------------
__global__ void ln_kernel(const float* __restrict__ x, const float* __restrict__ gamma,
                          const float* __restrict__ beta, float* __restrict__ out) {
    __shared__ float red[4];
    int row = blockIdx.x; int t = threadIdx.x;
    float4 v = ((const float4*)(x + (size_t)row * DD))[t];
    float s = v.x+v.y+v.z+v.w;
    #pragma unroll
    for (int o=16;o;o>>=1) s += __shfl_xor_sync(0xffffffffu,s,o);
    if ((t&31)==0) red[t>>5]=s;
    __syncthreads();
    float mu=(red[0]+red[1]+red[2]+red[3])*(1.0f/DD);
    float dx=v.x-mu,dy=v.y-mu,dz=v.z-mu,dw=v.w-mu;
    float ss=dx*dx+dy*dy+dz*dz+dw*dw;
    #pragma unroll
    for (int o=16;o;o>>=1) ss += __shfl_xor_sync(0xffffffffu,ss,o);
    __syncthreads();
    if ((t&31)==0) red[t>>5]=ss;
    __syncthreads();
    float rstd=rsqrtf((red[0]+red[1]+red[2]+red[3])*(1.0f/DD)+1e-5f);
    float4 g=((const float4*)gamma)[t], be=((const float4*)beta)[t];
    float4 o4; o4.x=dx*rstd*g.x+be.x; o4.y=dy*rstd*g.y+be.y; o4.z=dz*rstd*g.z+be.z; o4.w=dw*rstd*g.w+be.w;
    ((float4*)(out+(size_t)row*DD))[t]=o4;
}

// ---------------- positional embedding (row 2047 zero) ----------------
__global__ void pe_kernel(float* __restrict__ pe) {
    int j = blockIdx.x; int t = threadIdx.x;
    if (j >= PP_) { pe[(size_t)j*DD+2*t]=0.f; pe[(size_t)j*DD+2*t+1]=0.f; return; }
    float pos = (float)(j - (SS_ - 1));
    const float kconst = -0.01798894603901598415f;
    float div = expf((float)(2*t) * kconst);
    float sa, ca; sincosf(pos * div, &sa, &ca);
    pe[(size_t)j*DD + 2*t] = sa; pe[(size_t)j*DD + 2*t + 1] = ca;
}

// ---------------- fp32 -> hi/lo bf16 planes ----------------
__global__ void cvt_kernel(const float* __restrict__ src, bf16* __restrict__ hi,
                           bf16* __restrict__ lo, int n4){
    int i = blockIdx.x * 256 + threadIdx.x;
    if (i >= n4) return;
    float4 v = ((const float4*)src)[i];
    uint32_t h0,l0,h1,l1;
    pack_hilo(v.x, v.y, h0, l0);
    pack_hilo(v.z, v.w, h1, l1);
    ((uint2*)hi)[i] = make_uint2(h0,h1);
    ((uint2*)lo)[i] = make_uint2(l0,l1);
}

// ================= generic MMA GEMM: C[M,512] = A[M,512] @ B[512,512]^T =================
// modes: O32 != null -> fp32 out (+bias). Else hi/lo out Oh0/Ol0 (+bias); if Oh1: dual add0/add1.
__global__ __launch_bounds__(256) void gemm_mma(
    const bf16* __restrict__ Ah, const bf16* __restrict__ Al,
    const bf16* __restrict__ Bh, const bf16* __restrict__ Bl,
    const float* __restrict__ bias, const float* __restrict__ add0, const float* __restrict__ add1,
    bf16* __restrict__ Oh0, bf16* __restrict__ Ol0,
    bf16* __restrict__ Oh1, bf16* __restrict__ Ol1, float* __restrict__ O32)
{
    extern __shared__ char sm[];
    const int tid = threadIdx.x, lane = tid & 31, wid = tid >> 5;
    const int bm = blockIdx.y * 128, bn = blockIdx.x * 128;
    const uint32_t sb = smem_u32(sm);
    const int m0w = (wid>>2)*64, n0w = (wid&3)*32;

    float acc[4][4][4];
    #pragma unroll
    for (int a=0;a<4;++a)
        #pragma unroll
        for (int b=0;b<4;++b)
            #pragma unroll
            for (int c=0;c<4;++c) acc[a][b][c]=0.f;

    for (int kc = 0; kc < 8; ++kc) {
        for (int u = tid; u < 1024; u += 256) {
            int row = u>>3, cb = u&7;
            uint32_t off = swz((uint32_t)(row*128 + cb*16));
            size_t gA = (size_t)(bm+row)*DD + kc*64 + cb*8;
            size_t gB = (size_t)(bn+row)*DD + kc*64 + cb*8;
            *(uint4*)(sm + off)         = *(const uint4*)(Ah + gA);
            *(uint4*)(sm + 16384 + off) = *(const uint4*)(Al + gA);
            *(uint4*)(sm + 32768 + off) = *(const uint4*)(Bh + gB);
            *(uint4*)(sm + 49152 + off) = *(const uint4*)(Bl + gB);
        }
        __syncthreads();
        #pragma unroll
        for (int ks = 0; ks < 4; ++ks) {
            int k0 = ks*16;
            uint32_t aH[4][4], aL[4][4], bH[2][4], bL[2][4];
            #pragma unroll
            for (int mt=0; mt<4; ++mt) {
                ldsm4(aH[mt], a_addr(sb,        m0w+mt*16, k0, lane));
                ldsm4(aL[mt], a_addr(sb+16384,  m0w+mt*16, k0, lane));
            }
            #pragma unroll
            for (int p=0; p<2; ++p) {
                ldsm4(bH[p], b_addr(sb+32768, n0w+p*16, k0, lane));
                ldsm4(bL[p], b_addr(sb+49152, n0w+p*16, k0, lane));
            }
            #pragma unroll
            for (int mt=0; mt<4; ++mt)
                #pragma unroll
                for (int nt=0; nt<4; ++nt) {
                    const uint32_t* bh_ = &bH[nt>>1][(nt&1)*2];
                    const uint32_t* bl_ = &bL[nt>>1][(nt&1)*2];
                    mma16816(acc[mt][nt], aH[mt], bh_);
                    mma16816(acc[mt][nt], aH[mt], bl_);
                    mma16816(acc[mt][nt], aL[mt], bh_);
                }
        }
        __syncthreads();
    }
    // epilogue
    const int r = lane>>2, c = (lane&3)*2;
    #pragma unroll
    for (int mt=0; mt<4; ++mt)
        #pragma unroll
        for (int nt=0; nt<4; ++nt) {
            int n_ = bn + n0w + nt*8 + c;
            float b0 = bias ? bias[n_] : 0.f, b1 = bias ? bias[n_+1] : 0.f;
            #pragma unroll
            for (int half=0; half<2; ++half) {
                int m_ = bm + m0w + mt*16 + r + half*8;
                float v0 = acc[mt][nt][half*2+0] + b0;
                float v1 = acc[mt][nt][half*2+1] + b1;
                if (O32) {
                    *(float2*)(O32 + (size_t)m_*DD + n_) = make_float2(v0, v1);
                } else if (Oh1) {
                    uint32_t h,l;
                    pack_hilo(v0 + add0[n_], v1 + add0[n_+1], h, l);
                    *(uint32_t*)(Oh0 + (size_t)m_*DD + n_) = h;
                    *(uint32_t*)(Ol0 + (size_t)m_*DD + n_) = l;
                    pack_hilo(v0 + add1[n_], v1 + add1[n_+1], h, l);
                    *(uint32_t*)(Oh1 + (size_t)m_*DD + n_) = h;
                    *(uint32_t*)(Ol1 + (size_t)m_*DD + n_) = l;
                } else {
                    uint32_t h,l;
                    pack_hilo(v0, v1, h, l);
                    *(uint32_t*)(Oh0 + (size_t)m_*DD + n_) = h;
                    *(uint32_t*)(Ol0 + (size_t)m_*DD + n_) = l;
                }
            }
        }
}

// ================= scores: BD (banded, scattered) then AC, fused epilogue =================
__global__ __launch_bounds__(256) void scores_mma(
    const bf16* __restrict__ qvh, const bf16* __restrict__ qvl,
    const bf16* __restrict__ quh, const bf16* __restrict__ qul,
    const bf16* __restrict__ kh,  const bf16* __restrict__ kl,
    const bf16* __restrict__ ph,  const bf16* __restrict__ pl,
    const unsigned char* __restrict__ mask, float* __restrict__ sc)
{
    extern __shared__ char sm[];
    const int tid = threadIdx.x, lane = tid & 31, wid = tid >> 5;
    const int bh = blockIdx.z, b = bh >> 3, h = bh & 7;
    const int qc = blockIdx.y * 128, kc = blockIdx.x * 128;
    const int pbase = 1024 + kc - qc - 127;   // in [1, 1921]
    const uint32_t sb = smem_u32(sm);
    float* bd = (float*)(sm + 98304);
    const int m0w = (wid>>2)*64, n0w = (wid&3)*32;
    const int r = lane>>2, c = (lane&3)*2;

    // load Qv (A) + P band (B, 256 rows)
    for (int u = tid; u < 1024; u += 256) {
        int row = u>>3, cb = u&7;
        uint32_t off = swz((uint32_t)(row*128 + cb*16));
        size_t g = (size_t)(b*SS_ + qc + row)*DD + h*DKK + cb*8;
        *(uint4*)(sm + off)         = *(const uint4*)(qvh + g);
        *(uint4*)(sm + 16384 + off) = *(const uint4*)(qvl + g);
    }
    for (int u = tid; u < 2048; u += 256) {
        int row = u>>3, cb = u&7;
        uint32_t off = swz((uint32_t)(row*128 + cb*16));
        size_t g = (size_t)(pbase + row)*DD + h*DKK + cb*8;
        *(uint4*)(sm + 32768 + off) = *(const uint4*)(ph + g);
        *(uint4*)(sm + 65536 + off) = *(const uint4*)(pl + g);
    }
    __syncthreads();

    // BD: two n=128 passes, scatter j = t + i - 127
    #pragma unroll
    for (int pass = 0; pass < 2; ++pass) {
        float acc[4][4][4];
        #pragma unroll
        for (int a=0;a<4;++a)
            #pragma unroll
            for (int bq=0;bq<4;++bq)
                #pragma unroll
                for (int e=0;e<4;++e) acc[a][bq][e]=0.f;
        #pragma unroll
        for (int ks = 0; ks < 4; ++ks) {
            int k0 = ks*16;
            uint32_t aH[4][4], aL[4][4], bH[2][4], bL[2][4];
            #pragma unroll
            for (int mt=0; mt<4; ++mt) {
                ldsm4(aH[mt], a_addr(sb,       m0w+mt*16, k0, lane));
                ldsm4(aL[mt], a_addr(sb+16384, m0w+mt*16, k0, lane));
            }
            #pragma unroll
            for (int p=0; p<2; ++p) {
                ldsm4(bH[p], b_addr(sb+32768, pass*128 + n0w + p*16, k0, lane));
                ldsm4(bL[p], b_addr(sb+65536, pass*128 + n0w + p*16, k0, lane));
            }
            #pragma unroll
            for (int mt=0; mt<4; ++mt)
                #pragma unroll
                for (int nt=0; nt<4; ++nt) {
                    const uint32_t* bh_ = &bH[nt>>1][(nt&1)*2];
                    const uint32_t* bl_ = &bL[nt>>1][(nt&1)*2];
                    mma16816(acc[mt][nt], aH[mt], bh_);
                    mma16816(acc[mt][nt], aH[mt], bl_);
                    mma16816(acc[mt][nt], aL[mt], bh_);
                }
        }
        #pragma unroll
        for (int mt=0; mt<4; ++mt)
            #pragma unroll
            for (int nt=0; nt<4; ++nt)
                #pragma unroll
                for (int half=0; half<2; ++half) {
                    int i = m0w + mt*16 + r + half*8;
                    #pragma unroll
                    for (int cc=0; cc<2; ++cc) {
                        int t = pass*128 + n0w + nt*8 + c + cc;
                        int j = t + i - 127;
                        if (j >= 0 && j < 128) bd[i*132 + j] = acc[mt][nt][half*2+cc];
                    }
                }
    }
    __syncthreads();

    // reload A=Qu, B=K
    for (int u = tid; u < 1024; u += 256) {
        int row = u>>3, cb = u&7;
        uint32_t off = swz((uint32_t)(row*128 + cb*16));
        size_t gq = (size_t)(b*SS_ + qc + row)*DD + h*DKK + cb*8;
        size_t gk = (size_t)(b*SS_ + kc + row)*DD + h*DKK + cb*8;
        *(uint4*)(sm + off)         = *(const uint4*)(quh + gq);
        *(uint4*)(sm + 16384 + off) = *(const uint4*)(qul + gq);
        *(uint4*)(sm + 32768 + off) = *(const uint4*)(kh + gk);
        *(uint4*)(sm + 65536 + off) = *(const uint4*)(kl + gk);
    }
    __syncthreads();

    float acc[4][4][4];
    #pragma unroll
    for (int a=0;a<4;++a)
        #pragma unroll
        for (int bq=0;bq<4;++bq)
            #pragma unroll
            for (int e=0;e<4;++e) acc[a][bq][e]=0.f;
    #pragma unroll
    for (int ks = 0; ks < 4; ++ks) {
        int k0 = ks*16;
        uint32_t aH[4][4], aL[4][4], bH[2][4], bL[2][4];
        #pragma unroll
        for (int mt=0; mt<4; ++mt) {
            ldsm4(aH[mt], a_addr(sb,       m0w+mt*16, k0, lane));
            ldsm4(aL[mt], a_addr(sb+16384, m0w+mt*16, k0, lane));
        }
        #pragma unroll
        for (int p=0; p<2; ++p) {
            ldsm4(bH[p], b_addr(sb+32768, n0w+p*16, k0, lane));
            ldsm4(bL[p], b_addr(sb+65536, n0w+p*16, k0, lane));
        }
        #pragma unroll
        for (int mt=0; mt<4; ++mt)
            #pragma unroll
            for (int nt=0; nt<4; ++nt) {
                const uint32_t* bh_ = &bH[nt>>1][(nt&1)*2];
                const uint32_t* bl_ = &bL[nt>>1][(nt&1)*2];
                mma16816(acc[mt][nt], aH[mt], bh_);
                mma16816(acc[mt][nt], aH[mt], bl_);
                mma16816(acc[mt][nt], aL[mt], bh_);
            }
    }

    // epilogue: (AC + BD)/8, wrap, mask, store
    #pragma unroll
    for (int mt=0; mt<4; ++mt)
        #pragma unroll
        for (int nt=0; nt<4; ++nt) {
            int jc = n0w + nt*8 + c;
            int kg = kc + jc;
            #pragma unroll
            for (int half=0; half<2; ++half) {
                int i = m0w + mt*16 + r + half*8;
                int q = qc + i;
                float v0 = (acc[mt][nt][half*2+0] + bd[i*132 + jc    ]) * 0.125f;
                float v1 = (acc[mt][nt][half*2+1] + bd[i*132 + jc + 1]) * 0.125f;
                if (q == 0 && kg + 1 == SS_ - 1) {
                    float s = 0.f;
                    #pragma unroll
                    for (int d = 0; d < DKK; ++d) {
                        float qq = __bfloat162float(qvh[(size_t)(b*SS_+1)*DD + h*DKK + d])
                                 + __bfloat162float(qvl[(size_t)(b*SS_+1)*DD + h*DKK + d]);
                        float pp = __bfloat162float(ph[h*DKK + d]) + __bfloat162float(pl[h*DKK + d]);
                        s += qq * pp;
                    }
                    v1 += s * 0.125f;
                }
                const unsigned char* mrow = mask + (size_t)b*SS_*SS_ + (size_t)q*SS_ + kg;
                if (mrow[0]) v0 = -10000.0f;
                if (mrow[1]) v1 = -10000.0f;
                *(float2*)(sc + ((size_t)bh*SS_ + q)*SS_ + kg) = make_float2(v0, v1);
            }
        }
}

// ---------------- softmax: fp32 scores -> hi/lo bf16 attn ----------------
__global__ void softmax_kernel(const float* __restrict__ sc, bf16* __restrict__ ah, bf16* __restrict__ al) {
    __shared__ float red[33];
    size_t row = blockIdx.x;
    const float* rp = sc + row * SS_;
    int t = threadIdx.x;
    float4 v = ((const float4*)rp)[t];
    float m = fmaxf(fmaxf(v.x,v.y), fmaxf(v.z,v.w));
    #pragma unroll
    for (int o=16;o;o>>=1) m = fmaxf(m, __shfl_xor_sync(0xffffffffu,m,o));
    if ((t&31)==0) red[t>>5]=m;
    __syncthreads();
    if (t==0){ float mm=red[0]; for(int i=1;i<8;++i) mm=fmaxf(mm,red[i]); red[32]=mm; }
    __syncthreads();
    m = red[32];
    float4 e;
    e.x=expf(v.x-m); e.y=expf(v.y-m); e.z=expf(v.z-m); e.w=expf(v.w-m);
    float s = e.x+e.y+e.z+e.w;
    #pragma unroll
    for (int o=16;o;o>>=1) s += __shfl_xor_sync(0xffffffffu,s,o);
    __syncthreads();
    if ((t&31)==0) red[t>>5]=s;
    __syncthreads();
    if (t==0){ float tot=0.f; for(int i=0;i<8;++i) tot+=red[i]; red[32]=1.0f/tot; }
    __syncthreads();
    float inv = red[32];
    e.x*=inv; e.y*=inv; e.z*=inv; e.w*=inv;
    uint32_t h0,l0,h1,l1;
    pack_hilo(e.x, e.y, h0, l0);
    pack_hilo(e.z, e.w, h1, l1);
    ((uint2*)(ah + row*SS_))[t] = make_uint2(h0,h1);
    ((uint2*)(al + row*SS_))[t] = make_uint2(l0,l1);
}

// ================= attn @ V (MMA, trans-B), writes hi/lo tmp =================
__global__ __launch_bounds__(256) void av_mma(
    const bf16* __restrict__ ah, const bf16* __restrict__ al,
    const bf16* __restrict__ vh, const bf16* __restrict__ vl,
    bf16* __restrict__ th, bf16* __restrict__ tl)
{
    extern __shared__ char sm[];
    const int tid = threadIdx.x, lane = tid & 31, wid = tid >> 5;
    const int bh = blockIdx.y, b = bh >> 3, h = bh & 7;
    const int qc = blockIdx.x * 128;
    const uint32_t sb = smem_u32(sm);
    const int m0w = (wid>>1)*32, n0w = (wid&1)*32;
    const int r = lane>>2, c = (lane&3)*2;

    float acc[2][4][4];
    #pragma unroll
    for (int a=0;a<2;++a)
        #pragma unroll
        for (int bq=0;bq<4;++bq)
            #pragma unroll
            for (int e=0;e<4;++e) acc[a][bq][e]=0.f;

    for (int kn = 0; kn < 16; ++kn) {
        for (int u = tid; u < 1024; u += 256) {
            int row = u>>3, cb = u&7;
            uint32_t off = swz((uint32_t)(row*128 + cb*16));
            size_t g = (size_t)(bh*SS_ + qc + row)*SS_ + kn*64 + cb*8;
            *(uint4*)(sm + off)         = *(const uint4*)(ah + g);
            *(uint4*)(sm + 16384 + off) = *(const uint4*)(al + g);
        }
        for (int u = tid; u < 512; u += 256) {
            int row = u>>3, cb = u&7;
            uint32_t off = swz((uint32_t)(row*128 + cb*16));
            size_t g = (size_t)(b*SS_ + kn*64 + row)*DD + h*DKK + cb*8;
            *(uint4*)(sm + 32768 + off) = *(const uint4*)(vh + g);
            *(uint4*)(sm + 40960 + off) = *(const uint4*)(vl + g);
        }
        __syncthreads();
        #pragma unroll
        for (int ks = 0; ks < 4; ++ks) {
            int k0 = ks*16;
            uint32_t aH[2][4], aL[2][4], bH[2][4], bL[2][4];
            #pragma unroll
            for (int mt=0; mt<2; ++mt) {
                ldsm4(aH[mt], a_addr(sb,       m0w+mt*16, k0, lane));
                ldsm4(aL[mt], a_addr(sb+16384, m0w+mt*16, k0, lane));
            }
            #pragma unroll
            for (int p=0; p<2; ++p) {
                ldsm4t(bH[p], v_addr(sb+32768, k0, n0w+p*16, lane));
                ldsm4t(bL[p], v_addr(sb+40960, k0, n0w+p*16, lane));
            }
            #pragma unroll
            for (int mt=0; mt<2; ++mt)
                #pragma unroll
                for (int nt=0; nt<4; ++nt) {
                    const uint32_t* bh_ = &bH[nt>>1][(nt&1)*2];
                    const uint32_t* bl_ = &bL[nt>>1][(nt&1)*2];
                    mma16816(acc[mt][nt], aH[mt], bh_);
                    mma16816(acc[mt][nt], aH[mt], bl_);
                    mma16816(acc[mt][nt], aL[mt], bh_);
                }
        }
        __syncthreads();
    }
    #pragma unroll
    for (int mt=0; mt<2; ++mt)
        #pragma unroll
        for (int nt=0; nt<4; ++nt) {
            int d = n0w + nt*8 + c;
            #pragma unroll
            for (int half=0; half<2; ++half) {
                int q = qc + m0w + mt*16 + r + half*8;
                uint32_t hh, ll;
                pack_hilo(acc[mt][nt][half*2+0], acc[mt][nt][half*2+1], hh, ll);
                *(uint32_t*)(th + (size_t)(b*SS_+q)*DD + h*DKK + d) = hh;
                *(uint32_t*)(tl + (size_t)(b*SS_+q)*DD + h*DKK + d) = ll;
            }
        }
}

// ---------------- launch ----------------
extern "C" void kernel_launch(void* const* d_in, const int* in_sizes, int n_in,
                              void* d_out, int out_size) {
    const float* inputs        = (const float*)d_in[0];
    const unsigned char* amask = (const unsigned char*)d_in[1];
    const float* Wq = (const float*)d_in[2];
    const float* bq = (const float*)d_in[3];
    const float* Wk = (const float*)d_in[4];
    const float* bk = (const float*)d_in[5];
    const float* Wv = (const float*)d_in[6];
    const float* bv = (const float*)d_in[7];
    const float* Wo = (const float*)d_in[8];
    const float* bo = (const float*)d_in[9];
    const float* Wp = (const float*)d_in[10];
    const float* pu = (const float*)d_in[11];
    const float* pv = (const float*)d_in[12];
    const float* gamma = (const float*)d_in[13];
    const float* beta  = (const float*)d_in[14];
    float* out = (float*)d_out;

    float *xn, *pe, *sc;
    bf16 *xh,*xl,*peh,*pel,*wh,*wl,*quh,*qul,*qvh,*qvl,*kh,*kl,*vh,*vl,*php,*ppl,*ah,*al,*th,*tl;
    cudaGetSymbolAddress((void**)&xn, g_xn);
    cudaGetSymbolAddress((void**)&pe, g_pe);
    cudaGetSymbolAddress((void**)&sc, g_sc);
    cudaGetSymbolAddress((void**)&xh, g_xh);   cudaGetSymbolAddress((void**)&xl, g_xl);
    cudaGetSymbolAddress((void**)&peh, g_peh); cudaGetSymbolAddress((void**)&pel, g_pel);
    cudaGetSymbolAddress((void**)&wh, g_wh);   cudaGetSymbolAddress((void**)&wl, g_wl);
    cudaGetSymbolAddress((void**)&quh, g_quh); cudaGetSymbolAddress((void**)&qul, g_qul);
    cudaGetSymbolAddress((void**)&qvh, g_qvh); cudaGetSymbolAddress((void**)&qvl, g_qvl);
    cudaGetSymbolAddress((void**)&kh, g_kh);   cudaGetSymbolAddress((void**)&kl, g_kl);
    cudaGetSymbolAddress((void**)&vh, g_vh);   cudaGetSymbolAddress((void**)&vl, g_vl);
    cudaGetSymbolAddress((void**)&php, g_php); cudaGetSymbolAddress((void**)&ppl, g_ppl);
    cudaGetSymbolAddress((void**)&ah, g_ah);   cudaGetSymbolAddress((void**)&al, g_al);
    cudaGetSymbolAddress((void**)&th, g_th);   cudaGetSymbolAddress((void**)&tl, g_tl);

    cudaFuncSetAttribute(gemm_mma,   cudaFuncAttributeMaxDynamicSharedMemorySize, 65536);
    cudaFuncSetAttribute(scores_mma, cudaFuncAttributeMaxDynamicSharedMemorySize, 165888);
    cudaFuncSetAttribute(av_mma,     cudaFuncAttributeMaxDynamicSharedMemorySize, 49152);

    ln_kernel<<<BB*SS_, 128>>>(inputs, gamma, beta, xn);
    pe_kernel<<<PPAD, 256>>>(pe);

    cvt_kernel<<<2048, 256>>>(xn, xh, xl, BB*SS_*DD/4);
    cvt_kernel<<<1024, 256>>>(pe, peh, pel, PPAD*DD/4);
    cvt_kernel<<<256, 256>>>(Wq, wh + 0*DD*DD, wl + 0*DD*DD, DD*DD/4);
    cvt_kernel<<<256, 256>>>(Wk, wh + 1*DD*DD, wl + 1*DD*DD, DD*DD/4);
    cvt_kernel<<<256, 256>>>(Wv, wh + 2*DD*DD, wl + 2*DD*DD, DD*DD/4);
    cvt_kernel<<<256, 256>>>(Wo, wh + 3*DD*DD, wl + 3*DD*DD, DD*DD/4);
    cvt_kernel<<<256, 256>>>(Wp, wh + 4*DD*DD, wl + 4*DD*DD, DD*DD/4);

    // projections (warp-MMA, split-bf16)
    gemm_mma<<<dim3(4,32), 256, 65536>>>(xh, xl, wh+0*DD*DD, wl+0*DD*DD, bq, pu, pv,
                                          quh, qul, qvh, qvl, nullptr);
    gemm_mma<<<dim3(4,32), 256, 65536>>>(xh, xl, wh+1*DD*DD, wl+1*DD*DD, bk, nullptr, nullptr,
                                          kh, kl, nullptr, nullptr, nullptr);
    gemm_mma<<<dim3(4,32), 256, 65536>>>(xh, xl, wh+2*DD*DD, wl+2*DD*DD, bv, nullptr, nullptr,
                                          vh, vl, nullptr, nullptr, nullptr);
    gemm_mma<<<dim3(4,16), 256, 65536>>>(peh, pel, wh+4*DD*DD, wl+4*DD*DD, nullptr, nullptr, nullptr,
                                          php, ppl, nullptr, nullptr, nullptr);

    scores_mma<<<dim3(8,8,BB*HH), 256, 165888>>>(qvh, qvl, quh, qul, kh, kl, php, ppl, amask, sc);
    softmax_kernel<<<BB*HH*SS_, 256>>>(sc, ah, al);
    av_mma<<<dim3(8, BB*HH), 256, 49152>>>(ah, al, vh, vl, th, tl);

    gemm_mma<<<dim3(4,32), 256, 65536>>>(th, tl, wh+3*DD*DD, wl+3*DD*DD, bo, nullptr, nullptr,
                                          nullptr, nullptr, nullptr, nullptr, out);

    (void)in_sizes; (void)n_in; (void)out_size;
}

// round 5
// speedup vs baseline: 2.8478x; 1.2399x over previous
#include <cuda_runtime.h>
#include <cuda_bf16.h>
#include <math.h>
#include <stdint.h>

#define BB 4
#define SS_ 1024
#define DD 512
#define HH 8
#define DKK 64
#define PP_ 2047
#define PPAD 2048
#define PBAND 2304

typedef __nv_bfloat16 bf16;

// ---------------- scratch ----------------
__device__ float g_xn[BB*SS_*DD];
__device__ float g_pe[PPAD*DD];
__device__ bf16 g_xh[BB*SS_*DD], g_xl[BB*SS_*DD];
__device__ bf16 g_peh[PPAD*DD],  g_pel[PPAD*DD];
__device__ bf16 g_wh[5*DD*DD],   g_wl[5*DD*DD];
__device__ bf16 g_quh[BB*SS_*DD], g_qul[BB*SS_*DD];
__device__ bf16 g_qvh[BB*SS_*DD], g_qvl[BB*SS_*DD];
__device__ bf16 g_kh [BB*SS_*DD], g_kl [BB*SS_*DD];
__device__ bf16 g_vh [BB*SS_*DD], g_vl [BB*SS_*DD];
__device__ bf16 g_php[(size_t)PBAND*DD], g_ppl[(size_t)PBAND*DD];
__device__ bf16 g_th[BB*SS_*DD], g_tl[BB*SS_*DD];

// ---------------- warp-mma helpers ----------------
__device__ __forceinline__ void mma16816(float* d, const uint32_t* a, const uint32_t* b){
    asm volatile("mma.sync.aligned.m16n8k16.row.col.f32.bf16.bf16.f32 "
        "{%0,%1,%2,%3}, {%4,%5,%6,%7}, {%8,%9}, {%0,%1,%2,%3};"
        : "+f"(d[0]),"+f"(d[1]),"+f"(d[2]),"+f"(d[3])
        : "r"(a[0]),"r"(a[1]),"r"(a[2]),"r"(a[3]), "r"(b[0]),"r"(b[1]));
}
__device__ __forceinline__ void ldsm4(uint32_t* r, uint32_t addr){
    asm volatile("ldmatrix.sync.aligned.m8n8.x4.shared.b16 {%0,%1,%2,%3}, [%4];"
        :"=r"(r[0]),"=r"(r[1]),"=r"(r[2]),"=r"(r[3]):"r"(addr));
}
__device__ __forceinline__ void ldsm4t(uint32_t* r, uint32_t addr){
    asm volatile("ldmatrix.sync.aligned.m8n8.x4.trans.shared.b16 {%0,%1,%2,%3}, [%4];"
        :"=r"(r[0]),"=r"(r[1]),"=r"(r[2]),"=r"(r[3]):"r"(addr));
}
__device__ __forceinline__ uint32_t smem_u32(const void* p){
    uint32_t a; asm("{ .reg .u64 t; cvta.to.shared.u64 t, %1; cvt.u32.u64 %0, t; }":"=r"(a):"l"(p)); return a;
}
static __device__ __forceinline__ uint32_t swz(uint32_t o){ return o ^ ((o>>3)&0x70); }
__device__ __forceinline__ uint32_t a_addr(uint32_t base, int m16, int k0, int lane){
    int g = lane>>3, r = lane&7;
    int row = m16 + r + (g&1)*8;
    uint32_t o = (uint32_t)(row*128 + (k0 + (g>>1)*8)*2);
    return base + swz(o);
}
__device__ __forceinline__ uint32_t b_addr(uint32_t base, int n0, int k0, int lane){
    int g = lane>>3, r = lane&7;
    int row = n0 + r + (g>>1)*8;
    uint32_t o = (uint32_t)(row*128 + (k0 + (g&1)*8)*2);
    return base + swz(o);
}
__device__ __forceinline__ uint32_t v_addr(uint32_t base, int k0, int d0, int lane){
    int g = lane>>3, r = lane&7;
    int row = k0 + r + (g&1)*8;
    uint32_t o = (uint32_t)(row*128 + (d0 + (g>>1)*8)*2);
    return base + swz(o);
}
__device__ __forceinline__ void pack_hilo(float x, float y, uint32_t& hi, uint32_t& lo){
    bf16 hx = __float2bfloat16(x), hy = __float2bfloat16(y);
    float rx = x - __bfloat162float(hx), ry = y - __bfloat162float(hy);
    bf16 lx = __float2bfloat16(rx), ly = __float2bfloat16(ry);
    hi = ((uint32_t)__bfloat16_as_ushort(hy)<<16) | __bfloat16_as_ushort(hx);
    lo = ((uint32_t)__bfloat16_as_ushort(ly)<<16) | __bfloat16_as_ushort(lx);
}

// ---------------- LayerNorm ----------------
__global__ void ln_kernel(const float* __restrict__ x, const float* __restrict__ gamma,
                          const float* __restrict__ beta, float* __restrict__ out) {
    __shared__ float red[4];
    int row = blockIdx.x; int t = threadIdx.x;
    float4 v = ((const float4*)(x + (size_t)row * DD))[t];
    float s = v.x+v.y+v.z+v.w;
    #pragma unroll
    for (int o=16;o;o>>=1) s += __shfl_xor_sync(0xffffffffu,s,o);
    if ((t&31)==0) red[t>>5]=s;
    __syncthreads();
    float mu=(red[0]+red[1]+red[2]+red[3])*(1.0f/DD);
    float dx=v.x-mu,dy=v.y-mu,dz=v.z-mu,dw=v.w-mu;
    float ss=dx*dx+dy*dy+dz*dz+dw*dw;
    #pragma unroll
    for (int o=16;o;o>>=1) ss += __shfl_xor_sync(0xffffffffu,ss,o);
    __syncthreads();
    if ((t&31)==0) red[t>>5]=ss;
    __syncthreads();
    float rstd=rsqrtf((red[0]+red[1]+red[2]+red[3])*(1.0f/DD)+1e-5f);
    float4 g=((const float4*)gamma)[t], be=((const float4*)beta)[t];
    float4 o4; o4.x=dx*rstd*g.x+be.x; o4.y=dy*rstd*g.y+be.y; o4.z=dz*rstd*g.z+be.z; o4.w=dw*rstd*g.w+be.w;
    ((float4*)(out+(size_t)row*DD))[t]=o4;
}

// ---------------- positional embedding (row 2047 zero) ----------------
__global__ void pe_kernel(float* __restrict__ pe) {
    int j = blockIdx.x; int t = threadIdx.x;
    if (j >= PP_) { pe[(size_t)j*DD+2*t]=0.f; pe[(size_t)j*DD+2*t+1]=0.f; return; }
    float pos = (float)(j - (SS_ - 1));
    const float kconst = -0.01798894603901598415f;
    float div = expf((float)(2*t) * kconst);
    float sa, ca; sincosf(pos * div, &sa, &ca);
    pe[(size_t)j*DD + 2*t] = sa; pe[(size_t)j*DD + 2*t + 1] = ca;
}

// ---------------- fp32 -> hi/lo bf16 planes ----------------
__global__ void cvt_kernel(const float* __restrict__ src, bf16* __restrict__ hi,
                           bf16* __restrict__ lo, int n4){
    int i = blockIdx.x * 256 + threadIdx.x;
    if (i >= n4) return;
    float4 v = ((const float4*)src)[i];
    uint32_t h0,l0,h1,l1;
    pack_hilo(v.x, v.y, h0, l0);
    pack_hilo(v.z, v.w, h1, l1);
    ((uint2*)hi)[i] = make_uint2(h0,h1);
    ((uint2*)lo)[i] = make_uint2(l0,l1);
}

// ================= generic MMA GEMM (unchanged from R4) =================
__global__ __launch_bounds__(256) void gemm_mma(
    const bf16* __restrict__ Ah, const bf16* __restrict__ Al,
    const bf16* __restrict__ Bh, const bf16* __restrict__ Bl,
    const float* __restrict__ bias, const float* __restrict__ add0, const float* __restrict__ add1,
    bf16* __restrict__ Oh0, bf16* __restrict__ Ol0,
    bf16* __restrict__ Oh1, bf16* __restrict__ Ol1, float* __restrict__ O32)
{
    extern __shared__ char sm[];
    const int tid = threadIdx.x, lane = tid & 31, wid = tid >> 5;
    const int bm = blockIdx.y * 128, bn = blockIdx.x * 128;
    const uint32_t sb = smem_u32(sm);
    const int m0w = (wid>>2)*64, n0w = (wid&3)*32;

    float acc[4][4][4];
    #pragma unroll
    for (int a=0;a<4;++a)
        #pragma unroll
        for (int b=0;b<4;++b)
            #pragma unroll
            for (int c=0;c<4;++c) acc[a][b][c]=0.f;

    for (int kc = 0; kc < 8; ++kc) {
        for (int u = tid; u < 1024; u += 256) {
            int row = u>>3, cb = u&7;
            uint32_t off = swz((uint32_t)(row*128 + cb*16));
            size_t gA = (size_t)(bm+row)*DD + kc*64 + cb*8;
            size_t gB = (size_t)(bn+row)*DD + kc*64 + cb*8;
            *(uint4*)(sm + off)         = *(const uint4*)(Ah + gA);
            *(uint4*)(sm + 16384 + off) = *(const uint4*)(Al + gA);
            *(uint4*)(sm + 32768 + off) = *(const uint4*)(Bh + gB);
            *(uint4*)(sm + 49152 + off) = *(const uint4*)(Bl + gB);
        }
        __syncthreads();
        #pragma unroll
        for (int ks = 0; ks < 4; ++ks) {
            int k0 = ks*16;
            uint32_t aH[4][4], aL[4][4], bH[2][4], bL[2][4];
            #pragma unroll
            for (int mt=0; mt<4; ++mt) {
                ldsm4(aH[mt], a_addr(sb,        m0w+mt*16, k0, lane));
                ldsm4(aL[mt], a_addr(sb+16384,  m0w+mt*16, k0, lane));
            }
            #pragma unroll
            for (int p=0; p<2; ++p) {
                ldsm4(bH[p], b_addr(sb+32768, n0w+p*16, k0, lane));
                ldsm4(bL[p], b_addr(sb+49152, n0w+p*16, k0, lane));
            }
            #pragma unroll
            for (int mt=0; mt<4; ++mt)
                #pragma unroll
                for (int nt=0; nt<4; ++nt) {
                    const uint32_t* bh_ = &bH[nt>>1][(nt&1)*2];
                    const uint32_t* bl_ = &bL[nt>>1][(nt&1)*2];
                    mma16816(acc[mt][nt], aH[mt], bh_);
                    mma16816(acc[mt][nt], aH[mt], bl_);
                    mma16816(acc[mt][nt], aL[mt], bh_);
                }
        }
        __syncthreads();
    }
    const int r = lane>>2, c = (lane&3)*2;
    #pragma unroll
    for (int mt=0; mt<4; ++mt)
        #pragma unroll
        for (int nt=0; nt<4; ++nt) {
            int n_ = bn + n0w + nt*8 + c;
            float b0 = bias ? bias[n_] : 0.f, b1 = bias ? bias[n_+1] : 0.f;
            #pragma unroll
            for (int half=0; half<2; ++half) {
                int m_ = bm + m0w + mt*16 + r + half*8;
                float v0 = acc[mt][nt][half*2+0] + b0;
                float v1 = acc[mt][nt][half*2+1] + b1;
                if (O32) {
                    *(float2*)(O32 + (size_t)m_*DD + n_) = make_float2(v0, v1);
                } else if (Oh1) {
                    uint32_t h,l;
                    pack_hilo(v0 + add0[n_], v1 + add0[n_+1], h, l);
                    *(uint32_t*)(Oh0 + (size_t)m_*DD + n_) = h;
                    *(uint32_t*)(Ol0 + (size_t)m_*DD + n_) = l;
                    pack_hilo(v0 + add1[n_], v1 + add1[n_+1], h, l);
                    *(uint32_t*)(Oh1 + (size_t)m_*DD + n_) = h;
                    *(uint32_t*)(Ol1 + (size_t)m_*DD + n_) = l;
                } else {
                    uint32_t h,l;
                    pack_hilo(v0, v1, h, l);
                    *(uint32_t*)(Oh0 + (size_t)m_*DD + n_) = h;
                    *(uint32_t*)(Ol0 + (size_t)m_*DD + n_) = l;
                }
            }
        }
}

// ================= fused attention: scores(AC+BD) + online softmax + P@V =================
// grid (8 q-tiles, 32 bh), 256 threads = 8 warps x 16 q-rows each.
__global__ __launch_bounds__(256) void attn_fused(
    const bf16* __restrict__ quh, const bf16* __restrict__ qul,
    const bf16* __restrict__ qvh, const bf16* __restrict__ qvl,
    const bf16* __restrict__ kh,  const bf16* __restrict__ kl,
    const bf16* __restrict__ vh,  const bf16* __restrict__ vl,
    const bf16* __restrict__ pph, const bf16* __restrict__ ppl,
    const unsigned char* __restrict__ mask,
    bf16* __restrict__ th, bf16* __restrict__ tl)
{
    extern __shared__ char sm[];
    const int tid = threadIdx.x, lane = tid & 31, wid = tid >> 5;
    const int bh = blockIdx.y, b = bh >> 3, h = bh & 7;
    const int qc = blockIdx.x * 128;
    const uint32_t sb = smem_u32(sm);
    const uint32_t opH = sb + 65536, opL = sb + 81920;
    float* bd = (float*)(sm + 98304);     // [128][132] fp32
    const int wq = wid * 16;
    const int r = lane>>2, c = (lane&3)*2;

    // resident Q tiles: Quh, Qul, Qvh, Qvl (16KB each)
    for (int u = tid; u < 1024; u += 256) {
        int row = u>>3, cb = u&7;
        uint32_t off = swz((uint32_t)(row*128 + cb*16));
        size_t g = (size_t)(b*SS_ + qc + row)*DD + h*DKK + cb*8;
        *(uint4*)(sm + off)         = *(const uint4*)(quh + g);
        *(uint4*)(sm + 16384 + off) = *(const uint4*)(qul + g);
        *(uint4*)(sm + 32768 + off) = *(const uint4*)(qvh + g);
        *(uint4*)(sm + 49152 + off) = *(const uint4*)(qvl + g);
    }

    // rel_shift wrap value: bd(0,1023) = qv[b,h,1]·p[0]  (only block qc==0 needs it)
    float wrapv = 0.f;
    if (qc == 0 && wid == 0) {
        #pragma unroll
        for (int d = 0; d < DKK; ++d) {
            float qq = __bfloat162float(qvh[(size_t)(b*SS_+1)*DD + h*DKK + d])
                     + __bfloat162float(qvl[(size_t)(b*SS_+1)*DD + h*DKK + d]);
            float pp = __bfloat162float(pph[h*DKK + d]) + __bfloat162float(ppl[h*DKK + d]);
            wrapv += qq * pp;
        }
    }

    float m0 = -1e30f, m1 = -1e30f, l0 = 0.f, l1 = 0.f;
    float accO[8][4];
    #pragma unroll
    for (int i=0;i<8;++i)
        #pragma unroll
        for (int j=0;j<4;++j) accO[i][j]=0.f;

    for (int ch = 0; ch < 8; ++ch) {
        const int kk0 = ch * 128;
        const int pbase = 1024 + kk0 - qc - 127;

        // ---- BD banded GEMM: per-warp t-window of 9 n16 groups ----
        float bdacc[9][2][4];
        #pragma unroll
        for (int gi=0;gi<9;++gi)
            #pragma unroll
            for (int q2=0;q2<2;++q2)
                #pragma unroll
                for (int e=0;e<4;++e) bdacc[gi][q2][e]=0.f;

        #pragma unroll
        for (int pass = 0; pass < 2; ++pass) {
            __syncthreads();
            for (int u = tid; u < 1024; u += 256) {
                int row = u>>3, cb = u&7;
                uint32_t off = swz((uint32_t)(row*128 + cb*16));
                size_t g = (size_t)(pbase + pass*128 + row)*DD + h*DKK + cb*8;
                *(uint4*)(sm + 65536 + off) = *(const uint4*)(pph + g);
                *(uint4*)(sm + 81920 + off) = *(const uint4*)(ppl + g);
            }
            __syncthreads();
            #pragma unroll
            for (int ks = 0; ks < 4; ++ks) {
                int k0 = ks*16;
                uint32_t aH[4], aL[4];
                ldsm4(aH, a_addr(sb + 32768, wq, k0, lane));
                ldsm4(aL, a_addr(sb + 49152, wq, k0, lane));
                #pragma unroll
                for (int gi = 0; gi < 9; ++gi) {
                    int g16 = 7 - wid + gi;
                    bool ip = pass ? (g16 >= 8) : (g16 <= 7);
                    if (ip) {
                        int n0 = g16*16 - pass*128;
                        uint32_t bH[4], bL[4];
                        ldsm4(bH, b_addr(opH, n0, k0, lane));
                        ldsm4(bL, b_addr(opL, n0, k0, lane));
                        mma16816(bdacc[gi][0], aH, &bH[0]);
                        mma16816(bdacc[gi][0], aH, &bL[0]);
                        mma16816(bdacc[gi][0], aL, &bH[0]);
                        mma16816(bdacc[gi][1], aH, &bH[2]);
                        mma16816(bdacc[gi][1], aH, &bL[2]);
                        mma16816(bdacc[gi][1], aL, &bH[2]);
                    }
                }
            }
            // scatter this pass's groups: bd[i][j], j = t + i - 127
            #pragma unroll
            for (int gi = 0; gi < 9; ++gi) {
                int g16 = 7 - wid + gi;
                bool ip = pass ? (g16 >= 8) : (g16 <= 7);
                if (ip) {
                    #pragma unroll
                    for (int q2 = 0; q2 < 2; ++q2) {
                        int t0 = g16*16 + q2*8 + c;
                        int i0 = wq + r, i1 = i0 + 8;
                        int j;
                        j = t0     + i0 - 127; if (j>=0 && j<128) bd[i0*132+j] = bdacc[gi][q2][0];
                        j = t0 + 1 + i0 - 127; if (j>=0 && j<128) bd[i0*132+j] = bdacc[gi][q2][1];
                        j = t0     + i1 - 127; if (j>=0 && j<128) bd[i1*132+j] = bdacc[gi][q2][2];
                        j = t0 + 1 + i1 - 127; if (j>=0 && j<128) bd[i1*132+j] = bdacc[gi][q2][3];
                    }
                }
            }
        }

        // ---- AC GEMM: Qu @ K^T over this k-chunk ----
        __syncthreads();
        for (int u = tid; u < 1024; u += 256) {
            int row = u>>3, cb = u&7;
            uint32_t off = swz((uint32_t)(row*128 + cb*16));
            size_t g = (size_t)(b*SS_ + kk0 + row)*DD + h*DKK + cb*8;
            *(uint4*)(sm + 65536 + off) = *(const uint4*)(kh + g);
            *(uint4*)(sm + 81920 + off) = *(const uint4*)(kl + g);
        }
        __syncthreads();
        float s[16][4];
        #pragma unroll
        for (int nt=0;nt<16;++nt)
            #pragma unroll
            for (int e=0;e<4;++e) s[nt][e]=0.f;
        #pragma unroll
        for (int ks = 0; ks < 4; ++ks) {
            int k0 = ks*16;
            uint32_t aH[4], aL[4];
            ldsm4(aH, a_addr(sb,         wq, k0, lane));
            ldsm4(aL, a_addr(sb + 16384, wq, k0, lane));
            #pragma unroll
            for (int g16 = 0; g16 < 8; ++g16) {
                uint32_t bH[4], bL[4];
                ldsm4(bH, b_addr(opH, g16*16, k0, lane));
                ldsm4(bL, b_addr(opL, g16*16, k0, lane));
                mma16816(s[2*g16],   aH, &bH[0]);
                mma16816(s[2*g16],   aH, &bL[0]);
                mma16816(s[2*g16],   aL, &bH[0]);
                mma16816(s[2*g16+1], aH, &bH[2]);
                mma16816(s[2*g16+1], aH, &bL[2]);
                mma16816(s[2*g16+1], aL, &bH[2]);
            }
        }
        __syncwarp();

        // ---- combine, scale, wrap, mask; online softmax ----
        const int i0 = wq + r, i1 = i0 + 8;
        float mc0 = -1e30f, mc1 = -1e30f;
        #pragma unroll
        for (int nt = 0; nt < 16; ++nt) {
            int jc = nt*8 + c;
            float v0 = s[nt][0] + bd[i0*132 + jc];
            float v1 = s[nt][1] + bd[i0*132 + jc + 1];
            float v2 = s[nt][2] + bd[i1*132 + jc];
            float v3 = s[nt][3] + bd[i1*132 + jc + 1];
            if (qc == 0 && ch == 7 && nt == 15 && wid == 0 && lane == 3) v1 += wrapv;
            v0 *= 0.125f; v1 *= 0.125f; v2 *= 0.125f; v3 *= 0.125f;
            const unsigned char* mr0 = mask + (size_t)b*SS_*SS_ + (size_t)(qc+i0)*SS_ + kk0 + jc;
            const unsigned char* mr1 = mask + (size_t)b*SS_*SS_ + (size_t)(qc+i1)*SS_ + kk0 + jc;
            uchar2 mq0 = *(const uchar2*)mr0;
            uchar2 mq1 = *(const uchar2*)mr1;
            if (mq0.x) v0 = -10000.f;
            if (mq0.y) v1 = -10000.f;
            if (mq1.x) v2 = -10000.f;
            if (mq1.y) v3 = -10000.f;
            s[nt][0]=v0; s[nt][1]=v1; s[nt][2]=v2; s[nt][3]=v3;
            mc0 = fmaxf(mc0, fmaxf(v0, v1));
            mc1 = fmaxf(mc1, fmaxf(v2, v3));
        }
        mc0 = fmaxf(mc0, __shfl_xor_sync(0xffffffffu, mc0, 1));
        mc0 = fmaxf(mc0, __shfl_xor_sync(0xffffffffu, mc0, 2));
        mc1 = fmaxf(mc1, __shfl_xor_sync(0xffffffffu, mc1, 1));
        mc1 = fmaxf(mc1, __shfl_xor_sync(0xffffffffu, mc1, 2));
        float mn0 = fmaxf(m0, mc0), mn1 = fmaxf(m1, mc1);
        float cor0 = __expf(m0 - mn0), cor1 = __expf(m1 - mn1);
        m0 = mn0; m1 = mn1;

        float ls0 = 0.f, ls1 = 0.f;
        uint32_t paH[8][4], paL[8][4];
        #pragma unroll
        for (int kt = 0; kt < 8; ++kt) {
            float p00 = __expf(s[2*kt][0]   - m0), p01 = __expf(s[2*kt][1]   - m0);
            float p02 = __expf(s[2*kt][2]   - m1), p03 = __expf(s[2*kt][3]   - m1);
            float p10 = __expf(s[2*kt+1][0] - m0), p11 = __expf(s[2*kt+1][1] - m0);
            float p12 = __expf(s[2*kt+1][2] - m1), p13 = __expf(s[2*kt+1][3] - m1);
            ls0 += p00 + p01 + p10 + p11;
            ls1 += p02 + p03 + p12 + p13;
            pack_hilo(p00, p01, paH[kt][0], paL[kt][0]);
            pack_hilo(p02, p03, paH[kt][1], paL[kt][1]);
            pack_hilo(p10, p11, paH[kt][2], paL[kt][2]);
            pack_hilo(p12, p13, paH[kt][3], paL[kt][3]);
        }
        ls0 += __shfl_xor_sync(0xffffffffu, ls0, 1);
        ls0 += __shfl_xor_sync(0xffffffffu, ls0, 2);
        ls1 += __shfl_xor_sync(0xffffffffu, ls1, 1);
        ls1 += __shfl_xor_sync(0xffffffffu, ls1, 2);
        l0 = l0*cor0 + ls0;
        l1 = l1*cor1 + ls1;
        #pragma unroll
        for (int dn = 0; dn < 8; ++dn) {
            accO[dn][0]*=cor0; accO[dn][1]*=cor0; accO[dn][2]*=cor1; accO[dn][3]*=cor1;
        }

        // ---- P @ V ----
        __syncthreads();
        for (int u = tid; u < 1024; u += 256) {
            int row = u>>3, cb = u&7;
            uint32_t off = swz((uint32_t)(row*128 + cb*16));
            size_t g = (size_t)(b*SS_ + kk0 + row)*DD + h*DKK + cb*8;
            *(uint4*)(sm + 65536 + off) = *(const uint4*)(vh + g);
            *(uint4*)(sm + 81920 + off) = *(const uint4*)(vl + g);
        }
        __syncthreads();
        #pragma unroll
        for (int kt = 0; kt < 8; ++kt) {
            #pragma unroll
            for (int dp = 0; dp < 4; ++dp) {
                uint32_t bH[4], bL[4];
                ldsm4t(bH, v_addr(opH, kt*16, dp*16, lane));
                ldsm4t(bL, v_addr(opL, kt*16, dp*16, lane));
                mma16816(accO[2*dp],   paH[kt], &bH[0]);
                mma16816(accO[2*dp],   paH[kt], &bL[0]);
                mma16816(accO[2*dp],   paL[kt], &bH[0]);
                mma16816(accO[2*dp+1], paH[kt], &bH[2]);
                mma16816(accO[2*dp+1], paH[kt], &bL[2]);
                mma16816(accO[2*dp+1], paL[kt], &bH[2]);
            }
        }
    }

    // ---- finalize: O /= l, write hi/lo bf16 ----
    float inv0 = 1.f / l0, inv1 = 1.f / l1;
    const int q0 = qc + wq + r, q1 = q0 + 8;
    #pragma unroll
    for (int dn = 0; dn < 8; ++dn) {
        int d = dn*8 + c;
        uint32_t hh, ll;
        pack_hilo(accO[dn][0]*inv0, accO[dn][1]*inv0, hh, ll);
        *(uint32_t*)(th + (size_t)(b*SS_+q0)*DD + h*DKK + d) = hh;
        *(uint32_t*)(tl + (size_t)(b*SS_+q0)*DD + h*DKK + d) = ll;
        pack_hilo(accO[dn][2]*inv1, accO[dn][3]*inv1, hh, ll);
        *(uint32_t*)(th + (size_t)(b*SS_+q1)*DD + h*DKK + d) = hh;
        *(uint32_t*)(tl + (size_t)(b*SS_+q1)*DD + h*DKK + d) = ll;
    }
}

// ---------------- launch ----------------
extern "C" void kernel_launch(void* const* d_in, const int* in_sizes, int n_in,
                              void* d_out, int out_size) {
    const float* inputs        = (const float*)d_in[0];
    const unsigned char* amask = (const unsigned char*)d_in[1];
    const float* Wq = (const float*)d_in[2];
    const float* bq = (const float*)d_in[3];
    const float* Wk = (const float*)d_in[4];
    const float* bk = (const float*)d_in[5];
    const float* Wv = (const float*)d_in[6];
    const float* bv = (const float*)d_in[7];
    const float* Wo = (const float*)d_in[8];
    const float* bo = (const float*)d_in[9];
    const float* Wp = (const float*)d_in[10];
    const float* pu = (const float*)d_in[11];
    const float* pv = (const float*)d_in[12];
    const float* gamma = (const float*)d_in[13];
    const float* beta  = (const float*)d_in[14];
    float* out = (float*)d_out;

    float *xn, *pe;
    bf16 *xh,*xl,*peh,*pel,*wh,*wl,*quh,*qul,*qvh,*qvl,*kh,*kl,*vh,*vl,*php,*ppl,*th,*tl;
    cudaGetSymbolAddress((void**)&xn, g_xn);
    cudaGetSymbolAddress((void**)&pe, g_pe);
    cudaGetSymbolAddress((void**)&xh, g_xh);   cudaGetSymbolAddress((void**)&xl, g_xl);
    cudaGetSymbolAddress((void**)&peh, g_peh); cudaGetSymbolAddress((void**)&pel, g_pel);
    cudaGetSymbolAddress((void**)&wh, g_wh);   cudaGetSymbolAddress((void**)&wl, g_wl);
    cudaGetSymbolAddress((void**)&quh, g_quh); cudaGetSymbolAddress((void**)&qul, g_qul);
    cudaGetSymbolAddress((void**)&qvh, g_qvh); cudaGetSymbolAddress((void**)&qvl, g_qvl);
    cudaGetSymbolAddress((void**)&kh, g_kh);   cudaGetSymbolAddress((void**)&kl, g_kl);
    cudaGetSymbolAddress((void**)&vh, g_vh);   cudaGetSymbolAddress((void**)&vl, g_vl);
    cudaGetSymbolAddress((void**)&php, g_php); cudaGetSymbolAddress((void**)&ppl, g_ppl);
    cudaGetSymbolAddress((void**)&th, g_th);   cudaGetSymbolAddress((void**)&tl, g_tl);

    cudaFuncSetAttribute(gemm_mma,   cudaFuncAttributeMaxDynamicSharedMemorySize, 65536);
    cudaFuncSetAttribute(attn_fused, cudaFuncAttributeMaxDynamicSharedMemorySize, 165888);

    ln_kernel<<<BB*SS_, 128>>>(inputs, gamma, beta, xn);
    pe_kernel<<<PPAD, 256>>>(pe);

    cvt_kernel<<<2048, 256>>>(xn, xh, xl, BB*SS_*DD/4);
    cvt_kernel<<<1024, 256>>>(pe, peh, pel, PPAD*DD/4);
    cvt_kernel<<<256, 256>>>(Wq, wh + 0*DD*DD, wl + 0*DD*DD, DD*DD/4);
    cvt_kernel<<<256, 256>>>(Wk, wh + 1*DD*DD, wl + 1*DD*DD, DD*DD/4);
    cvt_kernel<<<256, 256>>>(Wv, wh + 2*DD*DD, wl + 2*DD*DD, DD*DD/4);
    cvt_kernel<<<256, 256>>>(Wo, wh + 3*DD*DD, wl + 3*DD*DD, DD*DD/4);
    cvt_kernel<<<256, 256>>>(Wp, wh + 4*DD*DD, wl + 4*DD*DD, DD*DD/4);

    // projections (warp-MMA, split-bf16)
    gemm_mma<<<dim3(4,32), 256, 65536>>>(xh, xl, wh+0*DD*DD, wl+0*DD*DD, bq, pu, pv,
                                          quh, qul, qvh, qvl, nullptr);
    gemm_mma<<<dim3(4,32), 256, 65536>>>(xh, xl, wh+1*DD*DD, wl+1*DD*DD, bk, nullptr, nullptr,
                                          kh, kl, nullptr, nullptr, nullptr);
    gemm_mma<<<dim3(4,32), 256, 65536>>>(xh, xl, wh+2*DD*DD, wl+2*DD*DD, bv, nullptr, nullptr,
                                          vh, vl, nullptr, nullptr, nullptr);
    gemm_mma<<<dim3(4,16), 256, 65536>>>(peh, pel, wh+4*DD*DD, wl+4*DD*DD, nullptr, nullptr, nullptr,
                                          php, ppl, nullptr, nullptr, nullptr);

    // fused attention (scores + softmax + attn@V)
    attn_fused<<<dim3(8, BB*HH), 256, 165888>>>(quh, qul, qvh, qvl, kh, kl, vh, vl,
                                                 php, ppl, amask, th, tl);

    // output projection
    gemm_mma<<<dim3(4,32), 256, 65536>>>(th, tl, wh+3*DD*DD, wl+3*DD*DD, bo, nullptr, nullptr,
                                          nullptr, nullptr, nullptr, nullptr, out);

    (void)in_sizes; (void)n_in; (void)out_size;
}

// round 6
// speedup vs baseline: 3.6985x; 1.2987x over previous
#include <cuda_runtime.h>
#include <cuda_bf16.h>
#include <math.h>
#include <stdint.h>

#define BB 4
#define SS_ 1024
#define DD 512
#define HH 8
#define DKK 64
#define PP_ 2047
#define PPAD 2048
#define PBAND 2304

typedef __nv_bfloat16 bf16;

// ---------------- scratch ----------------
__device__ bf16 g_xh[BB*SS_*DD], g_xl[BB*SS_*DD];
__device__ bf16 g_peh[PPAD*DD],  g_pel[PPAD*DD];
__device__ bf16 g_wh[5*DD*DD],   g_wl[5*DD*DD];
__device__ bf16 g_quh[BB*SS_*DD], g_qul[BB*SS_*DD];
__device__ bf16 g_qvh[BB*SS_*DD], g_qvl[BB*SS_*DD];
__device__ bf16 g_kh [BB*SS_*DD], g_kl [BB*SS_*DD];
__device__ bf16 g_vh [BB*SS_*DD], g_vl [BB*SS_*DD];
__device__ bf16 g_php[(size_t)PBAND*DD], g_ppl[(size_t)PBAND*DD];
__device__ bf16 g_th[BB*SS_*DD], g_tl[BB*SS_*DD];

// ---------------- helpers ----------------
__device__ __forceinline__ void mma16816(float* d, const uint32_t* a, const uint32_t* b){
    asm volatile("mma.sync.aligned.m16n8k16.row.col.f32.bf16.bf16.f32 "
        "{%0,%1,%2,%3}, {%4,%5,%6,%7}, {%8,%9}, {%0,%1,%2,%3};"
        : "+f"(d[0]),"+f"(d[1]),"+f"(d[2]),"+f"(d[3])
        : "r"(a[0]),"r"(a[1]),"r"(a[2]),"r"(a[3]), "r"(b[0]),"r"(b[1]));
}
__device__ __forceinline__ void ldsm4(uint32_t* r, uint32_t addr){
    asm volatile("ldmatrix.sync.aligned.m8n8.x4.shared.b16 {%0,%1,%2,%3}, [%4];"
        :"=r"(r[0]),"=r"(r[1]),"=r"(r[2]),"=r"(r[3]):"r"(addr));
}
__device__ __forceinline__ void ldsm4t(uint32_t* r, uint32_t addr){
    asm volatile("ldmatrix.sync.aligned.m8n8.x4.trans.shared.b16 {%0,%1,%2,%3}, [%4];"
        :"=r"(r[0]),"=r"(r[1]),"=r"(r[2]),"=r"(r[3]):"r"(addr));
}
__device__ __forceinline__ uint32_t smem_u32(const void* p){
    uint32_t a; asm("{ .reg .u64 t; cvta.to.shared.u64 t, %1; cvt.u32.u64 %0, t; }":"=r"(a):"l"(p)); return a;
}
__device__ __forceinline__ void cp16(uint32_t dst, const void* src){
    asm volatile("cp.async.cg.shared.global [%0], [%1], 16;"
        :: "r"(dst), "l"(__cvta_generic_to_global(src)));
}
#define CP_COMMIT() asm volatile("cp.async.commit_group;" ::: "memory")
#define CP_WAIT1()  asm volatile("cp.async.wait_group 1;" ::: "memory")
static __device__ __forceinline__ uint32_t swz(uint32_t o){ return o ^ ((o>>3)&0x70); }
__device__ __forceinline__ uint32_t a_addr(uint32_t base, int m16, int k0, int lane){
    int g = lane>>3, r = lane&7;
    int row = m16 + r + (g&1)*8;
    uint32_t o = (uint32_t)(row*128 + (k0 + (g>>1)*8)*2);
    return base + swz(o);
}
__device__ __forceinline__ uint32_t b_addr(uint32_t base, int n0, int k0, int lane){
    int g = lane>>3, r = lane&7;
    int row = n0 + r + (g>>1)*8;
    uint32_t o = (uint32_t)(row*128 + (k0 + (g&1)*8)*2);
    return base + swz(o);
}
__device__ __forceinline__ uint32_t v_addr(uint32_t base, int k0, int d0, int lane){
    int g = lane>>3, r = lane&7;
    int row = k0 + r + (g&1)*8;
    uint32_t o = (uint32_t)(row*128 + (d0 + (g>>1)*8)*2);
    return base + swz(o);
}
__device__ __forceinline__ void pack_hilo(float x, float y, uint32_t& hi, uint32_t& lo){
    bf16 hx = __float2bfloat16(x), hy = __float2bfloat16(y);
    float rx = x - __bfloat162float(hx), ry = y - __bfloat162float(hy);
    bf16 lx = __float2bfloat16(rx), ly = __float2bfloat16(ry);
    hi = ((uint32_t)__bfloat16_as_ushort(hy)<<16) | __bfloat16_as_ushort(hx);
    lo = ((uint32_t)__bfloat16_as_ushort(ly)<<16) | __bfloat16_as_ushort(lx);
}

// ---------------- LayerNorm -> hi/lo bf16 planes ----------------
__global__ void ln_kernel(const float* __restrict__ x, const float* __restrict__ gamma,
                          const float* __restrict__ beta,
                          bf16* __restrict__ xh, bf16* __restrict__ xl) {
    __shared__ float red[4];
    int row = blockIdx.x; int t = threadIdx.x;
    float4 v = ((const float4*)(x + (size_t)row * DD))[t];
    float s = v.x+v.y+v.z+v.w;
    #pragma unroll
    for (int o=16;o;o>>=1) s += __shfl_xor_sync(0xffffffffu,s,o);
    if ((t&31)==0) red[t>>5]=s;
    __syncthreads();
    float mu=(red[0]+red[1]+red[2]+red[3])*(1.0f/DD);
    float dx=v.x-mu,dy=v.y-mu,dz=v.z-mu,dw=v.w-mu;
    float ss=dx*dx+dy*dy+dz*dz+dw*dw;
    #pragma unroll
    for (int o=16;o;o>>=1) ss += __shfl_xor_sync(0xffffffffu,ss,o);
    __syncthreads();
    if ((t&31)==0) red[t>>5]=ss;
    __syncthreads();
    float rstd=rsqrtf((red[0]+red[1]+red[2]+red[3])*(1.0f/DD)+1e-5f);
    float4 g=((const float4*)gamma)[t], be=((const float4*)beta)[t];
    float o0=dx*rstd*g.x+be.x, o1=dy*rstd*g.y+be.y, o2=dz*rstd*g.z+be.z, o3=dw*rstd*g.w+be.w;
    uint32_t h0,l0,h1,l1;
    pack_hilo(o0,o1,h0,l0); pack_hilo(o2,o3,h1,l1);
    *(uint2*)(xh + (size_t)row*DD + 4*t) = make_uint2(h0,h1);
    *(uint2*)(xl + (size_t)row*DD + 4*t) = make_uint2(l0,l1);
}

// ---------------- positional embedding -> hi/lo (row >= PP_ zero) ----------------
__global__ void pe_kernel(bf16* __restrict__ peh, bf16* __restrict__ pel) {
    int j = blockIdx.x; int t = threadIdx.x;
    uint32_t h = 0, l = 0;
    if (j < PP_) {
        float pos = (float)(j - (SS_ - 1));
        const float kconst = -0.01798894603901598415f;
        float div = expf((float)(2*t) * kconst);
        float sa, ca; sincosf(pos * div, &sa, &ca);
        pack_hilo(sa, ca, h, l);
    }
    *(uint32_t*)(peh + (size_t)j*DD + 2*t) = h;
    *(uint32_t*)(pel + (size_t)j*DD + 2*t) = l;
}

// ---------------- fp32 -> hi/lo (weights only) ----------------
__global__ void cvt_kernel(const float* __restrict__ src, bf16* __restrict__ hi,
                           bf16* __restrict__ lo, int n4){
    int i = blockIdx.x * 256 + threadIdx.x;
    if (i >= n4) return;
    float4 v = ((const float4*)src)[i];
    uint32_t h0,l0,h1,l1;
    pack_hilo(v.x, v.y, h0, l0);
    pack_hilo(v.z, v.w, h1, l1);
    ((uint2*)hi)[i] = make_uint2(h0,h1);
    ((uint2*)lo)[i] = make_uint2(l0,l1);
}

// ================= generic MMA GEMM, cp.async double-buffered =================
__global__ __launch_bounds__(256) void gemm_mma(
    const bf16* __restrict__ Ah, const bf16* __restrict__ Al,
    const bf16* __restrict__ Bh, const bf16* __restrict__ Bl,
    const float* __restrict__ bias, const float* __restrict__ add0, const float* __restrict__ add1,
    bf16* __restrict__ Oh0, bf16* __restrict__ Ol0,
    bf16* __restrict__ Oh1, bf16* __restrict__ Ol1, float* __restrict__ O32)
{
    extern __shared__ char sm[];
    const int tid = threadIdx.x, lane = tid & 31, wid = tid >> 5;
    const int bm = blockIdx.y * 128, bn = blockIdx.x * 128;
    const uint32_t sb = smem_u32(sm);
    const int m0w = (wid>>2)*64, n0w = (wid&3)*32;

    auto issueg = [&](int kc){
        uint32_t base = sb + (uint32_t)(kc&1)*65536;
        for (int u = tid; u < 1024; u += 256) {
            int row = u>>3, cb = u&7;
            uint32_t off = swz((uint32_t)(row*128 + cb*16));
            size_t gA = (size_t)(bm+row)*DD + kc*64 + cb*8;
            size_t gB = (size_t)(bn+row)*DD + kc*64 + cb*8;
            cp16(base + off,         Ah + gA);
            cp16(base + 16384 + off, Al + gA);
            cp16(base + 32768 + off, Bh + gB);
            cp16(base + 49152 + off, Bl + gB);
        }
    };

    float acc[4][4][4];
    #pragma unroll
    for (int a=0;a<4;++a)
        #pragma unroll
        for (int b=0;b<4;++b)
            #pragma unroll
            for (int c=0;c<4;++c) acc[a][b][c]=0.f;

    issueg(0); CP_COMMIT();
    issueg(1); CP_COMMIT();

    for (int kc = 0; kc < 8; ++kc) {
        CP_WAIT1();
        __syncthreads();
        uint32_t base = sb + (uint32_t)(kc&1)*65536;
        #pragma unroll
        for (int ks = 0; ks < 4; ++ks) {
            int k0 = ks*16;
            uint32_t aH[4][4], aL[4][4], bH[2][4], bL[2][4];
            #pragma unroll
            for (int mt=0; mt<4; ++mt) {
                ldsm4(aH[mt], a_addr(base,        m0w+mt*16, k0, lane));
                ldsm4(aL[mt], a_addr(base+16384,  m0w+mt*16, k0, lane));
            }
            #pragma unroll
            for (int p=0; p<2; ++p) {
                ldsm4(bH[p], b_addr(base+32768, n0w+p*16, k0, lane));
                ldsm4(bL[p], b_addr(base+49152, n0w+p*16, k0, lane));
            }
            #pragma unroll
            for (int mt=0; mt<4; ++mt)
                #pragma unroll
                for (int nt=0; nt<4; ++nt) {
                    const uint32_t* bh_ = &bH[nt>>1][(nt&1)*2];
                    const uint32_t* bl_ = &bL[nt>>1][(nt&1)*2];
                    mma16816(acc[mt][nt], aH[mt], bh_);
                    mma16816(acc[mt][nt], aH[mt], bl_);
                    mma16816(acc[mt][nt], aL[mt], bh_);
                }
        }
        __syncthreads();
        if (kc + 2 < 8) issueg(kc + 2);
        CP_COMMIT();
    }
    const int r = lane>>2, c = (lane&3)*2;
    #pragma unroll
    for (int mt=0; mt<4; ++mt)
        #pragma unroll
        for (int nt=0; nt<4; ++nt) {
            int n_ = bn + n0w + nt*8 + c;
            float b0 = bias ? bias[n_] : 0.f, b1 = bias ? bias[n_+1] : 0.f;
            #pragma unroll
            for (int half=0; half<2; ++half) {
                int m_ = bm + m0w + mt*16 + r + half*8;
                float v0 = acc[mt][nt][half*2+0] + b0;
                float v1 = acc[mt][nt][half*2+1] + b1;
                if (O32) {
                    *(float2*)(O32 + (size_t)m_*DD + n_) = make_float2(v0, v1);
                } else if (Oh1) {
                    uint32_t h,l;
                    pack_hilo(v0 + add0[n_], v1 + add0[n_+1], h, l);
                    *(uint32_t*)(Oh0 + (size_t)m_*DD + n_) = h;
                    *(uint32_t*)(Ol0 + (size_t)m_*DD + n_) = l;
                    pack_hilo(v0 + add1[n_], v1 + add1[n_+1], h, l);
                    *(uint32_t*)(Oh1 + (size_t)m_*DD + n_) = h;
                    *(uint32_t*)(Ol1 + (size_t)m_*DD + n_) = l;
                } else {
                    uint32_t h,l;
                    pack_hilo(v0, v1, h, l);
                    *(uint32_t*)(Oh0 + (size_t)m_*DD + n_) = h;
                    *(uint32_t*)(Ol0 + (size_t)m_*DD + n_) = l;
                }
            }
        }
}

// ================= fused attention, 32-stage cp.async pipeline =================
// stages: chunk ch in 0..7, types {0:P-pass0, 1:P-pass1, 2:K, 3:V}; buffer = stage&1
__global__ __launch_bounds__(256) void attn_fused(
    const bf16* __restrict__ quh, const bf16* __restrict__ qul,
    const bf16* __restrict__ qvh, const bf16* __restrict__ qvl,
    const bf16* __restrict__ kh,  const bf16* __restrict__ kl,
    const bf16* __restrict__ vh,  const bf16* __restrict__ vl,
    const bf16* __restrict__ pph, const bf16* __restrict__ ppl,
    const unsigned char* __restrict__ mask,
    bf16* __restrict__ th, bf16* __restrict__ tl)
{
    extern __shared__ char sm[];
    const int tid = threadIdx.x, lane = tid & 31, wid = tid >> 5;
    const int bh = blockIdx.y, b = bh >> 3, h = bh & 7;
    const int qc = blockIdx.x * 128;
    const uint32_t sb = smem_u32(sm);
    float* bd = (float*)(sm + 131072);     // [128][132] fp32, warp-private rows
    const int wq = wid * 16;
    const int r = lane>>2, c = (lane&3)*2;

    auto issue = [&](int st){
        int type = st & 3, ch = st >> 2;
        const bf16 *sh_, *sl_;
        size_t rowbase;
        if (type < 2) { sh_ = pph; sl_ = ppl;
            rowbase = (size_t)(1024 + 128*ch - qc - 127 + type*128); }
        else if (type == 2) { sh_ = kh; sl_ = kl; rowbase = (size_t)(b*SS_ + 128*ch); }
        else { sh_ = vh; sl_ = vl; rowbase = (size_t)(b*SS_ + 128*ch); }
        uint32_t bufH = sb + 65536 + (uint32_t)(st&1)*32768;
        for (int u = tid; u < 1024; u += 256){
            int row = u>>3, cb = u&7;
            uint32_t off = swz((uint32_t)(row*128 + cb*16));
            size_t g = (rowbase + row)*DD + h*DKK + cb*8;
            cp16(bufH + off,         sh_ + g);
            cp16(bufH + 16384 + off, sl_ + g);
        }
    };

    // group 0: resident Q tiles + stage 0
    for (int u = tid; u < 1024; u += 256) {
        int row = u>>3, cb = u&7;
        uint32_t off = swz((uint32_t)(row*128 + cb*16));
        size_t g = (size_t)(b*SS_ + qc + row)*DD + h*DKK + cb*8;
        cp16(sb + off,         quh + g);
        cp16(sb + 16384 + off, qul + g);
        cp16(sb + 32768 + off, qvh + g);
        cp16(sb + 49152 + off, qvl + g);
    }
    issue(0); CP_COMMIT();
    issue(1); CP_COMMIT();

    // rel_shift wrap value (independent of smem)
    float wrapv = 0.f;
    if (qc == 0 && wid == 0) {
        #pragma unroll
        for (int d = 0; d < DKK; ++d) {
            float qq = __bfloat162float(qvh[(size_t)(b*SS_+1)*DD + h*DKK + d])
                     + __bfloat162float(qvl[(size_t)(b*SS_+1)*DD + h*DKK + d]);
            float pp = __bfloat162float(pph[h*DKK + d]) + __bfloat162float(ppl[h*DKK + d]);
            wrapv += qq * pp;
        }
    }

    float m0 = -1e30f, m1 = -1e30f, l0 = 0.f, l1 = 0.f;
    float accO[8][4];
    #pragma unroll
    for (int i=0;i<8;++i)
        #pragma unroll
        for (int j=0;j<4;++j) accO[i][j]=0.f;

    float bdacc[9][2][4];
    uint32_t paH[8][4], paL[8][4];

    for (int st = 0; st < 32; ++st) {
        CP_WAIT1();
        __syncthreads();
        const int type = st & 3, ch = st >> 2;
        const uint32_t opH = sb + 65536 + (uint32_t)(st&1)*32768;
        const uint32_t opL = opH + 16384;

        if (type == 0) {
            #pragma unroll
            for (int gi=0;gi<9;++gi)
                #pragma unroll
                for (int q2=0;q2<2;++q2)
                    #pragma unroll
                    for (int e=0;e<4;++e) bdacc[gi][q2][e]=0.f;
            #pragma unroll
            for (int ks = 0; ks < 4; ++ks) {
                int k0 = ks*16;
                uint32_t aH[4], aL[4];
                ldsm4(aH, a_addr(sb + 32768, wq, k0, lane));
                ldsm4(aL, a_addr(sb + 49152, wq, k0, lane));
                #pragma unroll
                for (int gi = 0; gi < 9; ++gi) {
                    int g16 = 7 - wid + gi;
                    if (g16 <= 7) {
                        int n0 = g16*16;
                        uint32_t bH[4], bL[4];
                        ldsm4(bH, b_addr(opH, n0, k0, lane));
                        ldsm4(bL, b_addr(opL, n0, k0, lane));
                        mma16816(bdacc[gi][0], aH, &bH[0]);
                        mma16816(bdacc[gi][0], aH, &bL[0]);
                        mma16816(bdacc[gi][0], aL, &bH[0]);
                        mma16816(bdacc[gi][1], aH, &bH[2]);
                        mma16816(bdacc[gi][1], aH, &bL[2]);
                        mma16816(bdacc[gi][1], aL, &bH[2]);
                    }
                }
            }
        } else if (type == 1) {
            #pragma unroll
            for (int ks = 0; ks < 4; ++ks) {
                int k0 = ks*16;
                uint32_t aH[4], aL[4];
                ldsm4(aH, a_addr(sb + 32768, wq, k0, lane));
                ldsm4(aL, a_addr(sb + 49152, wq, k0, lane));
                #pragma unroll
                for (int gi = 0; gi < 9; ++gi) {
                    int g16 = 7 - wid + gi;
                    if (g16 >= 8) {
                        int n0 = g16*16 - 128;
                        uint32_t bH[4], bL[4];
                        ldsm4(bH, b_addr(opH, n0, k0, lane));
                        ldsm4(bL, b_addr(opL, n0, k0, lane));
                        mma16816(bdacc[gi][0], aH, &bH[0]);
                        mma16816(bdacc[gi][0], aH, &bL[0]);
                        mma16816(bdacc[gi][0], aL, &bH[0]);
                        mma16816(bdacc[gi][1], aH, &bH[2]);
                        mma16816(bdacc[gi][1], aH, &bL[2]);
                        mma16816(bdacc[gi][1], aL, &bH[2]);
                    }
                }
            }
            // scatter: bd[i][j], j = t + i - 127   (warp-private rows)
            #pragma unroll
            for (int gi = 0; gi < 9; ++gi) {
                int g16 = 7 - wid + gi;
                #pragma unroll
                for (int q2 = 0; q2 < 2; ++q2) {
                    int t0 = g16*16 + q2*8 + c;
                    int i0 = wq + r, i1 = i0 + 8;
                    int j;
                    j = t0     + i0 - 127; if (j>=0 && j<128) bd[i0*132+j] = bdacc[gi][q2][0];
                    j = t0 + 1 + i0 - 127; if (j>=0 && j<128) bd[i0*132+j] = bdacc[gi][q2][1];
                    j = t0     + i1 - 127; if (j>=0 && j<128) bd[i1*132+j] = bdacc[gi][q2][2];
                    j = t0 + 1 + i1 - 127; if (j>=0 && j<128) bd[i1*132+j] = bdacc[gi][q2][3];
                }
            }
        } else if (type == 2) {
            const int kk0 = ch * 128;
            float s[16][4];
            #pragma unroll
            for (int nt=0;nt<16;++nt)
                #pragma unroll
                for (int e=0;e<4;++e) s[nt][e]=0.f;
            #pragma unroll
            for (int ks = 0; ks < 4; ++ks) {
                int k0 = ks*16;
                uint32_t aH[4], aL[4];
                ldsm4(aH, a_addr(sb,         wq, k0, lane));
                ldsm4(aL, a_addr(sb + 16384, wq, k0, lane));
                #pragma unroll
                for (int g16 = 0; g16 < 8; ++g16) {
                    uint32_t bH[4], bL[4];
                    ldsm4(bH, b_addr(opH, g16*16, k0, lane));
                    ldsm4(bL, b_addr(opL, g16*16, k0, lane));
                    mma16816(s[2*g16],   aH, &bH[0]);
                    mma16816(s[2*g16],   aH, &bL[0]);
                    mma16816(s[2*g16],   aL, &bH[0]);
                    mma16816(s[2*g16+1], aH, &bH[2]);
                    mma16816(s[2*g16+1], aH, &bL[2]);
                    mma16816(s[2*g16+1], aL, &bH[2]);
                }
            }
            const int i0 = wq + r, i1 = i0 + 8;
            float mc0 = -1e30f, mc1 = -1e30f;
            #pragma unroll
            for (int nt = 0; nt < 16; ++nt) {
                int jc = nt*8 + c;
                float v0 = s[nt][0] + bd[i0*132 + jc];
                float v1 = s[nt][1] + bd[i0*132 + jc + 1];
                float v2 = s[nt][2] + bd[i1*132 + jc];
                float v3 = s[nt][3] + bd[i1*132 + jc + 1];
                if (qc == 0 && ch == 7 && nt == 15 && wid == 0 && lane == 3) v1 += wrapv;
                v0 *= 0.125f; v1 *= 0.125f; v2 *= 0.125f; v3 *= 0.125f;
                const unsigned char* mr0 = mask + (size_t)b*SS_*SS_ + (size_t)(qc+i0)*SS_ + kk0 + jc;
                const unsigned char* mr1 = mask + (size_t)b*SS_*SS_ + (size_t)(qc+i1)*SS_ + kk0 + jc;
                uchar2 mq0 = *(const uchar2*)mr0;
                uchar2 mq1 = *(const uchar2*)mr1;
                if (mq0.x) v0 = -10000.f;
                if (mq0.y) v1 = -10000.f;
                if (mq1.x) v2 = -10000.f;
                if (mq1.y) v3 = -10000.f;
                s[nt][0]=v0; s[nt][1]=v1; s[nt][2]=v2; s[nt][3]=v3;
                mc0 = fmaxf(mc0, fmaxf(v0, v1));
                mc1 = fmaxf(mc1, fmaxf(v2, v3));
            }
            mc0 = fmaxf(mc0, __shfl_xor_sync(0xffffffffu, mc0, 1));
            mc0 = fmaxf(mc0, __shfl_xor_sync(0xffffffffu, mc0, 2));
            mc1 = fmaxf(mc1, __shfl_xor_sync(0xffffffffu, mc1, 1));
            mc1 = fmaxf(mc1, __shfl_xor_sync(0xffffffffu, mc1, 2));
            float mn0 = fmaxf(m0, mc0), mn1 = fmaxf(m1, mc1);
            float cor0 = __expf(m0 - mn0), cor1 = __expf(m1 - mn1);
            m0 = mn0; m1 = mn1;
            float ls0 = 0.f, ls1 = 0.f;
            #pragma unroll
            for (int kt = 0; kt < 8; ++kt) {
                float p00 = __expf(s[2*kt][0]   - m0), p01 = __expf(s[2*kt][1]   - m0);
                float p02 = __expf(s[2*kt][2]   - m1), p03 = __expf(s[2*kt][3]   - m1);
                float p10 = __expf(s[2*kt+1][0] - m0), p11 = __expf(s[2*kt+1][1] - m0);
                float p12 = __expf(s[2*kt+1][2] - m1), p13 = __expf(s[2*kt+1][3] - m1);
                ls0 += p00 + p01 + p10 + p11;
                ls1 += p02 + p03 + p12 + p13;
                pack_hilo(p00, p01, paH[kt][0], paL[kt][0]);
                pack_hilo(p02, p03, paH[kt][1], paL[kt][1]);
                pack_hilo(p10, p11, paH[kt][2], paL[kt][2]);
                pack_hilo(p12, p13, paH[kt][3], paL[kt][3]);
            }
            ls0 += __shfl_xor_sync(0xffffffffu, ls0, 1);
            ls0 += __shfl_xor_sync(0xffffffffu, ls0, 2);
            ls1 += __shfl_xor_sync(0xffffffffu, ls1, 1);
            ls1 += __shfl_xor_sync(0xffffffffu, ls1, 2);
            l0 = l0*cor0 + ls0;
            l1 = l1*cor1 + ls1;
            #pragma unroll
            for (int dn = 0; dn < 8; ++dn) {
                accO[dn][0]*=cor0; accO[dn][1]*=cor0; accO[dn][2]*=cor1; accO[dn][3]*=cor1;
            }
        } else {
            #pragma unroll
            for (int kt = 0; kt < 8; ++kt) {
                #pragma unroll
                for (int dp = 0; dp < 4; ++dp) {
                    uint32_t bH[4], bL[4];
                    ldsm4t(bH, v_addr(opH, kt*16, dp*16, lane));
                    ldsm4t(bL, v_addr(opL, kt*16, dp*16, lane));
                    mma16816(accO[2*dp],   paH[kt], &bH[0]);
                    mma16816(accO[2*dp],   paH[kt], &bL[0]);
                    mma16816(accO[2*dp],   paL[kt], &bH[0]);
                    mma16816(accO[2*dp+1], paH[kt], &bH[2]);
                    mma16816(accO[2*dp+1], paH[kt], &bL[2]);
                    mma16816(accO[2*dp+1], paL[kt], &bH[2]);
                }
            }
        }

        __syncthreads();
        if (st + 2 < 32) issue(st + 2);
        CP_COMMIT();
    }

    float inv0 = 1.f / l0, inv1 = 1.f / l1;
    const int q0 = qc + wq + r, q1 = q0 + 8;
    #pragma unroll
    for (int dn = 0; dn < 8; ++dn) {
        int d = dn*8 + c;
        uint32_t hh, ll;
        pack_hilo(accO[dn][0]*inv0, accO[dn][1]*inv0, hh, ll);
        *(uint32_t*)(th + (size_t)(b*SS_+q0)*DD + h*DKK + d) = hh;
        *(uint32_t*)(tl + (size_t)(b*SS_+q0)*DD + h*DKK + d) = ll;
        pack_hilo(accO[dn][2]*inv1, accO[dn][3]*inv1, hh, ll);
        *(uint32_t*)(th + (size_t)(b*SS_+q1)*DD + h*DKK + d) = hh;
        *(uint32_t*)(tl + (size_t)(b*SS_+q1)*DD + h*DKK + d) = ll;
    }
}

// ---------------- launch ----------------
extern "C" void kernel_launch(void* const* d_in, const int* in_sizes, int n_in,
                              void* d_out, int out_size) {
    const float* inputs        = (const float*)d_in[0];
    const unsigned char* amask = (const unsigned char*)d_in[1];
    const float* Wq = (const float*)d_in[2];
    const float* bq = (const float*)d_in[3];
    const float* Wk = (const float*)d_in[4];
    const float* bk = (const float*)d_in[5];
    const float* Wv = (const float*)d_in[6];
    const float* bv = (const float*)d_in[7];
    const float* Wo = (const float*)d_in[8];
    const float* bo = (const float*)d_in[9];
    const float* Wp = (const float*)d_in[10];
    const float* pu = (const float*)d_in[11];
    const float* pv = (const float*)d_in[12];
    const float* gamma = (const float*)d_in[13];
    const float* beta  = (const float*)d_in[14];
    float* out = (float*)d_out;

    bf16 *xh,*xl,*peh,*pel,*wh,*wl,*quh,*qul,*qvh,*qvl,*kh,*kl,*vh,*vl,*php,*ppl,*th,*tl;
    cudaGetSymbolAddress((void**)&xh, g_xh);   cudaGetSymbolAddress((void**)&xl, g_xl);
    cudaGetSymbolAddress((void**)&peh, g_peh); cudaGetSymbolAddress((void**)&pel, g_pel);
    cudaGetSymbolAddress((void**)&wh, g_wh);   cudaGetSymbolAddress((void**)&wl, g_wl);
    cudaGetSymbolAddress((void**)&quh, g_quh); cudaGetSymbolAddress((void**)&qul, g_qul);
    cudaGetSymbolAddress((void**)&qvh, g_qvh); cudaGetSymbolAddress((void**)&qvl, g_qvl);
    cudaGetSymbolAddress((void**)&kh, g_kh);   cudaGetSymbolAddress((void**)&kl, g_kl);
    cudaGetSymbolAddress((void**)&vh, g_vh);   cudaGetSymbolAddress((void**)&vl, g_vl);
    cudaGetSymbolAddress((void**)&php, g_php); cudaGetSymbolAddress((void**)&ppl, g_ppl);
    cudaGetSymbolAddress((void**)&th, g_th);   cudaGetSymbolAddress((void**)&tl, g_tl);

    cudaFuncSetAttribute(gemm_mma,   cudaFuncAttributeMaxDynamicSharedMemorySize, 131072);
    cudaFuncSetAttribute(attn_fused, cudaFuncAttributeMaxDynamicSharedMemorySize, 198656);

    ln_kernel<<<BB*SS_, 128>>>(inputs, gamma, beta, xh, xl);
    pe_kernel<<<PPAD, 256>>>(peh, pel);

    cvt_kernel<<<256, 256>>>(Wq, wh + 0*DD*DD, wl + 0*DD*DD, DD*DD/4);
    cvt_kernel<<<256, 256>>>(Wk, wh + 1*DD*DD, wl + 1*DD*DD, DD*DD/4);
    cvt_kernel<<<256, 256>>>(Wv, wh + 2*DD*DD, wl + 2*DD*DD, DD*DD/4);
    cvt_kernel<<<256, 256>>>(Wo, wh + 3*DD*DD, wl + 3*DD*DD, DD*DD/4);
    cvt_kernel<<<256, 256>>>(Wp, wh + 4*DD*DD, wl + 4*DD*DD, DD*DD/4);

    // projections (warp-MMA, split-bf16, double-buffered)
    gemm_mma<<<dim3(4,32), 256, 131072>>>(xh, xl, wh+0*DD*DD, wl+0*DD*DD, bq, pu, pv,
                                           quh, qul, qvh, qvl, nullptr);
    gemm_mma<<<dim3(4,32), 256, 131072>>>(xh, xl, wh+1*DD*DD, wl+1*DD*DD, bk, nullptr, nullptr,
                                           kh, kl, nullptr, nullptr, nullptr);
    gemm_mma<<<dim3(4,32), 256, 131072>>>(xh, xl, wh+2*DD*DD, wl+2*DD*DD, bv, nullptr, nullptr,
                                           vh, vl, nullptr, nullptr, nullptr);
    gemm_mma<<<dim3(4,16), 256, 131072>>>(peh, pel, wh+4*DD*DD, wl+4*DD*DD, nullptr, nullptr, nullptr,
                                           php, ppl, nullptr, nullptr, nullptr);

    // fused attention (scores + softmax + attn@V), pipelined
    attn_fused<<<dim3(8, BB*HH), 256, 198656>>>(quh, qul, qvh, qvl, kh, kl, vh, vl,
                                                 php, ppl, amask, th, tl);

    // output projection
    gemm_mma<<<dim3(4,32), 256, 131072>>>(th, tl, wh+3*DD*DD, wl+3*DD*DD, bo, nullptr, nullptr,
                                           nullptr, nullptr, nullptr, nullptr, out);

    (void)in_sizes; (void)n_in; (void)out_size;
}

// round 7
// speedup vs baseline: 7.8497x; 2.1224x over previous
#include <cuda_runtime.h>
#include <cuda_fp16.h>
#include <math.h>
#include <string.h>
#include <stdint.h>

#define BB 4
#define SS_ 1024
#define DD 512
#define HH 8
#define DKK 64
#define PP_ 2047
#define PPAD 2048
#define PBAND 2304

typedef __half half_t;

// ---------------- scratch (zero-initialized device globals) ----------------
__device__ half_t g_xf[BB*SS_*DD];
__device__ half_t g_pef[PPAD*DD];
__device__ half_t g_wf[5*DD*DD];
__device__ half_t g_quf[BB*SS_*DD], g_qvf[BB*SS_*DD];
__device__ half_t g_kf[BB*SS_*DD],  g_vf[BB*SS_*DD];
__device__ half_t g_pf[(size_t)PBAND*DD];   // rows >= 2047 stay zero
__device__ half_t g_tf[BB*SS_*DD];

// ---------------- helpers ----------------
__device__ __forceinline__ void mma16816(float* d, const uint32_t* a, const uint32_t* b){
    asm volatile("mma.sync.aligned.m16n8k16.row.col.f32.f16.f16.f32 "
        "{%0,%1,%2,%3}, {%4,%5,%6,%7}, {%8,%9}, {%0,%1,%2,%3};"
        : "+f"(d[0]),"+f"(d[1]),"+f"(d[2]),"+f"(d[3])
        : "r"(a[0]),"r"(a[1]),"r"(a[2]),"r"(a[3]), "r"(b[0]),"r"(b[1]));
}
__device__ __forceinline__ void ldsm4(uint32_t* r, uint32_t addr){
    asm volatile("ldmatrix.sync.aligned.m8n8.x4.shared.b16 {%0,%1,%2,%3}, [%4];"
        :"=r"(r[0]),"=r"(r[1]),"=r"(r[2]),"=r"(r[3]):"r"(addr));
}
__device__ __forceinline__ void ldsm4t(uint32_t* r, uint32_t addr){
    asm volatile("ldmatrix.sync.aligned.m8n8.x4.trans.shared.b16 {%0,%1,%2,%3}, [%4];"
        :"=r"(r[0]),"=r"(r[1]),"=r"(r[2]),"=r"(r[3]):"r"(addr));
}
__device__ __forceinline__ uint32_t smem_u32(const void* p){
    uint32_t a; asm("{ .reg .u64 t; cvta.to.shared.u64 t, %1; cvt.u32.u64 %0, t; }":"=r"(a):"l"(p)); return a;
}
__device__ __forceinline__ void cp16(uint32_t dst, const void* src){
    asm volatile("cp.async.cg.shared.global [%0], [%1], 16;"
        :: "r"(dst), "l"(__cvta_generic_to_global(src)));
}
#define CP_COMMIT() asm volatile("cp.async.commit_group;" ::: "memory")
#define CP_WAIT1()  asm volatile("cp.async.wait_group 1;" ::: "memory")
static __device__ __forceinline__ uint32_t swz(uint32_t o){ return o ^ ((o>>3)&0x70); }
__device__ __forceinline__ uint32_t a_addr(uint32_t base, int m16, int k0, int lane){
    int g = lane>>3, r = lane&7;
    int row = m16 + r + (g&1)*8;
    uint32_t o = (uint32_t)(row*128 + (k0 + (g>>1)*8)*2);
    return base + swz(o);
}
__device__ __forceinline__ uint32_t b_addr(uint32_t base, int n0, int k0, int lane){
    int g = lane>>3, r = lane&7;
    int row = n0 + r + (g>>1)*8;
    uint32_t o = (uint32_t)(row*128 + (k0 + (g&1)*8)*2);
    return base + swz(o);
}
__device__ __forceinline__ uint32_t v_addr(uint32_t base, int k0, int d0, int lane){
    int g = lane>>3, r = lane&7;
    int row = k0 + r + (g&1)*8;
    uint32_t o = (uint32_t)(row*128 + (d0 + (g>>1)*8)*2);
    return base + swz(o);
}
__device__ __forceinline__ uint32_t packh(float x, float y){
    __half2 h = __floats2half2_rn(x, y);
    uint32_t u; memcpy(&u, &h, 4); return u;
}

// ---------------- LayerNorm -> fp16 ----------------
__global__ void ln_kernel(const float* __restrict__ x, const float* __restrict__ gamma,
                          const float* __restrict__ beta, half_t* __restrict__ xf) {
    __shared__ float red[4];
    int row = blockIdx.x; int t = threadIdx.x;
    float4 v = ((const float4*)(x + (size_t)row * DD))[t];
    float s = v.x+v.y+v.z+v.w;
    #pragma unroll
    for (int o=16;o;o>>=1) s += __shfl_xor_sync(0xffffffffu,s,o);
    if ((t&31)==0) red[t>>5]=s;
    __syncthreads();
    float mu=(red[0]+red[1]+red[2]+red[3])*(1.0f/DD);
    float dx=v.x-mu,dy=v.y-mu,dz=v.z-mu,dw=v.w-mu;
    float ss=dx*dx+dy*dy+dz*dz+dw*dw;
    #pragma unroll
    for (int o=16;o;o>>=1) ss += __shfl_xor_sync(0xffffffffu,ss,o);
    __syncthreads();
    if ((t&31)==0) red[t>>5]=ss;
    __syncthreads();
    float rstd=rsqrtf((red[0]+red[1]+red[2]+red[3])*(1.0f/DD)+1e-5f);
    float4 g=((const float4*)gamma)[t], be=((const float4*)beta)[t];
    uint2 o2;
    o2.x = packh(dx*rstd*g.x+be.x, dy*rstd*g.y+be.y);
    o2.y = packh(dz*rstd*g.z+be.z, dw*rstd*g.w+be.w);
    *(uint2*)(xf + (size_t)row*DD + 4*t) = o2;
}

// ---------------- positional embedding -> fp16 (row >= PP_ zero) ----------------
__global__ void pe_kernel(half_t* __restrict__ pef) {
    int j = blockIdx.x; int t = threadIdx.x;
    uint32_t u = 0;
    if (j < PP_) {
        float pos = (float)(j - (SS_ - 1));
        const float kconst = -0.01798894603901598415f;
        float div = expf((float)(2*t) * kconst);
        float sa, ca; sincosf(pos * div, &sa, &ca);
        u = packh(sa, ca);
    }
    *(uint32_t*)(pef + (size_t)j*DD + 2*t) = u;
}

// ---------------- 5 weights fp32 -> fp16, one launch ----------------
__global__ void cvtw_kernel(const float* __restrict__ Wq, const float* __restrict__ Wk,
                            const float* __restrict__ Wv, const float* __restrict__ Wo,
                            const float* __restrict__ Wp, half_t* __restrict__ wf){
    int i = blockIdx.x * 256 + threadIdx.x;          // 5*65536 float4-groups
    int widx = i >> 16, j = i & 65535;
    const float* src = (widx==0)?Wq:(widx==1)?Wk:(widx==2)?Wv:(widx==3)?Wo:Wp;
    float4 v = ((const float4*)src)[j];
    uint2 o2; o2.x = packh(v.x, v.y); o2.y = packh(v.z, v.w);
    ((uint2*)(wf + (size_t)widx*DD*DD))[j] = o2;
}

// ================= fp16 MMA GEMM: C[M,512] = A[M,512] @ B[512,512]^T =================
__global__ __launch_bounds__(256) void gemm_f16(
    const half_t* __restrict__ A, const half_t* __restrict__ Bw,
    const float* __restrict__ bias, const float* __restrict__ add0, const float* __restrict__ add1,
    half_t* __restrict__ O0, half_t* __restrict__ O1, float* __restrict__ O32)
{
    extern __shared__ char sm[];
    const int tid = threadIdx.x, lane = tid & 31, wid = tid >> 5;
    const int bm = blockIdx.y * 128, bn = blockIdx.x * 128;
    const uint32_t sb = smem_u32(sm);
    const int m0w = (wid>>2)*64, n0w = (wid&3)*32;

    auto issueg = [&](int kc){
        uint32_t base = sb + (uint32_t)(kc&1)*32768;
        for (int u = tid; u < 1024; u += 256) {
            int row = u>>3, cb = u&7;
            uint32_t off = swz((uint32_t)(row*128 + cb*16));
            cp16(base + off,         A  + (size_t)(bm+row)*DD + kc*64 + cb*8);
            cp16(base + 16384 + off, Bw + (size_t)(bn+row)*DD + kc*64 + cb*8);
        }
    };

    float acc[4][4][4];
    #pragma unroll
    for (int a=0;a<4;++a)
        #pragma unroll
        for (int b=0;b<4;++b)
            #pragma unroll
            for (int c=0;c<4;++c) acc[a][b][c]=0.f;

    issueg(0); CP_COMMIT();
    issueg(1); CP_COMMIT();

    for (int kc = 0; kc < 8; ++kc) {
        CP_WAIT1();
        __syncthreads();
        uint32_t base = sb + (uint32_t)(kc&1)*32768;
        #pragma unroll
        for (int ks = 0; ks < 4; ++ks) {
            int k0 = ks*16;
            uint32_t aF[4][4], bF[2][4];
            #pragma unroll
            for (int mt=0; mt<4; ++mt) ldsm4(aF[mt], a_addr(base, m0w+mt*16, k0, lane));
            #pragma unroll
            for (int p=0; p<2; ++p)   ldsm4(bF[p], b_addr(base+16384, n0w+p*16, k0, lane));
            #pragma unroll
            for (int mt=0; mt<4; ++mt)
                #pragma unroll
                for (int nt=0; nt<4; ++nt)
                    mma16816(acc[mt][nt], aF[mt], &bF[nt>>1][(nt&1)*2]);
        }
        __syncthreads();
        if (kc + 2 < 8) issueg(kc + 2);
        CP_COMMIT();
    }
    const int r = lane>>2, c = (lane&3)*2;
    #pragma unroll
    for (int mt=0; mt<4; ++mt)
        #pragma unroll
        for (int nt=0; nt<4; ++nt) {
            int n_ = bn + n0w + nt*8 + c;
            float b0 = bias ? bias[n_] : 0.f, b1 = bias ? bias[n_+1] : 0.f;
            #pragma unroll
            for (int half_=0; half_<2; ++half_) {
                int m_ = bm + m0w + mt*16 + r + half_*8;
                float v0 = acc[mt][nt][half_*2+0] + b0;
                float v1 = acc[mt][nt][half_*2+1] + b1;
                if (O32) {
                    *(float2*)(O32 + (size_t)m_*DD + n_) = make_float2(v0, v1);
                } else if (O1) {
                    *(uint32_t*)(O0 + (size_t)m_*DD + n_) = packh(v0 + add0[n_], v1 + add0[n_+1]);
                    *(uint32_t*)(O1 + (size_t)m_*DD + n_) = packh(v0 + add1[n_], v1 + add1[n_+1]);
                } else {
                    *(uint32_t*)(O0 + (size_t)m_*DD + n_) = packh(v0, v1);
                }
            }
        }
}

// ================= fused attention, 24-stage cp.async pipeline, fp16 =================
// stage types per chunk: 0 = P band (256 rows, 32KB), 1 = K (16KB), 2 = V (16KB)
__global__ __launch_bounds__(256) void attn_fused(
    const half_t* __restrict__ quf, const half_t* __restrict__ qvf,
    const half_t* __restrict__ kf,  const half_t* __restrict__ vf,
    const half_t* __restrict__ pf,
    const unsigned char* __restrict__ mask,
    half_t* __restrict__ tf)
{
    extern __shared__ char sm[];
    const int tid = threadIdx.x, lane = tid & 31, wid = tid >> 5;
    const int bh = blockIdx.y, b = bh >> 3, h = bh & 7;
    const int qc = blockIdx.x * 128;
    const uint32_t sb = smem_u32(sm);
    float* bd = (float*)(sm + 98304);     // [128][132] fp32, warp-private rows
    const int wq = wid * 16;
    const int r = lane>>2, c = (lane&3)*2;

    auto issue = [&](int st){
        int type = st % 3, ch = st / 3;
        uint32_t buf = sb + 32768 + (uint32_t)(st&1)*32768;
        if (type == 0) {
            size_t rowbase = (size_t)(1024 + 128*ch - qc - 127);
            for (int u = tid; u < 2048; u += 256){
                int row = u>>3, cb = u&7;
                cp16(buf + swz((uint32_t)(row*128 + cb*16)), pf + (rowbase + row)*DD + h*DKK + cb*8);
            }
        } else {
            const half_t* src = (type == 1) ? kf : vf;
            size_t rowbase = (size_t)(b*SS_ + 128*ch);
            for (int u = tid; u < 1024; u += 256){
                int row = u>>3, cb = u&7;
                cp16(buf + swz((uint32_t)(row*128 + cb*16)), src + (rowbase + row)*DD + h*DKK + cb*8);
            }
        }
    };

    // group 0: resident Q tiles + stage 0
    for (int u = tid; u < 1024; u += 256) {
        int row = u>>3, cb = u&7;
        uint32_t off = swz((uint32_t)(row*128 + cb*16));
        size_t g = (size_t)(b*SS_ + qc + row)*DD + h*DKK + cb*8;
        cp16(sb + off,         quf + g);
        cp16(sb + 16384 + off, qvf + g);
    }
    issue(0); CP_COMMIT();
    issue(1); CP_COMMIT();

    // rel_shift wrap value: bd(0,1023) = qv[b,h,1]·p[0]
    float wrapv = 0.f;
    if (qc == 0 && wid == 0) {
        #pragma unroll
        for (int d = 0; d < DKK; ++d)
            wrapv += __half2float(qvf[(size_t)(b*SS_+1)*DD + h*DKK + d])
                   * __half2float(pf[h*DKK + d]);
    }

    float m0 = -1e30f, m1 = -1e30f, l0 = 0.f, l1 = 0.f;
    float accO[8][4];
    #pragma unroll
    for (int i=0;i<8;++i)
        #pragma unroll
        for (int j=0;j<4;++j) accO[i][j]=0.f;

    uint32_t paF[8][4];

    for (int st = 0; st < 24; ++st) {
        CP_WAIT1();
        __syncthreads();
        const int type = st % 3, ch = st / 3;
        const uint32_t op = sb + 32768 + (uint32_t)(st&1)*32768;

        if (type == 0) {
            // BD banded GEMM over 256-row P band; scatter j = t + i - 127 (warp-private rows)
            float bdacc[9][2][4];
            #pragma unroll
            for (int gi=0;gi<9;++gi)
                #pragma unroll
                for (int q2=0;q2<2;++q2)
                    #pragma unroll
                    for (int e=0;e<4;++e) bdacc[gi][q2][e]=0.f;
            #pragma unroll
            for (int ks = 0; ks < 4; ++ks) {
                int k0 = ks*16;
                uint32_t aF[4];
                ldsm4(aF, a_addr(sb + 16384, wq, k0, lane));
                #pragma unroll
                for (int gi = 0; gi < 9; ++gi) {
                    int n0 = (7 - wid + gi)*16;
                    uint32_t bF[4];
                    ldsm4(bF, b_addr(op, n0, k0, lane));
                    mma16816(bdacc[gi][0], aF, &bF[0]);
                    mma16816(bdacc[gi][1], aF, &bF[2]);
                }
            }
            #pragma unroll
            for (int gi = 0; gi < 9; ++gi) {
                int g16 = 7 - wid + gi;
                #pragma unroll
                for (int q2 = 0; q2 < 2; ++q2) {
                    int t0 = g16*16 + q2*8 + c;
                    int i0 = wq + r, i1 = i0 + 8;
                    int j;
                    j = t0     + i0 - 127; if (j>=0 && j<128) bd[i0*132+j] = bdacc[gi][q2][0];
                    j = t0 + 1 + i0 - 127; if (j>=0 && j<128) bd[i0*132+j] = bdacc[gi][q2][1];
                    j = t0     + i1 - 127; if (j>=0 && j<128) bd[i1*132+j] = bdacc[gi][q2][2];
                    j = t0 + 1 + i1 - 127; if (j>=0 && j<128) bd[i1*132+j] = bdacc[gi][q2][3];
                }
            }
        } else if (type == 1) {
            const int kk0 = ch * 128;
            float s[16][4];
            #pragma unroll
            for (int nt=0;nt<16;++nt)
                #pragma unroll
                for (int e=0;e<4;++e) s[nt][e]=0.f;
            #pragma unroll
            for (int ks = 0; ks < 4; ++ks) {
                int k0 = ks*16;
                uint32_t aF[4];
                ldsm4(aF, a_addr(sb, wq, k0, lane));
                #pragma unroll
                for (int g16 = 0; g16 < 8; ++g16) {
                    uint32_t bF[4];
                    ldsm4(bF, b_addr(op, g16*16, k0, lane));
                    mma16816(s[2*g16],   aF, &bF[0]);
                    mma16816(s[2*g16+1], aF, &bF[2]);
                }
            }
            const int i0 = wq + r, i1 = i0 + 8;
            float mc0 = -1e30f, mc1 = -1e30f;
            #pragma unroll
            for (int nt = 0; nt < 16; ++nt) {
                int jc = nt*8 + c;
                float v0 = s[nt][0] + bd[i0*132 + jc];
                float v1 = s[nt][1] + bd[i0*132 + jc + 1];
                float v2 = s[nt][2] + bd[i1*132 + jc];
                float v3 = s[nt][3] + bd[i1*132 + jc + 1];
                if (qc == 0 && ch == 7 && nt == 15 && wid == 0 && lane == 3) v1 += wrapv;
                v0 *= 0.125f; v1 *= 0.125f; v2 *= 0.125f; v3 *= 0.125f;
                const unsigned char* mr0 = mask + (size_t)b*SS_*SS_ + (size_t)(qc+i0)*SS_ + kk0 + jc;
                const unsigned char* mr1 = mask + (size_t)b*SS_*SS_ + (size_t)(qc+i1)*SS_ + kk0 + jc;
                uchar2 mq0 = *(const uchar2*)mr0;
                uchar2 mq1 = *(const uchar2*)mr1;
                if (mq0.x) v0 = -10000.f;
                if (mq0.y) v1 = -10000.f;
                if (mq1.x) v2 = -10000.f;
                if (mq1.y) v3 = -10000.f;
                s[nt][0]=v0; s[nt][1]=v1; s[nt][2]=v2; s[nt][3]=v3;
                mc0 = fmaxf(mc0, fmaxf(v0, v1));
                mc1 = fmaxf(mc1, fmaxf(v2, v3));
            }
            mc0 = fmaxf(mc0, __shfl_xor_sync(0xffffffffu, mc0, 1));
            mc0 = fmaxf(mc0, __shfl_xor_sync(0xffffffffu, mc0, 2));
            mc1 = fmaxf(mc1, __shfl_xor_sync(0xffffffffu, mc1, 1));
            mc1 = fmaxf(mc1, __shfl_xor_sync(0xffffffffu, mc1, 2));
            float mn0 = fmaxf(m0, mc0), mn1 = fmaxf(m1, mc1);
            float cor0 = __expf(m0 - mn0), cor1 = __expf(m1 - mn1);
            m0 = mn0; m1 = mn1;
            float ls0 = 0.f, ls1 = 0.f;
            #pragma unroll
            for (int kt = 0; kt < 8; ++kt) {
                float p00 = __expf(s[2*kt][0]   - m0), p01 = __expf(s[2*kt][1]   - m0);
                float p02 = __expf(s[2*kt][2]   - m1), p03 = __expf(s[2*kt][3]   - m1);
                float p10 = __expf(s[2*kt+1][0] - m0), p11 = __expf(s[2*kt+1][1] - m0);
                float p12 = __expf(s[2*kt+1][2] - m1), p13 = __expf(s[2*kt+1][3] - m1);
                ls0 += p00 + p01 + p10 + p11;
                ls1 += p02 + p03 + p12 + p13;
                paF[kt][0] = packh(p00, p01);
                paF[kt][1] = packh(p02, p03);
                paF[kt][2] = packh(p10, p11);
                paF[kt][3] = packh(p12, p13);
            }
            ls0 += __shfl_xor_sync(0xffffffffu, ls0, 1);
            ls0 += __shfl_xor_sync(0xffffffffu, ls0, 2);
            ls1 += __shfl_xor_sync(0xffffffffu, ls1, 1);
            ls1 += __shfl_xor_sync(0xffffffffu, ls1, 2);
            l0 = l0*cor0 + ls0;
            l1 = l1*cor1 + ls1;
            #pragma unroll
            for (int dn = 0; dn < 8; ++dn) {
                accO[dn][0]*=cor0; accO[dn][1]*=cor0; accO[dn][2]*=cor1; accO[dn][3]*=cor1;
            }
        } else {
            #pragma unroll
            for (int kt = 0; kt < 8; ++kt) {
                #pragma unroll
                for (int dp = 0; dp < 4; ++dp) {
                    uint32_t bF[4];
                    ldsm4t(bF, v_addr(op, kt*16, dp*16, lane));
                    mma16816(accO[2*dp],   paF[kt], &bF[0]);
                    mma16816(accO[2*dp+1], paF[kt], &bF[2]);
                }
            }
        }

        __syncthreads();
        if (st + 2 < 24) issue(st + 2);
        CP_COMMIT();
    }

    float inv0 = 1.f / l0, inv1 = 1.f / l1;
    const int q0 = qc + wq + r, q1 = q0 + 8;
    #pragma unroll
    for (int dn = 0; dn < 8; ++dn) {
        int d = dn*8 + c;
        *(uint32_t*)(tf + (size_t)(b*SS_+q0)*DD + h*DKK + d) = packh(accO[dn][0]*inv0, accO[dn][1]*inv0);
        *(uint32_t*)(tf + (size_t)(b*SS_+q1)*DD + h*DKK + d) = packh(accO[dn][2]*inv1, accO[dn][3]*inv1);
    }
}

// ---------------- launch ----------------
extern "C" void kernel_launch(void* const* d_in, const int* in_sizes, int n_in,
                              void* d_out, int out_size) {
    const float* inputs        = (const float*)d_in[0];
    const unsigned char* amask = (const unsigned char*)d_in[1];
    const float* Wq = (const float*)d_in[2];
    const float* bq = (const float*)d_in[3];
    const float* Wk = (const float*)d_in[4];
    const float* bk = (const float*)d_in[5];
    const float* Wv = (const float*)d_in[6];
    const float* bv = (const float*)d_in[7];
    const float* Wo = (const float*)d_in[8];
    const float* bo = (const float*)d_in[9];
    const float* Wp = (const float*)d_in[10];
    const float* pu = (const float*)d_in[11];
    const float* pv = (const float*)d_in[12];
    const float* gamma = (const float*)d_in[13];
    const float* beta  = (const float*)d_in[14];
    float* out = (float*)d_out;

    half_t *xf,*pef,*wf,*quf,*qvf,*kf,*vf,*pf,*tf;
    cudaGetSymbolAddress((void**)&xf, g_xf);
    cudaGetSymbolAddress((void**)&pef, g_pef);
    cudaGetSymbolAddress((void**)&wf, g_wf);
    cudaGetSymbolAddress((void**)&quf, g_quf);
    cudaGetSymbolAddress((void**)&qvf, g_qvf);
    cudaGetSymbolAddress((void**)&kf, g_kf);
    cudaGetSymbolAddress((void**)&vf, g_vf);
    cudaGetSymbolAddress((void**)&pf, g_pf);
    cudaGetSymbolAddress((void**)&tf, g_tf);

    cudaFuncSetAttribute(gemm_f16,   cudaFuncAttributeMaxDynamicSharedMemorySize, 65536);
    cudaFuncSetAttribute(attn_fused, cudaFuncAttributeMaxDynamicSharedMemorySize, 165888);

    ln_kernel<<<BB*SS_, 128>>>(inputs, gamma, beta, xf);
    pe_kernel<<<PPAD, 256>>>(pef);
    cvtw_kernel<<<1280, 256>>>(Wq, Wk, Wv, Wo, Wp, wf);

    // projections (fp16 single-term)
    gemm_f16<<<dim3(4,32), 256, 65536>>>(xf, wf+0*DD*DD, bq, pu, pv, quf, qvf, nullptr);
    gemm_f16<<<dim3(4,32), 256, 65536>>>(xf, wf+1*DD*DD, bk, nullptr, nullptr, kf, nullptr, nullptr);
    gemm_f16<<<dim3(4,32), 256, 65536>>>(xf, wf+2*DD*DD, bv, nullptr, nullptr, vf, nullptr, nullptr);
    gemm_f16<<<dim3(4,16), 256, 65536>>>(pef, wf+4*DD*DD, nullptr, nullptr, nullptr, pf, nullptr, nullptr);

    // fused attention
    attn_fused<<<dim3(8, BB*HH), 256, 165888>>>(quf, qvf, kf, vf, pf, amask, tf);

    // output projection (fp32 out)
    gemm_f16<<<dim3(4,32), 256, 65536>>>(tf, wf+3*DD*DD, bo, nullptr, nullptr, nullptr, nullptr, out);

    (void)in_sizes; (void)n_in; (void)out_size;
}

// round 8
// speedup vs baseline: 9.0130x; 1.1482x over previous
#include <cuda_runtime.h>
#include <cuda_fp16.h>
#include <math.h>
#include <string.h>
#include <stdint.h>

#define BB 4
#define SS_ 1024
#define DD 512
#define HH 8
#define DKK 64
#define PP_ 2047
#define PPAD 2048
#define PBAND 2304

typedef __half half_t;

// ---------------- scratch (zero-initialized device globals) ----------------
__device__ half_t g_xf[BB*SS_*DD];
__device__ half_t g_pef[PPAD*DD];
__device__ half_t g_wf[5*DD*DD];
__device__ half_t g_quf[BB*SS_*DD], g_qvf[BB*SS_*DD];
__device__ half_t g_kf[BB*SS_*DD],  g_vf[BB*SS_*DD];
__device__ half_t g_pf[(size_t)PBAND*DD];   // rows >= 2047 stay zero
__device__ half_t g_tf[BB*SS_*DD];

// ---------------- helpers ----------------
__device__ __forceinline__ void mma16816(float* d, const uint32_t* a, const uint32_t* b){
    asm volatile("mma.sync.aligned.m16n8k16.row.col.f32.f16.f16.f32 "
        "{%0,%1,%2,%3}, {%4,%5,%6,%7}, {%8,%9}, {%0,%1,%2,%3};"
        : "+f"(d[0]),"+f"(d[1]),"+f"(d[2]),"+f"(d[3])
        : "r"(a[0]),"r"(a[1]),"r"(a[2]),"r"(a[3]), "r"(b[0]),"r"(b[1]));
}
__device__ __forceinline__ void ldsm4(uint32_t* r, uint32_t addr){
    asm volatile("ldmatrix.sync.aligned.m8n8.x4.shared.b16 {%0,%1,%2,%3}, [%4];"
        :"=r"(r[0]),"=r"(r[1]),"=r"(r[2]),"=r"(r[3]):"r"(addr));
}
__device__ __forceinline__ void ldsm4t(uint32_t* r, uint32_t addr){
    asm volatile("ldmatrix.sync.aligned.m8n8.x4.trans.shared.b16 {%0,%1,%2,%3}, [%4];"
        :"=r"(r[0]),"=r"(r[1]),"=r"(r[2]),"=r"(r[3]):"r"(addr));
}
__device__ __forceinline__ uint32_t smem_u32(const void* p){
    uint32_t a; asm("{ .reg .u64 t; cvta.to.shared.u64 t, %1; cvt.u32.u64 %0, t; }":"=r"(a):"l"(p)); return a;
}
__device__ __forceinline__ void cp16(uint32_t dst, const void* src){
    asm volatile("cp.async.cg.shared.global [%0], [%1], 16;"
        :: "r"(dst), "l"(__cvta_generic_to_global(src)));
}
#define CP_COMMIT() asm volatile("cp.async.commit_group;" ::: "memory")
#define CP_WAIT1()  asm volatile("cp.async.wait_group 1;" ::: "memory")
static __device__ __forceinline__ uint32_t swz(uint32_t o){ return o ^ ((o>>3)&0x70); }
__device__ __forceinline__ uint32_t a_addr(uint32_t base, int m16, int k0, int lane){
    int g = lane>>3, r = lane&7;
    int row = m16 + r + (g&1)*8;
    uint32_t o = (uint32_t)(row*128 + (k0 + (g>>1)*8)*2);
    return base + swz(o);
}
__device__ __forceinline__ uint32_t b_addr(uint32_t base, int n0, int k0, int lane){
    int g = lane>>3, r = lane&7;
    int row = n0 + r + (g>>1)*8;
    uint32_t o = (uint32_t)(row*128 + (k0 + (g&1)*8)*2);
    return base + swz(o);
}
__device__ __forceinline__ uint32_t v_addr(uint32_t base, int k0, int d0, int lane){
    int g = lane>>3, r = lane&7;
    int row = k0 + r + (g&1)*8;
    uint32_t o = (uint32_t)(row*128 + (d0 + (g>>1)*8)*2);
    return base + swz(o);
}
__device__ __forceinline__ uint32_t packh(float x, float y){
    __half2 h = __floats2half2_rn(x, y);
    uint32_t u; memcpy(&u, &h, 4); return u;
}

// ================= prep: LN + PE + weight converts, one launch =================
// blocks [0,2048): LN (2 rows/block); [2048,4096): PE; [4096,5376): weight cvt
__global__ void prep_kernel(const float* __restrict__ x, const float* __restrict__ gamma,
                            const float* __restrict__ beta,
                            const float* __restrict__ Wq, const float* __restrict__ Wk,
                            const float* __restrict__ Wv, const float* __restrict__ Wo,
                            const float* __restrict__ Wp,
                            half_t* __restrict__ xf, half_t* __restrict__ pef,
                            half_t* __restrict__ wf) {
    __shared__ float red[8];
    const int blk = blockIdx.x, tid = threadIdx.x;
    if (blk < 2048) {
        int halfid = tid >> 7, t = tid & 127;
        int row = blk*2 + halfid;
        float4 v = ((const float4*)(x + (size_t)row*DD))[t];
        float s = v.x+v.y+v.z+v.w;
        #pragma unroll
        for (int o=16;o;o>>=1) s += __shfl_xor_sync(0xffffffffu,s,o);
        if ((t&31)==0) red[tid>>5]=s;
        __syncthreads();
        float mu=(red[halfid*4]+red[halfid*4+1]+red[halfid*4+2]+red[halfid*4+3])*(1.0f/DD);
        float dx=v.x-mu,dy=v.y-mu,dz=v.z-mu,dw=v.w-mu;
        float ss=dx*dx+dy*dy+dz*dz+dw*dw;
        #pragma unroll
        for (int o=16;o;o>>=1) ss += __shfl_xor_sync(0xffffffffu,ss,o);
        __syncthreads();
        if ((t&31)==0) red[tid>>5]=ss;
        __syncthreads();
        float rstd=rsqrtf((red[halfid*4]+red[halfid*4+1]+red[halfid*4+2]+red[halfid*4+3])*(1.0f/DD)+1e-5f);
        float4 g=((const float4*)gamma)[t], be=((const float4*)beta)[t];
        uint2 o2;
        o2.x = packh(dx*rstd*g.x+be.x, dy*rstd*g.y+be.y);
        o2.y = packh(dz*rstd*g.z+be.z, dw*rstd*g.w+be.w);
        *(uint2*)(xf + (size_t)row*DD + 4*t) = o2;
    } else if (blk < 4096) {
        int j = blk - 2048;
        uint32_t u = 0;
        if (j < PP_) {
            float pos = (float)(j - (SS_ - 1));
            const float kconst = -0.01798894603901598415f;
            float div = expf((float)(2*tid) * kconst);
            float sa, ca; sincosf(pos * div, &sa, &ca);
            u = packh(sa, ca);
        }
        *(uint32_t*)(pef + (size_t)j*DD + 2*tid) = u;
    } else {
        int i = (blk - 4096)*256 + tid;          // 0 .. 5*65536-1
        int widx = i >> 16, j = i & 65535;
        const float* src = (widx==0)?Wq:(widx==1)?Wk:(widx==2)?Wv:(widx==3)?Wo:Wp;
        float4 v = ((const float4*)src)[j];
        uint2 o2; o2.x = packh(v.x, v.y); o2.y = packh(v.z, v.w);
        ((uint2*)(wf + (size_t)widx*DD*DD))[j] = o2;
    }
}

// ================= fused projections: QKV (N=1536) + P, one launch =================
// blocks [0,384): qkv, bx=cta%12 (n-tile), by=cta/12 (m-tile of xf)
// blocks [384,448): p,  bx=(cta-384)%4,  by=(cta-384)/4 (m-tile of pef)
__global__ __launch_bounds__(256,2) void proj_all(
    const half_t* __restrict__ xf, const half_t* __restrict__ pef,
    const half_t* __restrict__ wf,
    const float* __restrict__ bq, const float* __restrict__ bk, const float* __restrict__ bv,
    const float* __restrict__ pu, const float* __restrict__ pv,
    half_t* __restrict__ quf, half_t* __restrict__ qvf,
    half_t* __restrict__ kf, half_t* __restrict__ vf, half_t* __restrict__ pf)
{
    extern __shared__ char sm[];
    const int tid = threadIdx.x, lane = tid & 31, wid = tid >> 5;
    const uint32_t sb = smem_u32(sm);
    const int m0w = (wid>>2)*64, n0w = (wid&3)*32;
    const int cta = blockIdx.x;
    const half_t *A, *B;
    int bm, bn, mode;
    if (cta < 384) {
        int bx = cta % 12, by = cta / 12;
        bm = by*128; bn = bx*128;
        A = xf; B = wf + (size_t)bn*DD;
        mode = bn >> 9;                 // 0=q, 1=k, 2=v
    } else {
        int c2 = cta - 384;
        int bx = c2 & 3, by = c2 >> 2;
        bm = by*128; bn = bx*128;
        A = pef; B = wf + 4*(size_t)DD*DD + (size_t)bn*DD;
        mode = 3;
    }

    auto issueg = [&](int kc){
        uint32_t base = sb + (uint32_t)(kc&1)*32768;
        for (int u = tid; u < 1024; u += 256) {
            int row = u>>3, cb = u&7;
            uint32_t off = swz((uint32_t)(row*128 + cb*16));
            cp16(base + off,         A + (size_t)(bm+row)*DD + kc*64 + cb*8);
            cp16(base + 16384 + off, B + (size_t)row*DD + kc*64 + cb*8);
        }
    };

    float acc[4][4][4];
    #pragma unroll
    for (int a=0;a<4;++a)
        #pragma unroll
        for (int b2=0;b2<4;++b2)
            #pragma unroll
            for (int c2=0;c2<4;++c2) acc[a][b2][c2]=0.f;

    issueg(0); CP_COMMIT();
    issueg(1); CP_COMMIT();

    for (int kc = 0; kc < 8; ++kc) {
        CP_WAIT1();
        __syncthreads();
        uint32_t base = sb + (uint32_t)(kc&1)*32768;
        #pragma unroll
        for (int ks = 0; ks < 4; ++ks) {
            int k0 = ks*16;
            uint32_t aF[4][4], bF[2][4];
            #pragma unroll
            for (int mt=0; mt<4; ++mt) ldsm4(aF[mt], a_addr(base, m0w+mt*16, k0, lane));
            #pragma unroll
            for (int p=0; p<2; ++p)   ldsm4(bF[p], b_addr(base+16384, n0w+p*16, k0, lane));
            #pragma unroll
            for (int mt=0; mt<4; ++mt)
                #pragma unroll
                for (int nt=0; nt<4; ++nt)
                    mma16816(acc[mt][nt], aF[mt], &bF[nt>>1][(nt&1)*2]);
        }
        __syncthreads();
        if (kc + 2 < 8) issueg(kc + 2);
        CP_COMMIT();
    }
    const int r = lane>>2, c = (lane&3)*2;
    const int nbase = bn & 511;
    #pragma unroll
    for (int mt=0; mt<4; ++mt)
        #pragma unroll
        for (int nt=0; nt<4; ++nt) {
            int nl = nbase + n0w + nt*8 + c;
            float b0 = 0.f, b1 = 0.f;
            if (mode == 0)      { b0 = bq[nl]; b1 = bq[nl+1]; }
            else if (mode == 1) { b0 = bk[nl]; b1 = bk[nl+1]; }
            else if (mode == 2) { b0 = bv[nl]; b1 = bv[nl+1]; }
            #pragma unroll
            for (int half_=0; half_<2; ++half_) {
                int m_ = bm + m0w + mt*16 + r + half_*8;
                float v0 = acc[mt][nt][half_*2+0] + b0;
                float v1 = acc[mt][nt][half_*2+1] + b1;
                if (mode == 0) {
                    *(uint32_t*)(quf + (size_t)m_*DD + nl) = packh(v0 + pu[nl], v1 + pu[nl+1]);
                    *(uint32_t*)(qvf + (size_t)m_*DD + nl) = packh(v0 + pv[nl], v1 + pv[nl+1]);
                } else if (mode == 1) {
                    *(uint32_t*)(kf + (size_t)m_*DD + nl) = packh(v0, v1);
                } else if (mode == 2) {
                    *(uint32_t*)(vf + (size_t)m_*DD + nl) = packh(v0, v1);
                } else {
                    *(uint32_t*)(pf + (size_t)m_*DD + nl) = packh(v0, v1);
                }
            }
        }
}

// ================= out projection (fp16 MMA, fp32 out) =================
__global__ __launch_bounds__(256) void gemm_out(
    const half_t* __restrict__ A, const half_t* __restrict__ Bw,
    const float* __restrict__ bias, float* __restrict__ O32)
{
    extern __shared__ char sm[];
    const int tid = threadIdx.x, lane = tid & 31, wid = tid >> 5;
    const int bm = blockIdx.y * 128, bn = blockIdx.x * 128;
    const uint32_t sb = smem_u32(sm);
    const int m0w = (wid>>2)*64, n0w = (wid&3)*32;

    auto issueg = [&](int kc){
        uint32_t base = sb + (uint32_t)(kc&1)*32768;
        for (int u = tid; u < 1024; u += 256) {
            int row = u>>3, cb = u&7;
            uint32_t off = swz((uint32_t)(row*128 + cb*16));
            cp16(base + off,         A  + (size_t)(bm+row)*DD + kc*64 + cb*8);
            cp16(base + 16384 + off, Bw + (size_t)(bn+row)*DD + kc*64 + cb*8);
        }
    };

    float acc[4][4][4];
    #pragma unroll
    for (int a=0;a<4;++a)
        #pragma unroll
        for (int b2=0;b2<4;++b2)
            #pragma unroll
            for (int c2=0;c2<4;++c2) acc[a][b2][c2]=0.f;

    issueg(0); CP_COMMIT();
    issueg(1); CP_COMMIT();

    for (int kc = 0; kc < 8; ++kc) {
        CP_WAIT1();
        __syncthreads();
        uint32_t base = sb + (uint32_t)(kc&1)*32768;
        #pragma unroll
        for (int ks = 0; ks < 4; ++ks) {
            int k0 = ks*16;
            uint32_t aF[4][4], bF[2][4];
            #pragma unroll
            for (int mt=0; mt<4; ++mt) ldsm4(aF[mt], a_addr(base, m0w+mt*16, k0, lane));
            #pragma unroll
            for (int p=0; p<2; ++p)   ldsm4(bF[p], b_addr(base+16384, n0w+p*16, k0, lane));
            #pragma unroll
            for (int mt=0; mt<4; ++mt)
                #pragma unroll
                for (int nt=0; nt<4; ++nt)
                    mma16816(acc[mt][nt], aF[mt], &bF[nt>>1][(nt&1)*2]);
        }
        __syncthreads();
        if (kc + 2 < 8) issueg(kc + 2);
        CP_COMMIT();
    }
    const int r = lane>>2, c = (lane&3)*2;
    #pragma unroll
    for (int mt=0; mt<4; ++mt)
        #pragma unroll
        for (int nt=0; nt<4; ++nt) {
            int n_ = bn + n0w + nt*8 + c;
            float b0 = bias[n_], b1 = bias[n_+1];
            #pragma unroll
            for (int half_=0; half_<2; ++half_) {
                int m_ = bm + m0w + mt*16 + r + half_*8;
                *(float2*)(O32 + (size_t)m_*DD + n_) =
                    make_float2(acc[mt][nt][half_*2+0] + b0, acc[mt][nt][half_*2+1] + b1);
            }
        }
}

// ================= fused attention, 16-stage cp.async pipeline =================
// per chunk ch: stage 2ch = P band (32KB), stage 2ch+1 = K+V (16+16KB)
__global__ __launch_bounds__(256) void attn_fused(
    const half_t* __restrict__ quf, const half_t* __restrict__ qvf,
    const half_t* __restrict__ kf,  const half_t* __restrict__ vf,
    const half_t* __restrict__ pf,
    const unsigned char* __restrict__ mask,
    half_t* __restrict__ tf)
{
    extern __shared__ char sm[];
    const int tid = threadIdx.x, lane = tid & 31, wid = tid >> 5;
    const int bh = blockIdx.y, b = bh >> 3, h = bh & 7;
    const int qc = blockIdx.x * 128;
    const uint32_t sb = smem_u32(sm);
    float* bd = (float*)(sm + 98304);     // [128][132] fp32, warp-private rows
    const int wq = wid * 16;
    const int r = lane>>2, c = (lane&3)*2;

    auto issue = [&](int st){
        int ch = st >> 1;
        uint32_t buf = sb + 32768 + (uint32_t)(st&1)*32768;
        if ((st & 1) == 0) {  // P band: 256 rows
            size_t rowbase = (size_t)(1024 + 128*ch - qc - 127);
            for (int u = tid; u < 2048; u += 256){
                int row = u>>3, cb = u&7;
                cp16(buf + swz((uint32_t)(row*128 + cb*16)), pf + (rowbase + row)*DD + h*DKK + cb*8);
            }
        } else {              // K (16KB) + V (16KB)
            size_t rowbase = (size_t)(b*SS_ + 128*ch);
            for (int u = tid; u < 1024; u += 256){
                int row = u>>3, cb = u&7;
                uint32_t off = swz((uint32_t)(row*128 + cb*16));
                cp16(buf + off,         kf + (rowbase + row)*DD + h*DKK + cb*8);
                cp16(buf + 16384 + off, vf + (rowbase + row)*DD + h*DKK + cb*8);
            }
        }
    };

    // group 0: resident Q tiles + stage 0
    for (int u = tid; u < 1024; u += 256) {
        int row = u>>3, cb = u&7;
        uint32_t off = swz((uint32_t)(row*128 + cb*16));
        size_t g = (size_t)(b*SS_ + qc + row)*DD + h*DKK + cb*8;
        cp16(sb + off,         quf + g);
        cp16(sb + 16384 + off, qvf + g);
    }
    issue(0); CP_COMMIT();
    issue(1); CP_COMMIT();

    // rel_shift wrap value: bd(0,1023) = qv[b,h,1]·p[0]
    float wrapv = 0.f;
    if (qc == 0 && wid == 0) {
        #pragma unroll
        for (int d = 0; d < DKK; ++d)
            wrapv += __half2float(qvf[(size_t)(b*SS_+1)*DD + h*DKK + d])
                   * __half2float(pf[h*DKK + d]);
    }

    float m0 = -1e30f, m1 = -1e30f, l0 = 0.f, l1 = 0.f;
    float accO[8][4];
    #pragma unroll
    for (int i=0;i<8;++i)
        #pragma unroll
        for (int j=0;j<4;++j) accO[i][j]=0.f;

    for (int st = 0; st < 16; ++st) {
        CP_WAIT1();
        __syncthreads();
        const int ch = st >> 1;
        const uint32_t op = sb + 32768 + (uint32_t)(st&1)*32768;

        if ((st & 1) == 0) {
            // BD banded GEMM over 256-row P band; scatter j = t + i - 127
            float bdacc[9][2][4];
            #pragma unroll
            for (int gi=0;gi<9;++gi)
                #pragma unroll
                for (int q2=0;q2<2;++q2)
                    #pragma unroll
                    for (int e=0;e<4;++e) bdacc[gi][q2][e]=0.f;
            #pragma unroll
            for (int ks = 0; ks < 4; ++ks) {
                int k0 = ks*16;
                uint32_t aF[4];
                ldsm4(aF, a_addr(sb + 16384, wq, k0, lane));
                #pragma unroll
                for (int gi = 0; gi < 9; ++gi) {
                    int n0 = (7 - wid + gi)*16;
                    uint32_t bF[4];
                    ldsm4(bF, b_addr(op, n0, k0, lane));
                    mma16816(bdacc[gi][0], aF, &bF[0]);
                    mma16816(bdacc[gi][1], aF, &bF[2]);
                }
            }
            #pragma unroll
            for (int gi = 0; gi < 9; ++gi) {
                int g16 = 7 - wid + gi;
                #pragma unroll
                for (int q2 = 0; q2 < 2; ++q2) {
                    int t0 = g16*16 + q2*8 + c;
                    int i0 = wq + r, i1 = i0 + 8;
                    int j;
                    j = t0     + i0 - 127; if (j>=0 && j<128) bd[i0*132+j] = bdacc[gi][q2][0];
                    j = t0 + 1 + i0 - 127; if (j>=0 && j<128) bd[i0*132+j] = bdacc[gi][q2][1];
                    j = t0     + i1 - 127; if (j>=0 && j<128) bd[i1*132+j] = bdacc[gi][q2][2];
                    j = t0 + 1 + i1 - 127; if (j>=0 && j<128) bd[i1*132+j] = bdacc[gi][q2][3];
                }
            }
        } else {
            // AC GEMM (K at op) + online softmax + PV GEMM (V at op+16384)
            const int kk0 = ch * 128;
            float s[16][4];
            #pragma unroll
            for (int nt=0;nt<16;++nt)
                #pragma unroll
                for (int e=0;e<4;++e) s[nt][e]=0.f;
            #pragma unroll
            for (int ks = 0; ks < 4; ++ks) {
                int k0 = ks*16;
                uint32_t aF[4];
                ldsm4(aF, a_addr(sb, wq, k0, lane));
                #pragma unroll
                for (int g16 = 0; g16 < 8; ++g16) {
                    uint32_t bF[4];
                    ldsm4(bF, b_addr(op, g16*16, k0, lane));
                    mma16816(s[2*g16],   aF, &bF[0]);
                    mma16816(s[2*g16+1], aF, &bF[2]);
                }
            }
            const int i0 = wq + r, i1 = i0 + 8;
            float mc0 = -1e30f, mc1 = -1e30f;
            #pragma unroll
            for (int nt = 0; nt < 16; ++nt) {
                int jc = nt*8 + c;
                float v0 = s[nt][0] + bd[i0*132 + jc];
                float v1 = s[nt][1] + bd[i0*132 + jc + 1];
                float v2 = s[nt][2] + bd[i1*132 + jc];
                float v3 = s[nt][3] + bd[i1*132 + jc + 1];
                if (qc == 0 && ch == 7 && nt == 15 && wid == 0 && lane == 3) v1 += wrapv;
                v0 *= 0.125f; v1 *= 0.125f; v2 *= 0.125f; v3 *= 0.125f;
                const unsigned char* mr0 = mask + (size_t)b*SS_*SS_ + (size_t)(qc+i0)*SS_ + kk0 + jc;
                const unsigned char* mr1 = mask + (size_t)b*SS_*SS_ + (size_t)(qc+i1)*SS_ + kk0 + jc;
                uchar2 mq0 = *(const uchar2*)mr0;
                uchar2 mq1 = *(const uchar2*)mr1;
                if (mq0.x) v0 = -10000.f;
                if (mq0.y) v1 = -10000.f;
                if (mq1.x) v2 = -10000.f;
                if (mq1.y) v3 = -10000.f;
                s[nt][0]=v0; s[nt][1]=v1; s[nt][2]=v2; s[nt][3]=v3;
                mc0 = fmaxf(mc0, fmaxf(v0, v1));
                mc1 = fmaxf(mc1, fmaxf(v2, v3));
            }
            mc0 = fmaxf(mc0, __shfl_xor_sync(0xffffffffu, mc0, 1));
            mc0 = fmaxf(mc0, __shfl_xor_sync(0xffffffffu, mc0, 2));
            mc1 = fmaxf(mc1, __shfl_xor_sync(0xffffffffu, mc1, 1));
            mc1 = fmaxf(mc1, __shfl_xor_sync(0xffffffffu, mc1, 2));
            float mn0 = fmaxf(m0, mc0), mn1 = fmaxf(m1, mc1);
            float cor0 = __expf(m0 - mn0), cor1 = __expf(m1 - mn1);
            m0 = mn0; m1 = mn1;
            float ls0 = 0.f, ls1 = 0.f;
            uint32_t paF[8][4];
            #pragma unroll
            for (int kt = 0; kt < 8; ++kt) {
                float p00 = __expf(s[2*kt][0]   - m0), p01 = __expf(s[2*kt][1]   - m0);
                float p02 = __expf(s[2*kt][2]   - m1), p03 = __expf(s[2*kt][3]   - m1);
                float p10 = __expf(s[2*kt+1][0] - m0), p11 = __expf(s[2*kt+1][1] - m0);
                float p12 = __expf(s[2*kt+1][2] - m1), p13 = __expf(s[2*kt+1][3] - m1);
                ls0 += p00 + p01 + p10 + p11;
                ls1 += p02 + p03 + p12 + p13;
                paF[kt][0] = packh(p00, p01);
                paF[kt][1] = packh(p02, p03);
                paF[kt][2] = packh(p10, p11);
                paF[kt][3] = packh(p12, p13);
            }
            ls0 += __shfl_xor_sync(0xffffffffu, ls0, 1);
            ls0 += __shfl_xor_sync(0xffffffffu, ls0, 2);
            ls1 += __shfl_xor_sync(0xffffffffu, ls1, 1);
            ls1 += __shfl_xor_sync(0xffffffffu, ls1, 2);
            l0 = l0*cor0 + ls0;
            l1 = l1*cor1 + ls1;
            #pragma unroll
            for (int dn = 0; dn < 8; ++dn) {
                accO[dn][0]*=cor0; accO[dn][1]*=cor0; accO[dn][2]*=cor1; accO[dn][3]*=cor1;
            }
            const uint32_t opv = op + 16384;
            #pragma unroll
            for (int kt = 0; kt < 8; ++kt) {
                #pragma unroll
                for (int dp = 0; dp < 4; ++dp) {
                    uint32_t bF[4];
                    ldsm4t(bF, v_addr(opv, kt*16, dp*16, lane));
                    mma16816(accO[2*dp],   paF[kt], &bF[0]);
                    mma16816(accO[2*dp+1], paF[kt], &bF[2]);
                }
            }
        }

        __syncthreads();
        if (st + 2 < 16) issue(st + 2);
        CP_COMMIT();
    }

    float inv0 = 1.f / l0, inv1 = 1.f / l1;
    const int q0 = qc + wq + r, q1 = q0 + 8;
    #pragma unroll
    for (int dn = 0; dn < 8; ++dn) {
        int d = dn*8 + c;
        *(uint32_t*)(tf + (size_t)(b*SS_+q0)*DD + h*DKK + d) = packh(accO[dn][0]*inv0, accO[dn][1]*inv0);
        *(uint32_t*)(tf + (size_t)(b*SS_+q1)*DD + h*DKK + d) = packh(accO[dn][2]*inv1, accO[dn][3]*inv1);
    }
}

// ---------------- launch ----------------
extern "C" void kernel_launch(void* const* d_in, const int* in_sizes, int n_in,
                              void* d_out, int out_size) {
    const float* inputs        = (const float*)d_in[0];
    const unsigned char* amask = (const unsigned char*)d_in[1];
    const float* Wq = (const float*)d_in[2];
    const float* bq = (const float*)d_in[3];
    const float* Wk = (const float*)d_in[4];
    const float* bk = (const float*)d_in[5];
    const float* Wv = (const float*)d_in[6];
    const float* bv = (const float*)d_in[7];
    const float* Wo = (const float*)d_in[8];
    const float* bo = (const float*)d_in[9];
    const float* Wp = (const float*)d_in[10];
    const float* pu = (const float*)d_in[11];
    const float* pv = (const float*)d_in[12];
    const float* gamma = (const float*)d_in[13];
    const float* beta  = (const float*)d_in[14];
    float* out = (float*)d_out;

    half_t *xf,*pef,*wf,*quf,*qvf,*kf,*vf,*pf,*tf;
    cudaGetSymbolAddress((void**)&xf, g_xf);
    cudaGetSymbolAddress((void**)&pef, g_pef);
    cudaGetSymbolAddress((void**)&wf, g_wf);
    cudaGetSymbolAddress((void**)&quf, g_quf);
    cudaGetSymbolAddress((void**)&qvf, g_qvf);
    cudaGetSymbolAddress((void**)&kf, g_kf);
    cudaGetSymbolAddress((void**)&vf, g_vf);
    cudaGetSymbolAddress((void**)&pf, g_pf);
    cudaGetSymbolAddress((void**)&tf, g_tf);

    cudaFuncSetAttribute(proj_all,   cudaFuncAttributeMaxDynamicSharedMemorySize, 65536);
    cudaFuncSetAttribute(gemm_out,   cudaFuncAttributeMaxDynamicSharedMemorySize, 65536);
    cudaFuncSetAttribute(attn_fused, cudaFuncAttributeMaxDynamicSharedMemorySize, 165888);

    // LN + PE + weight converts, one launch
    prep_kernel<<<5376, 256>>>(inputs, gamma, beta, Wq, Wk, Wv, Wo, Wp, xf, pef, wf);

    // all projections (QKV fused N=1536 + P), one launch
    proj_all<<<448, 256, 65536>>>(xf, pef, wf, bq, bk, bv, pu, pv, quf, qvf, kf, vf, pf);

    // fused attention
    attn_fused<<<dim3(8, BB*HH), 256, 165888>>>(quf, qvf, kf, vf, pf, amask, tf);

    // output projection (fp32 out)
    gemm_out<<<dim3(4,32), 256, 65536>>>(tf, wf+3*(size_t)DD*DD, bo, out);

    (void)in_sizes; (void)n_in; (void)out_size;
}

// round 9
// speedup vs baseline: 9.2909x; 1.0308x over previous
#include <cuda_runtime.h>
#include <cuda_fp16.h>
#include <math.h>
#include <string.h>
#include <stdint.h>

#define BB 4
#define SS_ 1024
#define DD 512
#define HH 8
#define DKK 64
#define PP_ 2047
#define PPAD 2048
#define PBAND 2304

typedef __half half_t;

// ---------------- scratch (zero-initialized device globals) ----------------
__device__ half_t g_xf[BB*SS_*DD];
__device__ half_t g_pef[PPAD*DD];
__device__ half_t g_wf[5*DD*DD];
__device__ half_t g_quf[BB*SS_*DD], g_qvf[BB*SS_*DD];
__device__ half_t g_kf[BB*SS_*DD],  g_vf[BB*SS_*DD];
__device__ half_t g_pf[(size_t)PBAND*DD];   // rows >= 2047 stay zero
__device__ half_t g_tf[BB*SS_*DD];

// ---------------- helpers ----------------
__device__ __forceinline__ void mma16816(float* d, const uint32_t* a, const uint32_t* b){
    asm volatile("mma.sync.aligned.m16n8k16.row.col.f32.f16.f16.f32 "
        "{%0,%1,%2,%3}, {%4,%5,%6,%7}, {%8,%9}, {%0,%1,%2,%3};"
        : "+f"(d[0]),"+f"(d[1]),"+f"(d[2]),"+f"(d[3])
        : "r"(a[0]),"r"(a[1]),"r"(a[2]),"r"(a[3]), "r"(b[0]),"r"(b[1]));
}
__device__ __forceinline__ void ldsm4(uint32_t* r, uint32_t addr){
    asm volatile("ldmatrix.sync.aligned.m8n8.x4.shared.b16 {%0,%1,%2,%3}, [%4];"
        :"=r"(r[0]),"=r"(r[1]),"=r"(r[2]),"=r"(r[3]):"r"(addr));
}
__device__ __forceinline__ void ldsm4t(uint32_t* r, uint32_t addr){
    asm volatile("ldmatrix.sync.aligned.m8n8.x4.trans.shared.b16 {%0,%1,%2,%3}, [%4];"
        :"=r"(r[0]),"=r"(r[1]),"=r"(r[2]),"=r"(r[3]):"r"(addr));
}
__device__ __forceinline__ uint32_t smem_u32(const void* p){
    uint32_t a; asm("{ .reg .u64 t; cvta.to.shared.u64 t, %1; cvt.u32.u64 %0, t; }":"=r"(a):"l"(p)); return a;
}
__device__ __forceinline__ void cp16(uint32_t dst, const void* src){
    asm volatile("cp.async.cg.shared.global [%0], [%1], 16;"
        :: "r"(dst), "l"(__cvta_generic_to_global(src)));
}
#define CP_COMMIT() asm volatile("cp.async.commit_group;" ::: "memory")
#define CP_WAIT1()  asm volatile("cp.async.wait_group 1;" ::: "memory")
static __device__ __forceinline__ uint32_t swz(uint32_t o){ return o ^ ((o>>3)&0x70); }
__device__ __forceinline__ uint32_t a_addr(uint32_t base, int m16, int k0, int lane){
    int g = lane>>3, r = lane&7;
    int row = m16 + r + (g&1)*8;
    uint32_t o = (uint32_t)(row*128 + (k0 + (g>>1)*8)*2);
    return base + swz(o);
}
__device__ __forceinline__ uint32_t b_addr(uint32_t base, int n0, int k0, int lane){
    int g = lane>>3, r = lane&7;
    int row = n0 + r + (g>>1)*8;
    uint32_t o = (uint32_t)(row*128 + (k0 + (g&1)*8)*2);
    return base + swz(o);
}
__device__ __forceinline__ uint32_t v_addr(uint32_t base, int k0, int d0, int lane){
    int g = lane>>3, r = lane&7;
    int row = k0 + r + (g&1)*8;
    uint32_t o = (uint32_t)(row*128 + (d0 + (g>>1)*8)*2);
    return base + swz(o);
}
__device__ __forceinline__ uint32_t packh(float x, float y){
    __half2 h = __floats2half2_rn(x, y);
    uint32_t u; memcpy(&u, &h, 4); return u;
}

// ================= prep: LN + PE + weight converts, one launch =================
__global__ void prep_kernel(const float* __restrict__ x, const float* __restrict__ gamma,
                            const float* __restrict__ beta,
                            const float* __restrict__ Wq, const float* __restrict__ Wk,
                            const float* __restrict__ Wv, const float* __restrict__ Wo,
                            const float* __restrict__ Wp,
                            half_t* __restrict__ xf, half_t* __restrict__ pef,
                            half_t* __restrict__ wf) {
    __shared__ float red[8];
    const int blk = blockIdx.x, tid = threadIdx.x;
    if (blk < 2048) {
        int halfid = tid >> 7, t = tid & 127;
        int row = blk*2 + halfid;
        float4 v = ((const float4*)(x + (size_t)row*DD))[t];
        float s = v.x+v.y+v.z+v.w;
        #pragma unroll
        for (int o=16;o;o>>=1) s += __shfl_xor_sync(0xffffffffu,s,o);
        if ((t&31)==0) red[tid>>5]=s;
        __syncthreads();
        float mu=(red[halfid*4]+red[halfid*4+1]+red[halfid*4+2]+red[halfid*4+3])*(1.0f/DD);
        float dx=v.x-mu,dy=v.y-mu,dz=v.z-mu,dw=v.w-mu;
        float ss=dx*dx+dy*dy+dz*dz+dw*dw;
        #pragma unroll
        for (int o=16;o;o>>=1) ss += __shfl_xor_sync(0xffffffffu,ss,o);
        __syncthreads();
        if ((t&31)==0) red[tid>>5]=ss;
        __syncthreads();
        float rstd=rsqrtf((red[halfid*4]+red[halfid*4+1]+red[halfid*4+2]+red[halfid*4+3])*(1.0f/DD)+1e-5f);
        float4 g=((const float4*)gamma)[t], be=((const float4*)beta)[t];
        uint2 o2;
        o2.x = packh(dx*rstd*g.x+be.x, dy*rstd*g.y+be.y);
        o2.y = packh(dz*rstd*g.z+be.z, dw*rstd*g.w+be.w);
        *(uint2*)(xf + (size_t)row*DD + 4*t) = o2;
    } else if (blk < 4096) {
        int j = blk - 2048;
        uint32_t u = 0;
        if (j < PP_) {
            float pos = (float)(j - (SS_ - 1));
            const float kconst = -0.01798894603901598415f;
            float div = expf((float)(2*tid) * kconst);
            float sa, ca; sincosf(pos * div, &sa, &ca);
            u = packh(sa, ca);
        }
        *(uint32_t*)(pef + (size_t)j*DD + 2*tid) = u;
    } else {
        int i = (blk - 4096)*256 + tid;
        int widx = i >> 16, j = i & 65535;
        const float* src = (widx==0)?Wq:(widx==1)?Wk:(widx==2)?Wv:(widx==3)?Wo:Wp;
        float4 v = ((const float4*)src)[j];
        uint2 o2; o2.x = packh(v.x, v.y); o2.y = packh(v.z, v.w);
        ((uint2*)(wf + (size_t)widx*DD*DD))[j] = o2;
    }
}

// ================= fused projections: QKV (N=1536) + P, one launch =================
__global__ __launch_bounds__(256,2) void proj_all(
    const half_t* __restrict__ xf, const half_t* __restrict__ pef,
    const half_t* __restrict__ wf,
    const float* __restrict__ bq, const float* __restrict__ bk, const float* __restrict__ bv,
    const float* __restrict__ pu, const float* __restrict__ pv,
    half_t* __restrict__ quf, half_t* __restrict__ qvf,
    half_t* __restrict__ kf, half_t* __restrict__ vf, half_t* __restrict__ pf)
{
    extern __shared__ char sm[];
    const int tid = threadIdx.x, lane = tid & 31, wid = tid >> 5;
    const uint32_t sb = smem_u32(sm);
    const int m0w = (wid>>2)*64, n0w = (wid&3)*32;
    const int cta = blockIdx.x;
    const half_t *A, *B;
    int bm, bn, mode;
    if (cta < 384) {
        int bx = cta % 12, by = cta / 12;
        bm = by*128; bn = bx*128;
        A = xf; B = wf + (size_t)bn*DD;
        mode = bn >> 9;
    } else {
        int c2 = cta - 384;
        int bx = c2 & 3, by = c2 >> 2;
        bm = by*128; bn = bx*128;
        A = pef; B = wf + 4*(size_t)DD*DD + (size_t)bn*DD;
        mode = 3;
    }

    auto issueg = [&](int kc){
        uint32_t base = sb + (uint32_t)(kc&1)*32768;
        for (int u = tid; u < 1024; u += 256) {
            int row = u>>3, cb = u&7;
            uint32_t off = swz((uint32_t)(row*128 + cb*16));
            cp16(base + off,         A + (size_t)(bm+row)*DD + kc*64 + cb*8);
            cp16(base + 16384 + off, B + (size_t)row*DD + kc*64 + cb*8);
        }
    };

    float acc[4][4][4];
    #pragma unroll
    for (int a=0;a<4;++a)
        #pragma unroll
        for (int b2=0;b2<4;++b2)
            #pragma unroll
            for (int c2=0;c2<4;++c2) acc[a][b2][c2]=0.f;

    issueg(0); CP_COMMIT();
    issueg(1); CP_COMMIT();

    for (int kc = 0; kc < 8; ++kc) {
        CP_WAIT1();
        __syncthreads();
        uint32_t base = sb + (uint32_t)(kc&1)*32768;
        #pragma unroll
        for (int ks = 0; ks < 4; ++ks) {
            int k0 = ks*16;
            uint32_t aF[4][4], bF[2][4];
            #pragma unroll
            for (int mt=0; mt<4; ++mt) ldsm4(aF[mt], a_addr(base, m0w+mt*16, k0, lane));
            #pragma unroll
            for (int p=0; p<2; ++p)   ldsm4(bF[p], b_addr(base+16384, n0w+p*16, k0, lane));
            #pragma unroll
            for (int mt=0; mt<4; ++mt)
                #pragma unroll
                for (int nt=0; nt<4; ++nt)
                    mma16816(acc[mt][nt], aF[mt], &bF[nt>>1][(nt&1)*2]);
        }
        __syncthreads();
        if (kc + 2 < 8) issueg(kc + 2);
        CP_COMMIT();
    }
    const int r = lane>>2, c = (lane&3)*2;
    const int nbase = bn & 511;
    #pragma unroll
    for (int mt=0; mt<4; ++mt)
        #pragma unroll
        for (int nt=0; nt<4; ++nt) {
            int nl = nbase + n0w + nt*8 + c;
            float b0 = 0.f, b1 = 0.f;
            if (mode == 0)      { b0 = bq[nl]; b1 = bq[nl+1]; }
            else if (mode == 1) { b0 = bk[nl]; b1 = bk[nl+1]; }
            else if (mode == 2) { b0 = bv[nl]; b1 = bv[nl+1]; }
            #pragma unroll
            for (int half_=0; half_<2; ++half_) {
                int m_ = bm + m0w + mt*16 + r + half_*8;
                float v0 = acc[mt][nt][half_*2+0] + b0;
                float v1 = acc[mt][nt][half_*2+1] + b1;
                if (mode == 0) {
                    *(uint32_t*)(quf + (size_t)m_*DD + nl) = packh(v0 + pu[nl], v1 + pu[nl+1]);
                    *(uint32_t*)(qvf + (size_t)m_*DD + nl) = packh(v0 + pv[nl], v1 + pv[nl+1]);
                } else if (mode == 1) {
                    *(uint32_t*)(kf + (size_t)m_*DD + nl) = packh(v0, v1);
                } else if (mode == 2) {
                    *(uint32_t*)(vf + (size_t)m_*DD + nl) = packh(v0, v1);
                } else {
                    *(uint32_t*)(pf + (size_t)m_*DD + nl) = packh(v0, v1);
                }
            }
        }
}

// ================= out projection (fp16 MMA, fp32 out), 2 CTA/SM =================
__global__ __launch_bounds__(256,2) void gemm_out(
    const half_t* __restrict__ A, const half_t* __restrict__ Bw,
    const float* __restrict__ bias, float* __restrict__ O32)
{
    extern __shared__ char sm[];
    const int tid = threadIdx.x, lane = tid & 31, wid = tid >> 5;
    const int bm = blockIdx.y * 128, bn = blockIdx.x * 128;
    const uint32_t sb = smem_u32(sm);
    const int m0w = (wid>>2)*64, n0w = (wid&3)*32;

    auto issueg = [&](int kc){
        uint32_t base = sb + (uint32_t)(kc&1)*32768;
        for (int u = tid; u < 1024; u += 256) {
            int row = u>>3, cb = u&7;
            uint32_t off = swz((uint32_t)(row*128 + cb*16));
            cp16(base + off,         A  + (size_t)(bm+row)*DD + kc*64 + cb*8);
            cp16(base + 16384 + off, Bw + (size_t)(bn+row)*DD + kc*64 + cb*8);
        }
    };

    float acc[4][4][4];
    #pragma unroll
    for (int a=0;a<4;++a)
        #pragma unroll
        for (int b2=0;b2<4;++b2)
            #pragma unroll
            for (int c2=0;c2<4;++c2) acc[a][b2][c2]=0.f;

    issueg(0); CP_COMMIT();
    issueg(1); CP_COMMIT();

    for (int kc = 0; kc < 8; ++kc) {
        CP_WAIT1();
        __syncthreads();
        uint32_t base = sb + (uint32_t)(kc&1)*32768;
        #pragma unroll
        for (int ks = 0; ks < 4; ++ks) {
            int k0 = ks*16;
            uint32_t aF[4][4], bF[2][4];
            #pragma unroll
            for (int mt=0; mt<4; ++mt) ldsm4(aF[mt], a_addr(base, m0w+mt*16, k0, lane));
            #pragma unroll
            for (int p=0; p<2; ++p)   ldsm4(bF[p], b_addr(base+16384, n0w+p*16, k0, lane));
            #pragma unroll
            for (int mt=0; mt<4; ++mt)
                #pragma unroll
                for (int nt=0; nt<4; ++nt)
                    mma16816(acc[mt][nt], aF[mt], &bF[nt>>1][(nt&1)*2]);
        }
        __syncthreads();
        if (kc + 2 < 8) issueg(kc + 2);
        CP_COMMIT();
    }
    const int r = lane>>2, c = (lane&3)*2;
    #pragma unroll
    for (int mt=0; mt<4; ++mt)
        #pragma unroll
        for (int nt=0; nt<4; ++nt) {
            int n_ = bn + n0w + nt*8 + c;
            float b0 = bias[n_], b1 = bias[n_+1];
            #pragma unroll
            for (int half_=0; half_<2; ++half_) {
                int m_ = bm + m0w + mt*16 + r + half_*8;
                *(float2*)(O32 + (size_t)m_*DD + n_) =
                    make_float2(acc[mt][nt][half_*2+0] + b0, acc[mt][nt][half_*2+1] + b1);
            }
        }
}

// ================= fused attention: 64-row q-tiles, 128 thr, 2 CTA/SM =================
// smem: Qu 8K | Qv 8K @8192 | P buf 24K @16384 | K 16K @40960 | V 16K @57344 | bd 33K @73728
// stages: even = P band (192 rows), odd = K+V. Buffers fixed by parity.
#define AQ_V   8192
#define AP_BUF 16384
#define AK_BUF 40960
#define AV_BUF 57344
#define ABD    73728
#define ASMEM  107520
__global__ __launch_bounds__(128,2) void attn_fused(
    const half_t* __restrict__ quf, const half_t* __restrict__ qvf,
    const half_t* __restrict__ kf,  const half_t* __restrict__ vf,
    const half_t* __restrict__ pf,
    const unsigned char* __restrict__ mask,
    half_t* __restrict__ tf)
{
    extern __shared__ char sm[];
    const int tid = threadIdx.x, lane = tid & 31, wid = tid >> 5;   // 4 warps
    const int bh = blockIdx.y, b = bh >> 3, h = bh & 7;
    const int qc = blockIdx.x * 64;
    const uint32_t sb = smem_u32(sm);
    float* bd = (float*)(sm + ABD);     // [64][132] fp32
    const int wq = wid * 16;
    const int r = lane>>2, c = (lane&3)*2;

    auto issue = [&](int st){
        int ch = st >> 1;
        if ((st & 1) == 0) {  // P band: 192 rows -> 24KB
            size_t rowbase = (size_t)(1024 + 128*ch - qc - 63);
            for (int u = tid; u < 1536; u += 128){
                int row = u>>3, cb = u&7;
                cp16(sb + AP_BUF + swz((uint32_t)(row*128 + cb*16)),
                     pf + (rowbase + row)*DD + h*DKK + cb*8);
            }
        } else {              // K + V: 128 rows each
            size_t rowbase = (size_t)(b*SS_ + 128*ch);
            for (int u = tid; u < 1024; u += 128){
                int row = u>>3, cb = u&7;
                uint32_t off = swz((uint32_t)(row*128 + cb*16));
                cp16(sb + AK_BUF + off, kf + (rowbase + row)*DD + h*DKK + cb*8);
                cp16(sb + AV_BUF + off, vf + (rowbase + row)*DD + h*DKK + cb*8);
            }
        }
    };

    // group 0: resident Q tiles (64 rows each) + stage 0
    for (int u = tid; u < 512; u += 128) {
        int row = u>>3, cb = u&7;
        uint32_t off = swz((uint32_t)(row*128 + cb*16));
        size_t g = (size_t)(b*SS_ + qc + row)*DD + h*DKK + cb*8;
        cp16(sb + off,        quf + g);
        cp16(sb + AQ_V + off, qvf + g);
    }
    issue(0); CP_COMMIT();
    issue(1); CP_COMMIT();

    // rel_shift wrap value: bd(0,1023) = qv[b,h,1]·p[0]
    float wrapv = 0.f;
    if (qc == 0 && wid == 0) {
        #pragma unroll
        for (int d = 0; d < DKK; ++d)
            wrapv += __half2float(qvf[(size_t)(b*SS_+1)*DD + h*DKK + d])
                   * __half2float(pf[h*DKK + d]);
    }

    float m0 = -1e30f, m1 = -1e30f, l0 = 0.f, l1 = 0.f;
    float accO[8][4];
    #pragma unroll
    for (int i=0;i<8;++i)
        #pragma unroll
        for (int j=0;j<4;++j) accO[i][j]=0.f;

    for (int st = 0; st < 16; ++st) {
        CP_WAIT1();
        __syncthreads();
        const int ch = st >> 1;

        if ((st & 1) == 0) {
            // BD banded GEMM over 192-row P band; scatter j = t + i - 63
            float bdacc[9][2][4];
            #pragma unroll
            for (int gi=0;gi<9;++gi)
                #pragma unroll
                for (int q2=0;q2<2;++q2)
                    #pragma unroll
                    for (int e=0;e<4;++e) bdacc[gi][q2][e]=0.f;
            #pragma unroll
            for (int ks = 0; ks < 4; ++ks) {
                int k0 = ks*16;
                uint32_t aF[4];
                ldsm4(aF, a_addr(sb + AQ_V, wq, k0, lane));
                #pragma unroll
                for (int gi = 0; gi < 9; ++gi) {
                    int n0 = (3 - wid + gi)*16;      // 0..176, rows < 192
                    uint32_t bF[4];
                    ldsm4(bF, b_addr(sb + AP_BUF, n0, k0, lane));
                    mma16816(bdacc[gi][0], aF, &bF[0]);
                    mma16816(bdacc[gi][1], aF, &bF[2]);
                }
            }
            #pragma unroll
            for (int gi = 0; gi < 9; ++gi) {
                int g16 = 3 - wid + gi;
                #pragma unroll
                for (int q2 = 0; q2 < 2; ++q2) {
                    int t0 = g16*16 + q2*8 + c;
                    int i0 = wq + r, i1 = i0 + 8;
                    int j;
                    j = t0     + i0 - 63; if (j>=0 && j<128) bd[i0*132+j] = bdacc[gi][q2][0];
                    j = t0 + 1 + i0 - 63; if (j>=0 && j<128) bd[i0*132+j] = bdacc[gi][q2][1];
                    j = t0     + i1 - 63; if (j>=0 && j<128) bd[i1*132+j] = bdacc[gi][q2][2];
                    j = t0 + 1 + i1 - 63; if (j>=0 && j<128) bd[i1*132+j] = bdacc[gi][q2][3];
                }
            }
        } else {
            const int kk0 = ch * 128;
            float s[16][4];
            #pragma unroll
            for (int nt=0;nt<16;++nt)
                #pragma unroll
                for (int e=0;e<4;++e) s[nt][e]=0.f;
            #pragma unroll
            for (int ks = 0; ks < 4; ++ks) {
                int k0 = ks*16;
                uint32_t aF[4];
                ldsm4(aF, a_addr(sb, wq, k0, lane));
                #pragma unroll
                for (int g16 = 0; g16 < 8; ++g16) {
                    uint32_t bF[4];
                    ldsm4(bF, b_addr(sb + AK_BUF, g16*16, k0, lane));
                    mma16816(s[2*g16],   aF, &bF[0]);
                    mma16816(s[2*g16+1], aF, &bF[2]);
                }
            }
            const int i0 = wq + r, i1 = i0 + 8;
            float mc0 = -1e30f, mc1 = -1e30f;
            #pragma unroll
            for (int nt = 0; nt < 16; ++nt) {
                int jc = nt*8 + c;
                float v0 = s[nt][0] + bd[i0*132 + jc];
                float v1 = s[nt][1] + bd[i0*132 + jc + 1];
                float v2 = s[nt][2] + bd[i1*132 + jc];
                float v3 = s[nt][3] + bd[i1*132 + jc + 1];
                if (qc == 0 && ch == 7 && nt == 15 && wid == 0 && lane == 3) v1 += wrapv;
                v0 *= 0.125f; v1 *= 0.125f; v2 *= 0.125f; v3 *= 0.125f;
                const unsigned char* mr0 = mask + (size_t)b*SS_*SS_ + (size_t)(qc+i0)*SS_ + kk0 + jc;
                const unsigned char* mr1 = mask + (size_t)b*SS_*SS_ + (size_t)(qc+i1)*SS_ + kk0 + jc;
                uchar2 mq0 = *(const uchar2*)mr0;
                uchar2 mq1 = *(const uchar2*)mr1;
                if (mq0.x) v0 = -10000.f;
                if (mq0.y) v1 = -10000.f;
                if (mq1.x) v2 = -10000.f;
                if (mq1.y) v3 = -10000.f;
                s[nt][0]=v0; s[nt][1]=v1; s[nt][2]=v2; s[nt][3]=v3;
                mc0 = fmaxf(mc0, fmaxf(v0, v1));
                mc1 = fmaxf(mc1, fmaxf(v2, v3));
            }
            mc0 = fmaxf(mc0, __shfl_xor_sync(0xffffffffu, mc0, 1));
            mc0 = fmaxf(mc0, __shfl_xor_sync(0xffffffffu, mc0, 2));
            mc1 = fmaxf(mc1, __shfl_xor_sync(0xffffffffu, mc1, 1));
            mc1 = fmaxf(mc1, __shfl_xor_sync(0xffffffffu, mc1, 2));
            float mn0 = fmaxf(m0, mc0), mn1 = fmaxf(m1, mc1);
            float cor0 = __expf(m0 - mn0), cor1 = __expf(m1 - mn1);
            m0 = mn0; m1 = mn1;
            float ls0 = 0.f, ls1 = 0.f;
            uint32_t paF[8][4];
            #pragma unroll
            for (int kt = 0; kt < 8; ++kt) {
                float p00 = __expf(s[2*kt][0]   - m0), p01 = __expf(s[2*kt][1]   - m0);
                float p02 = __expf(s[2*kt][2]   - m1), p03 = __expf(s[2*kt][3]   - m1);
                float p10 = __expf(s[2*kt+1][0] - m0), p11 = __expf(s[2*kt+1][1] - m0);
                float p12 = __expf(s[2*kt+1][2] - m1), p13 = __expf(s[2*kt+1][3] - m1);
                ls0 += p00 + p01 + p10 + p11;
                ls1 += p02 + p03 + p12 + p13;
                paF[kt][0] = packh(p00, p01);
                paF[kt][1] = packh(p02, p03);
                paF[kt][2] = packh(p10, p11);
                paF[kt][3] = packh(p12, p13);
            }
            ls0 += __shfl_xor_sync(0xffffffffu, ls0, 1);
            ls0 += __shfl_xor_sync(0xffffffffu, ls0, 2);
            ls1 += __shfl_xor_sync(0xffffffffu, ls1, 1);
            ls1 += __shfl_xor_sync(0xffffffffu, ls1, 2);
            l0 = l0*cor0 + ls0;
            l1 = l1*cor1 + ls1;
            #pragma unroll
            for (int dn = 0; dn < 8; ++dn) {
                accO[dn][0]*=cor0; accO[dn][1]*=cor0; accO[dn][2]*=cor1; accO[dn][3]*=cor1;
            }
            #pragma unroll
            for (int kt = 0; kt < 8; ++kt) {
                #pragma unroll
                for (int dp = 0; dp < 4; ++dp) {
                    uint32_t bF[4];
                    ldsm4t(bF, v_addr(sb + AV_BUF, kt*16, dp*16, lane));
                    mma16816(accO[2*dp],   paF[kt], &bF[0]);
                    mma16816(accO[2*dp+1], paF[kt], &bF[2]);
                }
            }
        }

        __syncthreads();
        if (st + 2 < 16) issue(st + 2);
        CP_COMMIT();
    }

    float inv0 = 1.f / l0, inv1 = 1.f / l1;
    const int q0 = qc + wq + r, q1 = q0 + 8;
    #pragma unroll
    for (int dn = 0; dn < 8; ++dn) {
        int d = dn*8 + c;
        *(uint32_t*)(tf + (size_t)(b*SS_+q0)*DD + h*DKK + d) = packh(accO[dn][0]*inv0, accO[dn][1]*inv0);
        *(uint32_t*)(tf + (size_t)(b*SS_+q1)*DD + h*DKK + d) = packh(accO[dn][2]*inv1, accO[dn][3]*inv1);
    }
}

// ---------------- launch ----------------
extern "C" void kernel_launch(void* const* d_in, const int* in_sizes, int n_in,
                              void* d_out, int out_size) {
    const float* inputs        = (const float*)d_in[0];
    const unsigned char* amask = (const unsigned char*)d_in[1];
    const float* Wq = (const float*)d_in[2];
    const float* bq = (const float*)d_in[3];
    const float* Wk = (const float*)d_in[4];
    const float* bk = (const float*)d_in[5];
    const float* Wv = (const float*)d_in[6];
    const float* bv = (const float*)d_in[7];
    const float* Wo = (const float*)d_in[8];
    const float* bo = (const float*)d_in[9];
    const float* Wp = (const float*)d_in[10];
    const float* pu = (const float*)d_in[11];
    const float* pv = (const float*)d_in[12];
    const float* gamma = (const float*)d_in[13];
    const float* beta  = (const float*)d_in[14];
    float* out = (float*)d_out;

    half_t *xf,*pef,*wf,*quf,*qvf,*kf,*vf,*pf,*tf;
    cudaGetSymbolAddress((void**)&xf, g_xf);
    cudaGetSymbolAddress((void**)&pef, g_pef);
    cudaGetSymbolAddress((void**)&wf, g_wf);
    cudaGetSymbolAddress((void**)&quf, g_quf);
    cudaGetSymbolAddress((void**)&qvf, g_qvf);
    cudaGetSymbolAddress((void**)&kf, g_kf);
    cudaGetSymbolAddress((void**)&vf, g_vf);
    cudaGetSymbolAddress((void**)&pf, g_pf);
    cudaGetSymbolAddress((void**)&tf, g_tf);

    cudaFuncSetAttribute(proj_all,   cudaFuncAttributeMaxDynamicSharedMemorySize, 65536);
    cudaFuncSetAttribute(gemm_out,   cudaFuncAttributeMaxDynamicSharedMemorySize, 65536);
    cudaFuncSetAttribute(attn_fused, cudaFuncAttributeMaxDynamicSharedMemorySize, ASMEM);

    prep_kernel<<<5376, 256>>>(inputs, gamma, beta, Wq, Wk, Wv, Wo, Wp, xf, pef, wf);
    proj_all<<<448, 256, 65536>>>(xf, pef, wf, bq, bk, bv, pu, pv, quf, qvf, kf, vf, pf);
    attn_fused<<<dim3(16, BB*HH), 128, ASMEM>>>(quf, qvf, kf, vf, pf, amask, tf);
    gemm_out<<<dim3(4,32), 256, 65536>>>(tf, wf+3*(size_t)DD*DD, bo, out);

    (void)in_sizes; (void)n_in; (void)out_size;
}